// round 6
// baseline (speedup 1.0000x reference)
#include <cuda_runtime.h>
#include <cuda_bf16.h>
#include <math.h>
#include <stdint.h>

#define NT 8192
#define CD 1024
#define HD 4096
#define RC_CAP 512

// ---------------- scratch ----------------------------------------------------
__device__ __align__(16) float g_xln[NT * CD];
__device__ __align__(16) float g_r[NT * CD];
__device__ __align__(16) float g_a[NT * CD];
__device__ float g_scale[NT];
__device__ int g_cnt[3];
__device__ int g_list[3 * NT];
__device__ int g_winner[NT];
__device__ float g_conf3[3 * NT];
__device__ int g_rc_cnt;
__device__ int g_rc_list[RC_CAP];
__device__ __align__(16) __nv_bfloat16 g_hhi[NT * CD];   // xln split, then h split
__device__ __align__(16) __nv_bfloat16 g_hlo[NT * CD];
__device__ __align__(16) __nv_bfloat16 g_shi[NT * CD];
__device__ __align__(16) __nv_bfloat16 g_slo[NT * CD];
__device__ __align__(16) __nv_bfloat16 g_ahi[NT * CD];   // gated attn, then W2 out
__device__ __align__(16) __nv_bfloat16 g_alo[NT * CD];
__device__ __align__(16) __nv_bfloat16 g_hrhi[NT * HD];
__device__ __align__(16) __nv_bfloat16 g_hrlo[NT * HD];
#define WSZ (23u * 1048576u)
__device__ __align__(16) __nv_bfloat16 g_wthi[WSZ];
__device__ __align__(16) __nv_bfloat16 g_wtlo[WSZ];

// ---------------- helpers ----------------------------------------------------
__device__ __forceinline__ uint32_t smem_u32(const void* p) {
    uint32_t a;
    asm("{ .reg .u64 t; cvta.to.shared.u64 t, %1; cvt.u32.u64 %0, t; }" : "=r"(a) : "l"(p));
    return a;
}
__device__ __forceinline__ void ldsm4(uint32_t* r, uint32_t a) {
    asm volatile("ldmatrix.sync.aligned.m8n8.x4.shared.b16 {%0,%1,%2,%3}, [%4];"
                 : "=r"(r[0]), "=r"(r[1]), "=r"(r[2]), "=r"(r[3]) : "r"(a));
}
__device__ __forceinline__ void mma16816(float* d, const uint32_t* a, const uint32_t* b) {
    asm volatile("mma.sync.aligned.m16n8k16.row.col.f32.bf16.bf16.f32 "
                 "{%0,%1,%2,%3}, {%4,%5,%6,%7}, {%8,%9}, {%0,%1,%2,%3};"
                 : "+f"(d[0]), "+f"(d[1]), "+f"(d[2]), "+f"(d[3])
                 : "r"(a[0]), "r"(a[1]), "r"(a[2]), "r"(a[3]), "r"(b[0]), "r"(b[1]));
}
__device__ __forceinline__ float sigf(float x) { return 1.0f / (1.0f + expf(-x)); }
__device__ __forceinline__ unsigned packbf(__nv_bfloat16 a, __nv_bfloat16 b) {
    return (unsigned)__bfloat16_as_ushort(a) | ((unsigned)__bfloat16_as_ushort(b) << 16);
}
__device__ __forceinline__ float2 bf2x(unsigned u) {
    __nv_bfloat162 b = *reinterpret_cast<__nv_bfloat162*>(&u);
    return make_float2(__bfloat162float(b.x), __bfloat162float(b.y));
}
__device__ __forceinline__ void split2(float v0, float v1, unsigned& hw, unsigned& lw) {
    __nv_bfloat16 h0 = __float2bfloat16(v0), h1 = __float2bfloat16(v1);
    hw = packbf(h0, h1);
    lw = packbf(__float2bfloat16(v0 - __bfloat162float(h0)),
                __float2bfloat16(v1 - __bfloat162float(h1)));
}

// ================= HMMA tensor GEMM (bf16x3 emulated fp32) ====================
enum { TEPI_HR = 0, TEPI_STORE = 1, TEPI_GATE = 2, TEPI_SCATTER = 3,
       TEPI_SPLIT = 4, TEPI_GATE2 = 5, TEPI_ADDX = 6 };
#define TG_SMEM (2 * 32768 + 1024)

template <int EPI>
__device__ __forceinline__ void emit2(int grow, int gcol, float v0, float v1, int M,
                                      const float* __restrict__ aux,
                                      const int* __restrict__ sidx, const float* __restrict__ scl,
                                      float* __restrict__ outF,
                                      __nv_bfloat16* __restrict__ outHi,
                                      __nv_bfloat16* __restrict__ outLo, int ldo) {
    if (grow >= M) return;
    if (EPI == TEPI_STORE) {
        *(float2*)(outF + (size_t)grow * ldo + gcol) = make_float2(v0, v1);
    } else if (EPI == TEPI_ADDX) {
        float2 a = *(const float2*)(aux + (size_t)grow * CD + gcol);
        *(float2*)(outF + (size_t)grow * ldo + gcol) = make_float2(v0 + a.x, v1 + a.y);
    } else if (EPI == TEPI_SCATTER) {
        int orow = sidx[grow];
        float sc = scl[orow];
        float2* p = (float2*)(outF + (size_t)orow * ldo + gcol);
        float2 c = *p;
        c.x += v0 * sc; c.y += v1 * sc;
        *p = c;
    } else {
        if (EPI == TEPI_HR) {
            v0 = fmaxf(v0, 0.f); v0 *= v0;
            v1 = fmaxf(v1, 0.f); v1 *= v1;
        } else if (EPI == TEPI_GATE) {
            float2 a = *(const float2*)(aux + (size_t)grow * CD + gcol);
            v0 = a.x * sigf(v0); v1 = a.y * sigf(v1);
        } else if (EPI == TEPI_GATE2) {
            float2 a = *(const float2*)(aux + (size_t)grow * CD + gcol);
            v0 = sigf(a.x) * v0; v1 = sigf(a.y) * v1;
        }
        unsigned hw, lw;
        split2(v0, v1, hw, lw);
        *(unsigned*)(outHi + (size_t)grow * ldo + gcol) = hw;
        *(unsigned*)(outLo + (size_t)grow * ldo + gcol) = lw;
    }
}

template <int EPI>
__global__ void __launch_bounds__(256)
tgemm(const __nv_bfloat16* __restrict__ Ahi, const __nv_bfloat16* __restrict__ Alo,
      const __nv_bfloat16* __restrict__ Bhi, const __nv_bfloat16* __restrict__ Blo,
      int Mstat, const int* __restrict__ Mptr, int K,
      const int* __restrict__ gidx, const float* __restrict__ aux,
      const int* __restrict__ sidx, const float* __restrict__ scl,
      float* __restrict__ outF,
      __nv_bfloat16* __restrict__ outHi, __nv_bfloat16* __restrict__ outLo, int ldo) {
    int M = Mptr ? *Mptr : Mstat;
    int bm = blockIdx.x * 128;
    if (bm >= M) return;
    int bn = blockIdx.y * 128;

    extern __shared__ char smraw[];
    uint32_t smb0 = smem_u32(smraw);
    uint32_t smb = (smb0 + 1023u) & ~1023u;
    char* sb = smraw + (smb - smb0);

    int tid = threadIdx.x, lane = tid & 31, warp = tid >> 5;
    int wm = warp & 1, wn = warp >> 1;
    int quad = lane >> 3, r8 = lane & 7;

    uint32_t baseA[4], maskA[4];
    uint32_t kqA = (uint32_t)(quad >> 1) * 16;
#pragma unroll
    for (int mt = 0; mt < 4; mt++) {
        int rowA = wm * 64 + mt * 16 + (quad & 1) * 8 + r8;
        baseA[mt] = (uint32_t)rowA * 128;
        maskA[mt] = (uint32_t)(rowA & 7) << 4;
    }
    uint32_t baseB[2], maskB[2];
    uint32_t kqB = (uint32_t)(quad & 1) * 16;
#pragma unroll
    for (int n2 = 0; n2 < 2; n2++) {
        int rowB = wn * 32 + n2 * 16 + (quad >> 1) * 8 + r8;
        baseB[n2] = 16384u + (uint32_t)rowB * 128;
        maskB[n2] = (uint32_t)(rowB & 7) << 4;
    }

    int row = tid >> 1, h = tid & 1;
    int ra = bm + row; if (ra > M - 1) ra = M - 1;
    if (gidx) ra = gidx[ra];
    const __nv_bfloat16* pAh = Ahi + (size_t)ra * K + h * 16;
    const __nv_bfloat16* pAl = Alo + (size_t)ra * K + h * 16;
    const __nv_bfloat16* pBh = Bhi + (size_t)(bn + row) * K + h * 16;
    const __nv_bfloat16* pBl = Blo + (size_t)(bn + row) * K + h * 16;
    uint32_t mk = (uint32_t)(row & 7) << 4;
    uint32_t st0 = (uint32_t)row * 128 + (((uint32_t)h * 32) ^ mk);
    uint32_t st1 = (uint32_t)row * 128 + (((uint32_t)h * 32 + 16) ^ mk);
    uint32_t st2 = (uint32_t)row * 128 + ((64u + h * 32) ^ mk);
    uint32_t st3 = (uint32_t)row * 128 + ((64u + h * 32 + 16) ^ mk);

    float acc[4][4][4];
#pragma unroll
    for (int i = 0; i < 4; i++)
#pragma unroll
        for (int j = 0; j < 4; j++)
#pragma unroll
            for (int q = 0; q < 4; q++) acc[i][j][q] = 0.f;

    uint4 sah0, sah1, sal0, sal1, sbh0, sbh1, sbl0, sbl1;
    sah0 = *(const uint4*)(pAh); sah1 = *(const uint4*)(pAh + 8);
    sal0 = *(const uint4*)(pAl); sal1 = *(const uint4*)(pAl + 8);
    sbh0 = *(const uint4*)(pBh); sbh1 = *(const uint4*)(pBh + 8);
    sbl0 = *(const uint4*)(pBl); sbl1 = *(const uint4*)(pBl + 8);
    {
        char* bp = sb;
        *(uint4*)(bp + st0) = sah0; *(uint4*)(bp + st1) = sah1;
        *(uint4*)(bp + st2) = sal0; *(uint4*)(bp + st3) = sal1;
        bp += 16384;
        *(uint4*)(bp + st0) = sbh0; *(uint4*)(bp + st1) = sbh1;
        *(uint4*)(bp + st2) = sbl0; *(uint4*)(bp + st3) = sbl1;
    }
    __syncthreads();

    int nch = K >> 5;
    for (int t = 0; t < nch; t++) {
        uint32_t bufs = smb + (uint32_t)(t & 1) * 32768u;
        if (t + 1 < nch) {
            int kc = (t + 1) * 32;
            sah0 = *(const uint4*)(pAh + kc); sah1 = *(const uint4*)(pAh + kc + 8);
            sal0 = *(const uint4*)(pAl + kc); sal1 = *(const uint4*)(pAl + kc + 8);
            sbh0 = *(const uint4*)(pBh + kc); sbh1 = *(const uint4*)(pBh + kc + 8);
            sbl0 = *(const uint4*)(pBl + kc); sbl1 = *(const uint4*)(pBl + kc + 8);
        }
#pragma unroll
        for (int ks = 0; ks < 2; ks++) {
            uint32_t cbase = kqA + (uint32_t)ks * 32;
            uint32_t ah[4][4], al[4][4], bh[4][2], bl[4][2];
#pragma unroll
            for (int mt = 0; mt < 4; mt++) {
                ldsm4(ah[mt], bufs + baseA[mt] + (cbase ^ maskA[mt]));
                ldsm4(al[mt], bufs + baseA[mt] + ((cbase + 64u) ^ maskA[mt]));
            }
            uint32_t cbB = kqB + (uint32_t)ks * 32;
#pragma unroll
            for (int n2 = 0; n2 < 2; n2++) {
                uint32_t r[4];
                ldsm4(r, bufs + baseB[n2] + (cbB ^ maskB[n2]));
                bh[2 * n2][0] = r[0]; bh[2 * n2][1] = r[1];
                bh[2 * n2 + 1][0] = r[2]; bh[2 * n2 + 1][1] = r[3];
                ldsm4(r, bufs + baseB[n2] + ((cbB + 64u) ^ maskB[n2]));
                bl[2 * n2][0] = r[0]; bl[2 * n2][1] = r[1];
                bl[2 * n2 + 1][0] = r[2]; bl[2 * n2 + 1][1] = r[3];
            }
#pragma unroll
            for (int mt = 0; mt < 4; mt++)
#pragma unroll
                for (int nt = 0; nt < 4; nt++) {
                    mma16816(acc[mt][nt], ah[mt], bh[nt]);
                    mma16816(acc[mt][nt], ah[mt], bl[nt]);
                    mma16816(acc[mt][nt], al[mt], bh[nt]);
                }
        }
        if (t + 1 < nch) {
            char* bp = sb + ((t + 1) & 1) * 32768;
            *(uint4*)(bp + st0) = sah0; *(uint4*)(bp + st1) = sah1;
            *(uint4*)(bp + st2) = sal0; *(uint4*)(bp + st3) = sal1;
            bp += 16384;
            *(uint4*)(bp + st0) = sbh0; *(uint4*)(bp + st1) = sbh1;
            *(uint4*)(bp + st2) = sbl0; *(uint4*)(bp + st3) = sbl1;
            __syncthreads();
        }
    }

    int erow = lane >> 2, ecol = (lane & 3) * 2;
#pragma unroll
    for (int mt = 0; mt < 4; mt++) {
        int gr = bm + wm * 64 + mt * 16 + erow;
#pragma unroll
        for (int nt = 0; nt < 4; nt++) {
            int gc = bn + wn * 32 + nt * 8 + ecol;
            emit2<EPI>(gr,     gc, acc[mt][nt][0], acc[mt][nt][1], M, aux, sidx, scl, outF, outHi, outLo, ldo);
            emit2<EPI>(gr + 8, gc, acc[mt][nt][2], acc[mt][nt][3], M, aux, sidx, scl, outF, outHi, outLo, ldo);
        }
    }
}

// ======== transpose + split: W[K,N] -> WT_hi/lo[N,K] (bf16) ===================
__global__ void tsplit(const float* __restrict__ W, int K, int N,
                       __nv_bfloat16* __restrict__ hi, __nv_bfloat16* __restrict__ lo) {
    __shared__ float t[32][33];
    int n0 = blockIdx.x * 32, k0 = blockIdx.y * 32;
    int tx = threadIdx.x, ty = threadIdx.y;
#pragma unroll
    for (int j = 0; j < 4; j++)
        t[ty + 8 * j][tx] = W[(size_t)(k0 + ty + 8 * j) * N + n0 + tx];
    __syncthreads();
#pragma unroll
    for (int j = 0; j < 4; j++) {
        float v = t[tx][ty + 8 * j];
        size_t o = (size_t)(n0 + ty + 8 * j) * K + k0 + tx;
        __nv_bfloat16 h = __float2bfloat16(v);
        hi[o] = h;
        lo[o] = __float2bfloat16(v - __bfloat162float(h));
    }
}

// ================= LN / routing ===============================================
__device__ __forceinline__ float blockReduceSum(float v) {
    __shared__ float sh[8];
#pragma unroll
    for (int o = 16; o > 0; o >>= 1) v += __shfl_down_sync(0xffffffffu, v, o);
    int w = threadIdx.x >> 5, l = threadIdx.x & 31;
    if (l == 0) sh[w] = v;
    __syncthreads();
    if (threadIdx.x < 8) {
        float r = sh[threadIdx.x];
#pragma unroll
        for (int o = 4; o > 0; o >>= 1) r += __shfl_down_sync(0x000000ffu, r, o);
        if (threadIdx.x == 0) sh[0] = r;
    }
    __syncthreads();
    float res = sh[0];
    __syncthreads();
    return res;
}

// LN1: fp32 out + bf16 hi/lo split (fused)
__global__ void ln_kernel(const float* __restrict__ x, const float* __restrict__ w,
                          const float* __restrict__ b, float* __restrict__ out,
                          __nv_bfloat16* __restrict__ ohi, __nv_bfloat16* __restrict__ olo) {
    int row = blockIdx.x, tid = threadIdx.x;
    float4 v = ((const float4*)(x + (size_t)row * CD))[tid];
    float s = blockReduceSum(v.x + v.y + v.z + v.w);
    float mean = s * (1.0f / CD);
    float dx = v.x - mean, dy = v.y - mean, dz = v.z - mean, dw = v.w - mean;
    float s2 = blockReduceSum(dx * dx + dy * dy + dz * dz + dw * dw);
    float rstd = 1.0f / sqrtf(s2 * (1.0f / CD) + 1e-5f);
    float4 wv = ((const float4*)w)[tid], bv = ((const float4*)b)[tid];
    float4 o = make_float4(dx * rstd * wv.x + bv.x, dy * rstd * wv.y + bv.y,
                           dz * rstd * wv.z + bv.z, dw * rstd * wv.w + bv.w);
    ((float4*)(out + (size_t)row * CD))[tid] = o;
    unsigned h0, l0, h1, l1;
    split2(o.x, o.y, h0, l0);
    split2(o.z, o.w, h1, l1);
    ((uint2*)(ohi + (size_t)row * CD))[tid] = make_uint2(h0, h1);
    ((uint2*)(olo + (size_t)row * CD))[tid] = make_uint2(l0, l1);
}

// LN2 + provisional routing + h split + marginal-token flagging
__global__ void ln2_route_kernel(const float* __restrict__ x2, const float* __restrict__ w,
                                 const float* __restrict__ b, const float* __restrict__ conf_rwkv,
                                 const float* __restrict__ conf_trans, const float* __restrict__ w_diff,
                                 const float* __restrict__ W_aff, const float* __restrict__ capital,
                                 __nv_bfloat16* __restrict__ hhi, __nv_bfloat16* __restrict__ hlo,
                                 float* __restrict__ conf3, int* __restrict__ winner,
                                 int* __restrict__ rc_cnt, int* __restrict__ rc_list) {
    int row = blockIdx.x, tid = threadIdx.x;
    float4 v = ((const float4*)(x2 + (size_t)row * CD))[tid];
    float s = blockReduceSum(v.x + v.y + v.z + v.w);
    float mean = s * (1.0f / CD);
    float dx = v.x - mean, dy = v.y - mean, dz = v.z - mean, dw = v.w - mean;
    float s2 = blockReduceSum(dx * dx + dy * dy + dz * dz + dw * dw);
    float rstd = 1.0f / sqrtf(s2 * (1.0f / CD) + 1e-5f);
    float4 wv = ((const float4*)w)[tid], bv = ((const float4*)b)[tid];
    float4 o = make_float4(dx * rstd * wv.x + bv.x, dy * rstd * wv.y + bv.y,
                           dz * rstd * wv.z + bv.z, dw * rstd * wv.w + bv.w);
    unsigned h0, l0, h1, l1;
    split2(o.x, o.y, h0, l0);
    split2(o.z, o.w, h1, l1);
    ((uint2*)(hhi + (size_t)row * CD))[tid] = make_uint2(h0, h1);
    ((uint2*)(hlo + (size_t)row * CD))[tid] = make_uint2(l0, l1);

    float p[7];
    float4 c0 = ((const float4*)conf_rwkv)[tid];
    float4 c1 = ((const float4*)(conf_rwkv + CD))[tid];
    float4 ct = ((const float4*)conf_trans)[tid];
    float4 wd = ((const float4*)w_diff)[tid];
    p[0] = o.x * c0.x + o.y * c0.y + o.z * c0.z + o.w * c0.w;
    p[1] = o.x * c1.x + o.y * c1.y + o.z * c1.z + o.w * c1.w;
    p[2] = o.x * ct.x + o.y * ct.y + o.z * ct.z + o.w * ct.w;
    p[3] = o.x * wd.x + o.y * wd.y + o.z * wd.z + o.w * wd.w;
    const float* wa = W_aff + (size_t)tid * 12;
#pragma unroll
    for (int e = 0; e < 3; e++)
        p[4 + e] = o.x * wa[e] + o.y * wa[3 + e] + o.z * wa[6 + e] + o.w * wa[9 + e];

    __shared__ float red[7][8];
    int wid = tid >> 5, lid = tid & 31;
#pragma unroll
    for (int q = 0; q < 7; q++) {
        float vv = p[q];
#pragma unroll
        for (int o2 = 16; o2 > 0; o2 >>= 1) vv += __shfl_down_sync(0xffffffffu, vv, o2);
        if (lid == 0) red[q][wid] = vv;
    }
    __syncthreads();
    if (tid == 0) {
        float d[7];
#pragma unroll
        for (int q = 0; q < 7; q++) {
            float t = 0.f;
#pragma unroll
            for (int k = 0; k < 8; k++) t += red[q][k];
            d[q] = t;
        }
        float cf[3] = {sigf(d[0]), sigf(d[1]), sigf(d[2])};
        float diff = sigf(d[3]);
        float bids[3];
#pragma unroll
        for (int e = 0; e < 3; e++) {
            bids[e] = cf[e] * capital[e] * diff + d[4 + e];
            conf3[row * 3 + e] = cf[e];
        }
        int wdx = 0; float best = bids[0];
        if (bids[1] > best) { best = bids[1]; wdx = 1; }
        if (bids[2] > best) { best = bids[2]; wdx = 2; }
        float second = -1e30f;
#pragma unroll
        for (int e = 0; e < 3; e++)
            if (e != wdx && bids[e] > second) second = bids[e];
        winner[row] = wdx;
        if (best - second < 1e-3f) {
            int pos = atomicAdd(rc_cnt, 1);
            if (pos < RC_CAP) rc_list[pos] = row;
        }
    }
}

// exact fp32 recompute of routing for marginal tokens
__global__ void recheck_kernel(const float* __restrict__ x, const float* __restrict__ xln,
                               const __nv_bfloat16* __restrict__ wrh, const __nv_bfloat16* __restrict__ wrl,
                               const __nv_bfloat16* __restrict__ wvh, const __nv_bfloat16* __restrict__ wvl,
                               const __nv_bfloat16* __restrict__ woh, const __nv_bfloat16* __restrict__ wol,
                               const float* __restrict__ ln2w, const float* __restrict__ ln2b,
                               const float* __restrict__ conf_rwkv, const float* __restrict__ conf_trans,
                               const float* __restrict__ w_diff, const float* __restrict__ W_aff,
                               const float* __restrict__ capital,
                               const int* __restrict__ rc_cnt, const int* __restrict__ rc_list,
                               int* __restrict__ winner) {
    int bi = blockIdx.x;
    int n = *rc_cnt; if (n > RC_CAP) n = RC_CAP;
    if (bi >= n) return;
    int row = rc_list[bi];
    int tid = threadIdx.x;
    __shared__ float sx[CD];
    __shared__ float su[CD];
    __shared__ float satt[CD];
    for (int c = tid; c < CD; c += 256) sx[c] = xln[(size_t)row * CD + c];
    __syncthreads();
    for (int c = tid; c < CD; c += 256) {
        const __nv_bfloat16 *prh = wrh + (size_t)c * CD, *prl = wrl + (size_t)c * CD;
        const __nv_bfloat16 *pvh = wvh + (size_t)c * CD, *pvl = wvl + (size_t)c * CD;
        float r = 0.f, vv = 0.f;
        for (int k = 0; k < CD; k += 2) {
            float2 rh = bf2x(*(const unsigned*)(prh + k));
            float2 rl = bf2x(*(const unsigned*)(prl + k));
            float2 vh = bf2x(*(const unsigned*)(pvh + k));
            float2 vl = bf2x(*(const unsigned*)(pvl + k));
            r += sx[k] * (rh.x + rl.x) + sx[k + 1] * (rh.y + rl.y);
            vv += sx[k] * (vh.x + vl.x) + sx[k + 1] * (vh.y + vl.y);
        }
        su[c] = sigf(r) * vv;
    }
    __syncthreads();
    for (int c = tid; c < CD; c += 256) {
        const __nv_bfloat16 *ph = woh + (size_t)c * CD, *pl = wol + (size_t)c * CD;
        float a = 0.f;
        for (int k = 0; k < CD; k += 2) {
            float2 oh = bf2x(*(const unsigned*)(ph + k));
            float2 ol = bf2x(*(const unsigned*)(pl + k));
            a += su[k] * (oh.x + ol.x) + su[k + 1] * (oh.y + ol.y);
        }
        satt[c] = a + x[(size_t)row * CD + c];
    }
    __syncthreads();
    float ps = 0.f;
    for (int c = tid; c < CD; c += 256) ps += satt[c];
    float mean = blockReduceSum(ps) * (1.0f / CD);
    float ps2 = 0.f;
    for (int c = tid; c < CD; c += 256) { float d = satt[c] - mean; ps2 += d * d; }
    float rstd = 1.0f / sqrtf(blockReduceSum(ps2) * (1.0f / CD) + 1e-5f);

    float p[7] = {0, 0, 0, 0, 0, 0, 0};
    for (int c = tid; c < CD; c += 256) {
        float hc = (satt[c] - mean) * rstd * ln2w[c] + ln2b[c];
        p[0] += hc * conf_rwkv[c];
        p[1] += hc * conf_rwkv[CD + c];
        p[2] += hc * conf_trans[c];
        p[3] += hc * w_diff[c];
        p[4] += hc * W_aff[c * 3 + 0];
        p[5] += hc * W_aff[c * 3 + 1];
        p[6] += hc * W_aff[c * 3 + 2];
    }
    __shared__ float red[7][8];
    int wid = tid >> 5, lid = tid & 31;
#pragma unroll
    for (int q = 0; q < 7; q++) {
        float vv = p[q];
#pragma unroll
        for (int o2 = 16; o2 > 0; o2 >>= 1) vv += __shfl_down_sync(0xffffffffu, vv, o2);
        if (lid == 0) red[q][wid] = vv;
    }
    __syncthreads();
    if (tid == 0) {
        float d[7];
#pragma unroll
        for (int q = 0; q < 7; q++) {
            float t = 0.f;
#pragma unroll
            for (int k = 0; k < 8; k++) t += red[q][k];
            d[q] = t;
        }
        float cf[3] = {sigf(d[0]), sigf(d[1]), sigf(d[2])};
        float diff = sigf(d[3]);
        int wdx = 0; float best = -1e30f;
#pragma unroll
        for (int e = 0; e < 3; e++) {
            float bid = cf[e] * capital[e] * diff + d[4 + e];
            if (bid > best) { best = bid; wdx = e; }
        }
        winner[row] = wdx;
    }
}

__global__ void build_lists(const int* __restrict__ winner, const float* __restrict__ conf3,
                            float* __restrict__ scale_out, int* __restrict__ cnt, int* __restrict__ lst) {
    int i = blockIdx.x * 256 + threadIdx.x;
    if (i >= NT) return;
    int w = winner[i];
    float wc = conf3[i * 3 + w];
    scale_out[i] = wc / (wc + 1e-6f);
    int pos = atomicAdd(&cnt[w], 1);
    lst[w * NT + pos] = i;
}

__global__ void zero_cnt_kernel(int* c, int* rc) {
    if (threadIdx.x < 3) c[threadIdx.x] = 0;
    if (threadIdx.x == 0) *rc = 0;
}

// ================= launch =====================================================
extern "C" void kernel_launch(void* const* d_in, const int* in_sizes, int n_in,
                              void* d_out, int out_size) {
    const float* x = (const float*)d_in[0];
    const float* capital = (const float*)d_in[2];
    const float* ln1w = (const float*)d_in[3], *ln1b = (const float*)d_in[4];
    const float* ln2w = (const float*)d_in[5], *ln2b = (const float*)d_in[6];
    const float* Wr = (const float*)d_in[7], *Wv = (const float*)d_in[8];
    const float* Wo = (const float*)d_in[9], *Ws = (const float*)d_in[10];
    const float* Kr = (const float*)d_in[11], *Vr = (const float*)d_in[12];
    const float* confr = (const float*)d_in[13];
    const float* W1 = (const float*)d_in[14], *W2 = (const float*)d_in[15];
    const float* W3 = (const float*)d_in[16];
    const float* conft = (const float*)d_in[17], *wdiff = (const float*)d_in[18];
    const float* Waff = (const float*)d_in[19];
    float* out = (float*)d_out;

    void* p;
    cudaGetSymbolAddress(&p, g_xln);    float* xln = (float*)p;
    cudaGetSymbolAddress(&p, g_r);      float* rb = (float*)p;
    cudaGetSymbolAddress(&p, g_a);      float* ab = (float*)p;
    cudaGetSymbolAddress(&p, g_scale);  float* sclp = (float*)p;
    cudaGetSymbolAddress(&p, g_cnt);    int* cnt = (int*)p;
    cudaGetSymbolAddress(&p, g_list);   int* lst = (int*)p;
    cudaGetSymbolAddress(&p, g_winner); int* win = (int*)p;
    cudaGetSymbolAddress(&p, g_conf3);  float* conf3 = (float*)p;
    cudaGetSymbolAddress(&p, g_rc_cnt); int* rc_cnt = (int*)p;
    cudaGetSymbolAddress(&p, g_rc_list);int* rc_list = (int*)p;
    cudaGetSymbolAddress(&p, g_hhi);    __nv_bfloat16* hhi = (__nv_bfloat16*)p;
    cudaGetSymbolAddress(&p, g_hlo);    __nv_bfloat16* hlo = (__nv_bfloat16*)p;
    cudaGetSymbolAddress(&p, g_shi);    __nv_bfloat16* shi = (__nv_bfloat16*)p;
    cudaGetSymbolAddress(&p, g_slo);    __nv_bfloat16* slo = (__nv_bfloat16*)p;
    cudaGetSymbolAddress(&p, g_ahi);    __nv_bfloat16* ahi = (__nv_bfloat16*)p;
    cudaGetSymbolAddress(&p, g_alo);    __nv_bfloat16* alo = (__nv_bfloat16*)p;
    cudaGetSymbolAddress(&p, g_hrhi);   __nv_bfloat16* hrhi = (__nv_bfloat16*)p;
    cudaGetSymbolAddress(&p, g_hrlo);   __nv_bfloat16* hrlo = (__nv_bfloat16*)p;
    cudaGetSymbolAddress(&p, g_wthi);   __nv_bfloat16* wthi = (__nv_bfloat16*)p;
    cudaGetSymbolAddress(&p, g_wtlo);   __nv_bfloat16* wtlo = (__nv_bfloat16*)p;

    cudaFuncSetAttribute(tgemm<TEPI_HR>,      cudaFuncAttributeMaxDynamicSharedMemorySize, TG_SMEM);
    cudaFuncSetAttribute(tgemm<TEPI_STORE>,   cudaFuncAttributeMaxDynamicSharedMemorySize, TG_SMEM);
    cudaFuncSetAttribute(tgemm<TEPI_GATE>,    cudaFuncAttributeMaxDynamicSharedMemorySize, TG_SMEM);
    cudaFuncSetAttribute(tgemm<TEPI_SCATTER>, cudaFuncAttributeMaxDynamicSharedMemorySize, TG_SMEM);
    cudaFuncSetAttribute(tgemm<TEPI_SPLIT>,   cudaFuncAttributeMaxDynamicSharedMemorySize, TG_SMEM);
    cudaFuncSetAttribute(tgemm<TEPI_GATE2>,   cudaFuncAttributeMaxDynamicSharedMemorySize, TG_SMEM);
    cudaFuncSetAttribute(tgemm<TEPI_ADDX>,    cudaFuncAttributeMaxDynamicSharedMemorySize, TG_SMEM);

    const size_t M1 = 1048576;
    const size_t KR0T = 0, KR1T = 4 * M1, VR0T = 8 * M1, VR1T = 12 * M1;
    const size_t W1T = 16 * M1, W2T = 17 * M1, W3T = 18 * M1;
    const size_t WRT = 19 * M1, WVT = 20 * M1, WOT = 21 * M1, WST = 22 * M1;

    dim3 blk(256), tb(32, 8);
    dim3 gC(NT / 128, CD / 128), gH(NT / 128, HD / 128);

    // weight transpose+split (bf16 hi/lo)
    tsplit<<<dim3(HD / 32, CD / 32), tb>>>(Kr, CD, HD, wthi + KR0T, wtlo + KR0T);
    tsplit<<<dim3(HD / 32, CD / 32), tb>>>(Kr + (size_t)CD * HD, CD, HD, wthi + KR1T, wtlo + KR1T);
    tsplit<<<dim3(CD / 32, HD / 32), tb>>>(Vr, HD, CD, wthi + VR0T, wtlo + VR0T);
    tsplit<<<dim3(CD / 32, HD / 32), tb>>>(Vr + (size_t)HD * CD, HD, CD, wthi + VR1T, wtlo + VR1T);
    tsplit<<<dim3(CD / 32, CD / 32), tb>>>(W1, CD, CD, wthi + W1T, wtlo + W1T);
    tsplit<<<dim3(CD / 32, CD / 32), tb>>>(W2, CD, CD, wthi + W2T, wtlo + W2T);
    tsplit<<<dim3(CD / 32, CD / 32), tb>>>(W3, CD, CD, wthi + W3T, wtlo + W3T);
    tsplit<<<dim3(CD / 32, CD / 32), tb>>>(Wr, CD, CD, wthi + WRT, wtlo + WRT);
    tsplit<<<dim3(CD / 32, CD / 32), tb>>>(Wv, CD, CD, wthi + WVT, wtlo + WVT);
    tsplit<<<dim3(CD / 32, CD / 32), tb>>>(Wo, CD, CD, wthi + WOT, wtlo + WOT);
    tsplit<<<dim3(CD / 32, CD / 32), tb>>>(Ws, CD, CD, wthi + WST, wtlo + WST);

    zero_cnt_kernel<<<1, 32>>>(cnt, rc_cnt);
    ln_kernel<<<NT, 256>>>(x, ln1w, ln1b, xln, hhi, hlo);   // xln split -> hhi/hlo (temp)

    // attention path: bf16x3 HMMA
    tgemm<TEPI_STORE><<<gC, blk, TG_SMEM>>>(hhi, hlo, wthi + WRT, wtlo + WRT, NT, nullptr, CD,
                                            nullptr, nullptr, nullptr, nullptr, rb, nullptr, nullptr, CD);
    tgemm<TEPI_GATE2><<<gC, blk, TG_SMEM>>>(hhi, hlo, wthi + WVT, wtlo + WVT, NT, nullptr, CD,
                                            nullptr, rb, nullptr, nullptr, nullptr, ahi, alo, CD);
    tgemm<TEPI_SPLIT><<<gC, blk, TG_SMEM>>>(hhi, hlo, wthi + WST, wtlo + WST, NT, nullptr, CD,
                                            nullptr, nullptr, nullptr, nullptr, nullptr, shi, slo, CD);
    tgemm<TEPI_ADDX><<<gC, blk, TG_SMEM>>>(ahi, alo, wthi + WOT, wtlo + WOT, NT, nullptr, CD,
                                           nullptr, x, nullptr, nullptr, out, nullptr, nullptr, CD);

    // routing (provisional) + h split; recheck marginal tokens exactly; build lists
    ln2_route_kernel<<<NT, 256>>>(out, ln2w, ln2b, confr, conft, wdiff, Waff, capital,
                                  hhi, hlo, conf3, win, rc_cnt, rc_list);
    recheck_kernel<<<RC_CAP, 256>>>(x, xln, wthi + WRT, wtlo + WRT, wthi + WVT, wtlo + WVT,
                                    wthi + WOT, wtlo + WOT, ln2w, ln2b, confr, conft, wdiff,
                                    Waff, capital, rc_cnt, rc_list, win);
    build_lists<<<NT / 256, 256>>>(win, conf3, sclp, cnt, lst);

    // transformer expert (winner == 2)
    tgemm<TEPI_STORE><<<gC, blk, TG_SMEM>>>(hhi, hlo, wthi + W1T, wtlo + W1T, 0, cnt + 2, CD,
                                            lst + 2 * NT, nullptr, nullptr, nullptr, ab, nullptr, nullptr, CD);
    tgemm<TEPI_GATE><<<gC, blk, TG_SMEM>>>(shi, slo, wthi + W2T, wtlo + W2T, 0, cnt + 2, CD,
                                           lst + 2 * NT, ab, nullptr, nullptr, nullptr, ahi, alo, CD);
    tgemm<TEPI_SCATTER><<<gC, blk, TG_SMEM>>>(ahi, alo, wthi + W3T, wtlo + W3T, 0, cnt + 2, CD,
                                              nullptr, nullptr, lst + 2 * NT, sclp, out, nullptr, nullptr, CD);

    // RWKV experts
    for (int e = 0; e < 2; e++) {
        tgemm<TEPI_HR><<<gH, blk, TG_SMEM>>>(hhi, hlo, wthi + (e ? KR1T : KR0T), wtlo + (e ? KR1T : KR0T),
                                             0, cnt + e, CD, lst + e * NT, nullptr, nullptr, nullptr,
                                             nullptr, hrhi, hrlo, HD);
        tgemm<TEPI_SCATTER><<<gC, blk, TG_SMEM>>>(hrhi, hrlo, wthi + (e ? VR1T : VR0T), wtlo + (e ? VR1T : VR0T),
                                                  0, cnt + e, HD, nullptr, nullptr, lst + e * NT, sclp,
                                                  out, nullptr, nullptr, CD);
    }
}

// round 7
// speedup vs baseline: 1.3238x; 1.3238x over previous
#include <cuda_runtime.h>
#include <cuda_bf16.h>
#include <math.h>
#include <stdint.h>

#define NT 8192
#define CD 1024
#define HD 4096
#define RC_CAP 512

// ---------------- scratch ----------------------------------------------------
__device__ __align__(16) float g_xln[NT * CD];
__device__ __align__(16) float g_r[NT * CD];
__device__ __align__(16) float g_a[NT * CD];
__device__ float g_scale[NT];
__device__ int g_cnt[3];
__device__ int g_list[3 * NT];
__device__ int g_winner[NT];
__device__ float g_conf3[3 * NT];
__device__ int g_rc_cnt;
__device__ int g_rc_list[RC_CAP];
__device__ __align__(16) __nv_bfloat16 g_hhi[NT * CD];   // xln split, then h split
__device__ __align__(16) __nv_bfloat16 g_hlo[NT * CD];
__device__ __align__(16) __nv_bfloat16 g_shi[NT * CD];
__device__ __align__(16) __nv_bfloat16 g_slo[NT * CD];
__device__ __align__(16) __nv_bfloat16 g_ahi[NT * CD];   // gated attn, then W2 out
__device__ __align__(16) __nv_bfloat16 g_alo[NT * CD];
__device__ __align__(16) __nv_bfloat16 g_hrhi[NT * HD];
__device__ __align__(16) __nv_bfloat16 g_hrlo[NT * HD];
#define WSZ (23u * 1048576u)
__device__ __align__(16) __nv_bfloat16 g_wthi[WSZ];
__device__ __align__(16) __nv_bfloat16 g_wtlo[WSZ];

// ---------------- helpers ----------------------------------------------------
__device__ __forceinline__ uint32_t smem_u32(const void* p) {
    uint32_t a;
    asm("{ .reg .u64 t; cvta.to.shared.u64 t, %1; cvt.u32.u64 %0, t; }" : "=r"(a) : "l"(p));
    return a;
}
__device__ __forceinline__ void ldsm4(uint32_t* r, uint32_t a) {
    asm volatile("ldmatrix.sync.aligned.m8n8.x4.shared.b16 {%0,%1,%2,%3}, [%4];"
                 : "=r"(r[0]), "=r"(r[1]), "=r"(r[2]), "=r"(r[3]) : "r"(a));
}
__device__ __forceinline__ void mma16816(float* d, const uint32_t* a, const uint32_t* b) {
    asm volatile("mma.sync.aligned.m16n8k16.row.col.f32.bf16.bf16.f32 "
                 "{%0,%1,%2,%3}, {%4,%5,%6,%7}, {%8,%9}, {%0,%1,%2,%3};"
                 : "+f"(d[0]), "+f"(d[1]), "+f"(d[2]), "+f"(d[3])
                 : "r"(a[0]), "r"(a[1]), "r"(a[2]), "r"(a[3]), "r"(b[0]), "r"(b[1]));
}
__device__ __forceinline__ float sigf(float x) { return 1.0f / (1.0f + expf(-x)); }
__device__ __forceinline__ unsigned packbf(__nv_bfloat16 a, __nv_bfloat16 b) {
    return (unsigned)__bfloat16_as_ushort(a) | ((unsigned)__bfloat16_as_ushort(b) << 16);
}
__device__ __forceinline__ void split2(float v0, float v1, unsigned& hw, unsigned& lw) {
    __nv_bfloat16 h0 = __float2bfloat16(v0), h1 = __float2bfloat16(v1);
    hw = packbf(h0, h1);
    lw = packbf(__float2bfloat16(v0 - __bfloat162float(h0)),
                __float2bfloat16(v1 - __bfloat162float(h1)));
}

// ================= HMMA tensor GEMM (bf16x3 emulated fp32) ====================
enum { TEPI_HR = 0, TEPI_STORE = 1, TEPI_GATE = 2, TEPI_SCATTER = 3,
       TEPI_SPLIT = 4, TEPI_GATE2 = 5, TEPI_ADDX = 6 };
#define TG_SMEM (2 * 32768 + 1024)

template <int EPI>
__device__ __forceinline__ void emit2(int grow, int gcol, float v0, float v1, int M,
                                      const float* __restrict__ aux,
                                      const int* __restrict__ sidx, const float* __restrict__ scl,
                                      float* __restrict__ outF,
                                      __nv_bfloat16* __restrict__ outHi,
                                      __nv_bfloat16* __restrict__ outLo, int ldo) {
    if (grow >= M) return;
    if (EPI == TEPI_STORE) {
        *(float2*)(outF + (size_t)grow * ldo + gcol) = make_float2(v0, v1);
    } else if (EPI == TEPI_ADDX) {
        float2 a = *(const float2*)(aux + (size_t)grow * CD + gcol);
        *(float2*)(outF + (size_t)grow * ldo + gcol) = make_float2(v0 + a.x, v1 + a.y);
    } else if (EPI == TEPI_SCATTER) {
        int orow = sidx[grow];
        float sc = scl[orow];
        float2* p = (float2*)(outF + (size_t)orow * ldo + gcol);
        float2 c = *p;
        c.x += v0 * sc; c.y += v1 * sc;
        *p = c;
    } else {
        if (EPI == TEPI_HR) {
            v0 = fmaxf(v0, 0.f); v0 *= v0;
            v1 = fmaxf(v1, 0.f); v1 *= v1;
        } else if (EPI == TEPI_GATE) {
            float2 a = *(const float2*)(aux + (size_t)grow * CD + gcol);
            v0 = a.x * sigf(v0); v1 = a.y * sigf(v1);
        } else if (EPI == TEPI_GATE2) {
            float2 a = *(const float2*)(aux + (size_t)grow * CD + gcol);
            v0 = sigf(a.x) * v0; v1 = sigf(a.y) * v1;
        }
        unsigned hw, lw;
        split2(v0, v1, hw, lw);
        *(unsigned*)(outHi + (size_t)grow * ldo + gcol) = hw;
        *(unsigned*)(outLo + (size_t)grow * ldo + gcol) = lw;
    }
}

template <int EPI>
__global__ void __launch_bounds__(256)
tgemm(const __nv_bfloat16* __restrict__ Ahi, const __nv_bfloat16* __restrict__ Alo,
      const __nv_bfloat16* __restrict__ Bhi, const __nv_bfloat16* __restrict__ Blo,
      int Mstat, const int* __restrict__ Mptr, int K,
      const int* __restrict__ gidx, const float* __restrict__ aux,
      const int* __restrict__ sidx, const float* __restrict__ scl,
      float* __restrict__ outF,
      __nv_bfloat16* __restrict__ outHi, __nv_bfloat16* __restrict__ outLo, int ldo) {
    int M = Mptr ? *Mptr : Mstat;
    int bm = blockIdx.x * 128;
    if (bm >= M) return;
    int bn = blockIdx.y * 128;

    extern __shared__ char smraw[];
    uint32_t smb0 = smem_u32(smraw);
    uint32_t smb = (smb0 + 1023u) & ~1023u;
    char* sb = smraw + (smb - smb0);

    int tid = threadIdx.x, lane = tid & 31, warp = tid >> 5;
    int wm = warp & 1, wn = warp >> 1;
    int quad = lane >> 3, r8 = lane & 7;

    uint32_t baseA[4], maskA[4];
    uint32_t kqA = (uint32_t)(quad >> 1) * 16;
#pragma unroll
    for (int mt = 0; mt < 4; mt++) {
        int rowA = wm * 64 + mt * 16 + (quad & 1) * 8 + r8;
        baseA[mt] = (uint32_t)rowA * 128;
        maskA[mt] = (uint32_t)(rowA & 7) << 4;
    }
    uint32_t baseB[2], maskB[2];
    uint32_t kqB = (uint32_t)(quad & 1) * 16;
#pragma unroll
    for (int n2 = 0; n2 < 2; n2++) {
        int rowB = wn * 32 + n2 * 16 + (quad >> 1) * 8 + r8;
        baseB[n2] = 16384u + (uint32_t)rowB * 128;
        maskB[n2] = (uint32_t)(rowB & 7) << 4;
    }

    int row = tid >> 1, h = tid & 1;
    int ra = bm + row; if (ra > M - 1) ra = M - 1;
    if (gidx) ra = gidx[ra];
    const __nv_bfloat16* pAh = Ahi + (size_t)ra * K + h * 16;
    const __nv_bfloat16* pAl = Alo + (size_t)ra * K + h * 16;
    const __nv_bfloat16* pBh = Bhi + (size_t)(bn + row) * K + h * 16;
    const __nv_bfloat16* pBl = Blo + (size_t)(bn + row) * K + h * 16;
    uint32_t mk = (uint32_t)(row & 7) << 4;
    uint32_t st0 = (uint32_t)row * 128 + (((uint32_t)h * 32) ^ mk);
    uint32_t st1 = (uint32_t)row * 128 + (((uint32_t)h * 32 + 16) ^ mk);
    uint32_t st2 = (uint32_t)row * 128 + ((64u + h * 32) ^ mk);
    uint32_t st3 = (uint32_t)row * 128 + ((64u + h * 32 + 16) ^ mk);

    float acc[4][4][4];
#pragma unroll
    for (int i = 0; i < 4; i++)
#pragma unroll
        for (int j = 0; j < 4; j++)
#pragma unroll
            for (int q = 0; q < 4; q++) acc[i][j][q] = 0.f;

    uint4 sah0, sah1, sal0, sal1, sbh0, sbh1, sbl0, sbl1;
    sah0 = *(const uint4*)(pAh); sah1 = *(const uint4*)(pAh + 8);
    sal0 = *(const uint4*)(pAl); sal1 = *(const uint4*)(pAl + 8);
    sbh0 = *(const uint4*)(pBh); sbh1 = *(const uint4*)(pBh + 8);
    sbl0 = *(const uint4*)(pBl); sbl1 = *(const uint4*)(pBl + 8);
    {
        char* bp = sb;
        *(uint4*)(bp + st0) = sah0; *(uint4*)(bp + st1) = sah1;
        *(uint4*)(bp + st2) = sal0; *(uint4*)(bp + st3) = sal1;
        bp += 16384;
        *(uint4*)(bp + st0) = sbh0; *(uint4*)(bp + st1) = sbh1;
        *(uint4*)(bp + st2) = sbl0; *(uint4*)(bp + st3) = sbl1;
    }
    __syncthreads();

    int nch = K >> 5;
    for (int t = 0; t < nch; t++) {
        uint32_t bufs = smb + (uint32_t)(t & 1) * 32768u;
        if (t + 1 < nch) {
            int kc = (t + 1) * 32;
            sah0 = *(const uint4*)(pAh + kc); sah1 = *(const uint4*)(pAh + kc + 8);
            sal0 = *(const uint4*)(pAl + kc); sal1 = *(const uint4*)(pAl + kc + 8);
            sbh0 = *(const uint4*)(pBh + kc); sbh1 = *(const uint4*)(pBh + kc + 8);
            sbl0 = *(const uint4*)(pBl + kc); sbl1 = *(const uint4*)(pBl + kc + 8);
        }
#pragma unroll
        for (int ks = 0; ks < 2; ks++) {
            uint32_t cbase = kqA + (uint32_t)ks * 32;
            uint32_t ah[4][4], al[4][4], bh[4][2], bl[4][2];
#pragma unroll
            for (int mt = 0; mt < 4; mt++) {
                ldsm4(ah[mt], bufs + baseA[mt] + (cbase ^ maskA[mt]));
                ldsm4(al[mt], bufs + baseA[mt] + ((cbase + 64u) ^ maskA[mt]));
            }
            uint32_t cbB = kqB + (uint32_t)ks * 32;
#pragma unroll
            for (int n2 = 0; n2 < 2; n2++) {
                uint32_t r[4];
                ldsm4(r, bufs + baseB[n2] + (cbB ^ maskB[n2]));
                bh[2 * n2][0] = r[0]; bh[2 * n2][1] = r[1];
                bh[2 * n2 + 1][0] = r[2]; bh[2 * n2 + 1][1] = r[3];
                ldsm4(r, bufs + baseB[n2] + ((cbB + 64u) ^ maskB[n2]));
                bl[2 * n2][0] = r[0]; bl[2 * n2][1] = r[1];
                bl[2 * n2 + 1][0] = r[2]; bl[2 * n2 + 1][1] = r[3];
            }
#pragma unroll
            for (int mt = 0; mt < 4; mt++)
#pragma unroll
                for (int nt = 0; nt < 4; nt++) {
                    mma16816(acc[mt][nt], ah[mt], bh[nt]);
                    mma16816(acc[mt][nt], ah[mt], bl[nt]);
                    mma16816(acc[mt][nt], al[mt], bh[nt]);
                }
        }
        if (t + 1 < nch) {
            char* bp = sb + ((t + 1) & 1) * 32768;
            *(uint4*)(bp + st0) = sah0; *(uint4*)(bp + st1) = sah1;
            *(uint4*)(bp + st2) = sal0; *(uint4*)(bp + st3) = sal1;
            bp += 16384;
            *(uint4*)(bp + st0) = sbh0; *(uint4*)(bp + st1) = sbh1;
            *(uint4*)(bp + st2) = sbl0; *(uint4*)(bp + st3) = sbl1;
            __syncthreads();
        }
    }

    int erow = lane >> 2, ecol = (lane & 3) * 2;
#pragma unroll
    for (int mt = 0; mt < 4; mt++) {
        int gr = bm + wm * 64 + mt * 16 + erow;
#pragma unroll
        for (int nt = 0; nt < 4; nt++) {
            int gc = bn + wn * 32 + nt * 8 + ecol;
            emit2<EPI>(gr,     gc, acc[mt][nt][0], acc[mt][nt][1], M, aux, sidx, scl, outF, outHi, outLo, ldo);
            emit2<EPI>(gr + 8, gc, acc[mt][nt][2], acc[mt][nt][3], M, aux, sidx, scl, outF, outHi, outLo, ldo);
        }
    }
}

// ======== transpose + split: W[K,N] -> WT_hi/lo[N,K] (bf16) ===================
__global__ void tsplit(const float* __restrict__ W, int K, int N,
                       __nv_bfloat16* __restrict__ hi, __nv_bfloat16* __restrict__ lo) {
    __shared__ float t[32][33];
    int n0 = blockIdx.x * 32, k0 = blockIdx.y * 32;
    int tx = threadIdx.x, ty = threadIdx.y;
#pragma unroll
    for (int j = 0; j < 4; j++)
        t[ty + 8 * j][tx] = W[(size_t)(k0 + ty + 8 * j) * N + n0 + tx];
    __syncthreads();
#pragma unroll
    for (int j = 0; j < 4; j++) {
        float v = t[tx][ty + 8 * j];
        size_t o = (size_t)(n0 + ty + 8 * j) * K + k0 + tx;
        __nv_bfloat16 h = __float2bfloat16(v);
        hi[o] = h;
        lo[o] = __float2bfloat16(v - __bfloat162float(h));
    }
}

// ================= LN / routing ===============================================
__device__ __forceinline__ float blockReduceSum(float v) {
    __shared__ float sh[8];
#pragma unroll
    for (int o = 16; o > 0; o >>= 1) v += __shfl_down_sync(0xffffffffu, v, o);
    int w = threadIdx.x >> 5, l = threadIdx.x & 31;
    if (l == 0) sh[w] = v;
    __syncthreads();
    if (threadIdx.x < 8) {
        float r = sh[threadIdx.x];
#pragma unroll
        for (int o = 4; o > 0; o >>= 1) r += __shfl_down_sync(0x000000ffu, r, o);
        if (threadIdx.x == 0) sh[0] = r;
    }
    __syncthreads();
    float res = sh[0];
    __syncthreads();
    return res;
}

// LN1: fp32 out + bf16 hi/lo split (fused)
__global__ void ln_kernel(const float* __restrict__ x, const float* __restrict__ w,
                          const float* __restrict__ b, float* __restrict__ out,
                          __nv_bfloat16* __restrict__ ohi, __nv_bfloat16* __restrict__ olo) {
    int row = blockIdx.x, tid = threadIdx.x;
    float4 v = ((const float4*)(x + (size_t)row * CD))[tid];
    float s = blockReduceSum(v.x + v.y + v.z + v.w);
    float mean = s * (1.0f / CD);
    float dx = v.x - mean, dy = v.y - mean, dz = v.z - mean, dw = v.w - mean;
    float s2 = blockReduceSum(dx * dx + dy * dy + dz * dz + dw * dw);
    float rstd = 1.0f / sqrtf(s2 * (1.0f / CD) + 1e-5f);
    float4 wv = ((const float4*)w)[tid], bv = ((const float4*)b)[tid];
    float4 o = make_float4(dx * rstd * wv.x + bv.x, dy * rstd * wv.y + bv.y,
                           dz * rstd * wv.z + bv.z, dw * rstd * wv.w + bv.w);
    ((float4*)(out + (size_t)row * CD))[tid] = o;
    unsigned h0, l0, h1, l1;
    split2(o.x, o.y, h0, l0);
    split2(o.z, o.w, h1, l1);
    ((uint2*)(ohi + (size_t)row * CD))[tid] = make_uint2(h0, h1);
    ((uint2*)(olo + (size_t)row * CD))[tid] = make_uint2(l0, l1);
}

// LN2 + provisional routing + h split + marginal-token flagging
__global__ void ln2_route_kernel(const float* __restrict__ x2, const float* __restrict__ w,
                                 const float* __restrict__ b, const float* __restrict__ conf_rwkv,
                                 const float* __restrict__ conf_trans, const float* __restrict__ w_diff,
                                 const float* __restrict__ W_aff, const float* __restrict__ capital,
                                 __nv_bfloat16* __restrict__ hhi, __nv_bfloat16* __restrict__ hlo,
                                 float* __restrict__ conf3, int* __restrict__ winner,
                                 int* __restrict__ rc_cnt, int* __restrict__ rc_list) {
    int row = blockIdx.x, tid = threadIdx.x;
    float4 v = ((const float4*)(x2 + (size_t)row * CD))[tid];
    float s = blockReduceSum(v.x + v.y + v.z + v.w);
    float mean = s * (1.0f / CD);
    float dx = v.x - mean, dy = v.y - mean, dz = v.z - mean, dw = v.w - mean;
    float s2 = blockReduceSum(dx * dx + dy * dy + dz * dz + dw * dw);
    float rstd = 1.0f / sqrtf(s2 * (1.0f / CD) + 1e-5f);
    float4 wv = ((const float4*)w)[tid], bv = ((const float4*)b)[tid];
    float4 o = make_float4(dx * rstd * wv.x + bv.x, dy * rstd * wv.y + bv.y,
                           dz * rstd * wv.z + bv.z, dw * rstd * wv.w + bv.w);
    unsigned h0, l0, h1, l1;
    split2(o.x, o.y, h0, l0);
    split2(o.z, o.w, h1, l1);
    ((uint2*)(hhi + (size_t)row * CD))[tid] = make_uint2(h0, h1);
    ((uint2*)(hlo + (size_t)row * CD))[tid] = make_uint2(l0, l1);

    float p[7];
    float4 c0 = ((const float4*)conf_rwkv)[tid];
    float4 c1 = ((const float4*)(conf_rwkv + CD))[tid];
    float4 ct = ((const float4*)conf_trans)[tid];
    float4 wd = ((const float4*)w_diff)[tid];
    p[0] = o.x * c0.x + o.y * c0.y + o.z * c0.z + o.w * c0.w;
    p[1] = o.x * c1.x + o.y * c1.y + o.z * c1.z + o.w * c1.w;
    p[2] = o.x * ct.x + o.y * ct.y + o.z * ct.z + o.w * ct.w;
    p[3] = o.x * wd.x + o.y * wd.y + o.z * wd.z + o.w * wd.w;
    const float* wa = W_aff + (size_t)tid * 12;
#pragma unroll
    for (int e = 0; e < 3; e++)
        p[4 + e] = o.x * wa[e] + o.y * wa[3 + e] + o.z * wa[6 + e] + o.w * wa[9 + e];

    __shared__ float red[7][8];
    int wid = tid >> 5, lid = tid & 31;
#pragma unroll
    for (int q = 0; q < 7; q++) {
        float vv = p[q];
#pragma unroll
        for (int o2 = 16; o2 > 0; o2 >>= 1) vv += __shfl_down_sync(0xffffffffu, vv, o2);
        if (lid == 0) red[q][wid] = vv;
    }
    __syncthreads();
    if (tid == 0) {
        float d[7];
#pragma unroll
        for (int q = 0; q < 7; q++) {
            float t = 0.f;
#pragma unroll
            for (int k = 0; k < 8; k++) t += red[q][k];
            d[q] = t;
        }
        float cf[3] = {sigf(d[0]), sigf(d[1]), sigf(d[2])};
        float diff = sigf(d[3]);
        float bids[3];
#pragma unroll
        for (int e = 0; e < 3; e++) {
            bids[e] = cf[e] * capital[e] * diff + d[4 + e];
            conf3[row * 3 + e] = cf[e];
        }
        int wdx = 0; float best = bids[0];
        if (bids[1] > best) { best = bids[1]; wdx = 1; }
        if (bids[2] > best) { best = bids[2]; wdx = 2; }
        float second = -1e30f;
#pragma unroll
        for (int e = 0; e < 3; e++)
            if (e != wdx && bids[e] > second) second = bids[e];
        winner[row] = wdx;
        if (best - second < 1e-3f) {
            int pos = atomicAdd(rc_cnt, 1);
            if (pos < RC_CAP) rc_list[pos] = row;
        }
    }
}

// exact fp32 recompute of routing for marginal tokens — coalesced GEMV on the
// ORIGINAL row-major fp32 weights (W[k*CD + c], c contiguous across threads).
__global__ void recheck_kernel(const float* __restrict__ x, const float* __restrict__ xln,
                               const float* __restrict__ Wr, const float* __restrict__ Wv,
                               const float* __restrict__ Wo,
                               const float* __restrict__ ln2w, const float* __restrict__ ln2b,
                               const float* __restrict__ conf_rwkv, const float* __restrict__ conf_trans,
                               const float* __restrict__ w_diff, const float* __restrict__ W_aff,
                               const float* __restrict__ capital,
                               const int* __restrict__ rc_cnt, const int* __restrict__ rc_list,
                               int* __restrict__ winner) {
    int n = *rc_cnt; if (n > RC_CAP) n = RC_CAP;
    int bi = blockIdx.x;
    if (bi >= n) return;
    int row = rc_list[bi];
    int tid = threadIdx.x;
    __shared__ float sx[CD];
    __shared__ float su[CD];
    for (int c = tid; c < CD; c += 256) sx[c] = xln[(size_t)row * CD + c];
    __syncthreads();

    // phase 1: r = xln@Wr, v = xln@Wv (coalesced over output cols)
    float racc[4] = {0, 0, 0, 0}, vacc[4] = {0, 0, 0, 0};
    for (int k = 0; k < CD; k++) {
        float xv = sx[k];
        const float* wr = Wr + (size_t)k * CD + tid;
        const float* wv = Wv + (size_t)k * CD + tid;
#pragma unroll
        for (int j = 0; j < 4; j++) {
            racc[j] += xv * wr[j * 256];
            vacc[j] += xv * wv[j * 256];
        }
    }
#pragma unroll
    for (int j = 0; j < 4; j++)
        su[tid + j * 256] = sigf(racc[j]) * vacc[j];
    __syncthreads();

    // phase 2: att = u@Wo; satt = att + x  (reuse sx for satt)
    float oacc[4] = {0, 0, 0, 0};
    for (int k = 0; k < CD; k++) {
        float uv = su[k];
        const float* wo = Wo + (size_t)k * CD + tid;
#pragma unroll
        for (int j = 0; j < 4; j++) oacc[j] += uv * wo[j * 256];
    }
    __syncthreads();
#pragma unroll
    for (int j = 0; j < 4; j++)
        sx[tid + j * 256] = oacc[j] + x[(size_t)row * CD + tid + j * 256];
    __syncthreads();

    // LN2 + routing dots (fp32 exact)
    float ps = 0.f;
    for (int c = tid; c < CD; c += 256) ps += sx[c];
    float mean = blockReduceSum(ps) * (1.0f / CD);
    float ps2 = 0.f;
    for (int c = tid; c < CD; c += 256) { float d = sx[c] - mean; ps2 += d * d; }
    float rstd = 1.0f / sqrtf(blockReduceSum(ps2) * (1.0f / CD) + 1e-5f);

    float p[7] = {0, 0, 0, 0, 0, 0, 0};
    for (int c = tid; c < CD; c += 256) {
        float hc = (sx[c] - mean) * rstd * ln2w[c] + ln2b[c];
        p[0] += hc * conf_rwkv[c];
        p[1] += hc * conf_rwkv[CD + c];
        p[2] += hc * conf_trans[c];
        p[3] += hc * w_diff[c];
        p[4] += hc * W_aff[c * 3 + 0];
        p[5] += hc * W_aff[c * 3 + 1];
        p[6] += hc * W_aff[c * 3 + 2];
    }
    __shared__ float red[7][8];
    int wid = tid >> 5, lid = tid & 31;
#pragma unroll
    for (int q = 0; q < 7; q++) {
        float vv = p[q];
#pragma unroll
        for (int o2 = 16; o2 > 0; o2 >>= 1) vv += __shfl_down_sync(0xffffffffu, vv, o2);
        if (lid == 0) red[q][wid] = vv;
    }
    __syncthreads();
    if (tid == 0) {
        float d[7];
#pragma unroll
        for (int q = 0; q < 7; q++) {
            float t = 0.f;
#pragma unroll
            for (int k = 0; k < 8; k++) t += red[q][k];
            d[q] = t;
        }
        float cf[3] = {sigf(d[0]), sigf(d[1]), sigf(d[2])};
        float diff = sigf(d[3]);
        int wdx = 0; float best = -1e30f;
#pragma unroll
        for (int e = 0; e < 3; e++) {
            float bid = cf[e] * capital[e] * diff + d[4 + e];
            if (bid > best) { best = bid; wdx = e; }
        }
        winner[row] = wdx;
    }
}

__global__ void build_lists(const int* __restrict__ winner, const float* __restrict__ conf3,
                            float* __restrict__ scale_out, int* __restrict__ cnt, int* __restrict__ lst) {
    int i = blockIdx.x * 256 + threadIdx.x;
    if (i >= NT) return;
    int w = winner[i];
    float wc = conf3[i * 3 + w];
    scale_out[i] = wc / (wc + 1e-6f);
    int pos = atomicAdd(&cnt[w], 1);
    lst[w * NT + pos] = i;
}

__global__ void zero_cnt_kernel(int* c, int* rc) {
    if (threadIdx.x < 3) c[threadIdx.x] = 0;
    if (threadIdx.x == 0) *rc = 0;
}

// ================= launch =====================================================
extern "C" void kernel_launch(void* const* d_in, const int* in_sizes, int n_in,
                              void* d_out, int out_size) {
    const float* x = (const float*)d_in[0];
    const float* capital = (const float*)d_in[2];
    const float* ln1w = (const float*)d_in[3], *ln1b = (const float*)d_in[4];
    const float* ln2w = (const float*)d_in[5], *ln2b = (const float*)d_in[6];
    const float* Wr = (const float*)d_in[7], *Wv = (const float*)d_in[8];
    const float* Wo = (const float*)d_in[9], *Ws = (const float*)d_in[10];
    const float* Kr = (const float*)d_in[11], *Vr = (const float*)d_in[12];
    const float* confr = (const float*)d_in[13];
    const float* W1 = (const float*)d_in[14], *W2 = (const float*)d_in[15];
    const float* W3 = (const float*)d_in[16];
    const float* conft = (const float*)d_in[17], *wdiff = (const float*)d_in[18];
    const float* Waff = (const float*)d_in[19];
    float* out = (float*)d_out;

    void* p;
    cudaGetSymbolAddress(&p, g_xln);    float* xln = (float*)p;
    cudaGetSymbolAddress(&p, g_r);      float* rb = (float*)p;
    cudaGetSymbolAddress(&p, g_a);      float* ab = (float*)p;
    cudaGetSymbolAddress(&p, g_scale);  float* sclp = (float*)p;
    cudaGetSymbolAddress(&p, g_cnt);    int* cnt = (int*)p;
    cudaGetSymbolAddress(&p, g_list);   int* lst = (int*)p;
    cudaGetSymbolAddress(&p, g_winner); int* win = (int*)p;
    cudaGetSymbolAddress(&p, g_conf3);  float* conf3 = (float*)p;
    cudaGetSymbolAddress(&p, g_rc_cnt); int* rc_cnt = (int*)p;
    cudaGetSymbolAddress(&p, g_rc_list);int* rc_list = (int*)p;
    cudaGetSymbolAddress(&p, g_hhi);    __nv_bfloat16* hhi = (__nv_bfloat16*)p;
    cudaGetSymbolAddress(&p, g_hlo);    __nv_bfloat16* hlo = (__nv_bfloat16*)p;
    cudaGetSymbolAddress(&p, g_shi);    __nv_bfloat16* shi = (__nv_bfloat16*)p;
    cudaGetSymbolAddress(&p, g_slo);    __nv_bfloat16* slo = (__nv_bfloat16*)p;
    cudaGetSymbolAddress(&p, g_ahi);    __nv_bfloat16* ahi = (__nv_bfloat16*)p;
    cudaGetSymbolAddress(&p, g_alo);    __nv_bfloat16* alo = (__nv_bfloat16*)p;
    cudaGetSymbolAddress(&p, g_hrhi);   __nv_bfloat16* hrhi = (__nv_bfloat16*)p;
    cudaGetSymbolAddress(&p, g_hrlo);   __nv_bfloat16* hrlo = (__nv_bfloat16*)p;
    cudaGetSymbolAddress(&p, g_wthi);   __nv_bfloat16* wthi = (__nv_bfloat16*)p;
    cudaGetSymbolAddress(&p, g_wtlo);   __nv_bfloat16* wtlo = (__nv_bfloat16*)p;

    cudaFuncSetAttribute(tgemm<TEPI_HR>,      cudaFuncAttributeMaxDynamicSharedMemorySize, TG_SMEM);
    cudaFuncSetAttribute(tgemm<TEPI_STORE>,   cudaFuncAttributeMaxDynamicSharedMemorySize, TG_SMEM);
    cudaFuncSetAttribute(tgemm<TEPI_GATE>,    cudaFuncAttributeMaxDynamicSharedMemorySize, TG_SMEM);
    cudaFuncSetAttribute(tgemm<TEPI_SCATTER>, cudaFuncAttributeMaxDynamicSharedMemorySize, TG_SMEM);
    cudaFuncSetAttribute(tgemm<TEPI_SPLIT>,   cudaFuncAttributeMaxDynamicSharedMemorySize, TG_SMEM);
    cudaFuncSetAttribute(tgemm<TEPI_GATE2>,   cudaFuncAttributeMaxDynamicSharedMemorySize, TG_SMEM);
    cudaFuncSetAttribute(tgemm<TEPI_ADDX>,    cudaFuncAttributeMaxDynamicSharedMemorySize, TG_SMEM);

    const size_t M1 = 1048576;
    const size_t KR0T = 0, KR1T = 4 * M1, VR0T = 8 * M1, VR1T = 12 * M1;
    const size_t W1T = 16 * M1, W2T = 17 * M1, W3T = 18 * M1;
    const size_t WRT = 19 * M1, WVT = 20 * M1, WOT = 21 * M1, WST = 22 * M1;

    dim3 blk(256), tb(32, 8);
    dim3 gC(NT / 128, CD / 128), gH(NT / 128, HD / 128);

    // weight transpose+split (bf16 hi/lo)
    tsplit<<<dim3(HD / 32, CD / 32), tb>>>(Kr, CD, HD, wthi + KR0T, wtlo + KR0T);
    tsplit<<<dim3(HD / 32, CD / 32), tb>>>(Kr + (size_t)CD * HD, CD, HD, wthi + KR1T, wtlo + KR1T);
    tsplit<<<dim3(CD / 32, HD / 32), tb>>>(Vr, HD, CD, wthi + VR0T, wtlo + VR0T);
    tsplit<<<dim3(CD / 32, HD / 32), tb>>>(Vr + (size_t)HD * CD, HD, CD, wthi + VR1T, wtlo + VR1T);
    tsplit<<<dim3(CD / 32, CD / 32), tb>>>(W1, CD, CD, wthi + W1T, wtlo + W1T);
    tsplit<<<dim3(CD / 32, CD / 32), tb>>>(W2, CD, CD, wthi + W2T, wtlo + W2T);
    tsplit<<<dim3(CD / 32, CD / 32), tb>>>(W3, CD, CD, wthi + W3T, wtlo + W3T);
    tsplit<<<dim3(CD / 32, CD / 32), tb>>>(Wr, CD, CD, wthi + WRT, wtlo + WRT);
    tsplit<<<dim3(CD / 32, CD / 32), tb>>>(Wv, CD, CD, wthi + WVT, wtlo + WVT);
    tsplit<<<dim3(CD / 32, CD / 32), tb>>>(Wo, CD, CD, wthi + WOT, wtlo + WOT);
    tsplit<<<dim3(CD / 32, CD / 32), tb>>>(Ws, CD, CD, wthi + WST, wtlo + WST);

    zero_cnt_kernel<<<1, 32>>>(cnt, rc_cnt);
    ln_kernel<<<NT, 256>>>(x, ln1w, ln1b, xln, hhi, hlo);   // xln split -> hhi/hlo (temp)

    // attention path: bf16x3 HMMA
    tgemm<TEPI_STORE><<<gC, blk, TG_SMEM>>>(hhi, hlo, wthi + WRT, wtlo + WRT, NT, nullptr, CD,
                                            nullptr, nullptr, nullptr, nullptr, rb, nullptr, nullptr, CD);
    tgemm<TEPI_GATE2><<<gC, blk, TG_SMEM>>>(hhi, hlo, wthi + WVT, wtlo + WVT, NT, nullptr, CD,
                                            nullptr, rb, nullptr, nullptr, nullptr, ahi, alo, CD);
    tgemm<TEPI_SPLIT><<<gC, blk, TG_SMEM>>>(hhi, hlo, wthi + WST, wtlo + WST, NT, nullptr, CD,
                                            nullptr, nullptr, nullptr, nullptr, nullptr, shi, slo, CD);
    tgemm<TEPI_ADDX><<<gC, blk, TG_SMEM>>>(ahi, alo, wthi + WOT, wtlo + WOT, NT, nullptr, CD,
                                           nullptr, x, nullptr, nullptr, out, nullptr, nullptr, CD);

    // routing (provisional) + h split; recheck marginal tokens exactly; build lists
    ln2_route_kernel<<<NT, 256>>>(out, ln2w, ln2b, confr, conft, wdiff, Waff, capital,
                                  hhi, hlo, conf3, win, rc_cnt, rc_list);
    recheck_kernel<<<RC_CAP, 256>>>(x, xln, Wr, Wv, Wo, ln2w, ln2b, confr, conft, wdiff,
                                    Waff, capital, rc_cnt, rc_list, win);
    build_lists<<<NT / 256, 256>>>(win, conf3, sclp, cnt, lst);

    // transformer expert (winner == 2)
    tgemm<TEPI_STORE><<<gC, blk, TG_SMEM>>>(hhi, hlo, wthi + W1T, wtlo + W1T, 0, cnt + 2, CD,
                                            lst + 2 * NT, nullptr, nullptr, nullptr, ab, nullptr, nullptr, CD);
    tgemm<TEPI_GATE><<<gC, blk, TG_SMEM>>>(shi, slo, wthi + W2T, wtlo + W2T, 0, cnt + 2, CD,
                                           lst + 2 * NT, ab, nullptr, nullptr, nullptr, ahi, alo, CD);
    tgemm<TEPI_SCATTER><<<gC, blk, TG_SMEM>>>(ahi, alo, wthi + W3T, wtlo + W3T, 0, cnt + 2, CD,
                                              nullptr, nullptr, lst + 2 * NT, sclp, out, nullptr, nullptr, CD);

    // RWKV experts
    for (int e = 0; e < 2; e++) {
        tgemm<TEPI_HR><<<gH, blk, TG_SMEM>>>(hhi, hlo, wthi + (e ? KR1T : KR0T), wtlo + (e ? KR1T : KR0T),
                                             0, cnt + e, CD, lst + e * NT, nullptr, nullptr, nullptr,
                                             nullptr, hrhi, hrlo, HD);
        tgemm<TEPI_SCATTER><<<gC, blk, TG_SMEM>>>(hrhi, hrlo, wthi + (e ? VR1T : VR0T), wtlo + (e ? VR1T : VR0T),
                                                  0, cnt + e, HD, nullptr, nullptr, lst + e * NT, sclp,
                                                  out, nullptr, nullptr, CD);
    }
}

// round 8
// speedup vs baseline: 1.5609x; 1.1791x over previous
#include <cuda_runtime.h>
#include <cuda_bf16.h>
#include <math.h>
#include <stdint.h>

#define NT 8192
#define CD 1024
#define HD 4096
#define RC_CAP 512

// ---------------- scratch ----------------------------------------------------
__device__ __align__(16) float g_xln[NT * CD];
__device__ __align__(16) float g_r[NT * CD];
__device__ __align__(16) float g_a[NT * CD];
__device__ float g_scale[NT];
__device__ int g_cnt[3];
__device__ int g_list[3 * NT];
__device__ int g_winner[NT];
__device__ float g_conf3[3 * NT];
__device__ int g_rc_cnt;
__device__ int g_rc_list[RC_CAP];
__device__ __align__(16) __nv_bfloat16 g_xhi[NT * CD];   // xln split (persistent)
__device__ __align__(16) __nv_bfloat16 g_xlo[NT * CD];
__device__ __align__(16) __nv_bfloat16 g_hhi[NT * CD];   // h split
__device__ __align__(16) __nv_bfloat16 g_hlo[NT * CD];
__device__ __align__(16) __nv_bfloat16 g_shi[NT * CD];   // sparse rwkv_state split
__device__ __align__(16) __nv_bfloat16 g_slo[NT * CD];
__device__ __align__(16) __nv_bfloat16 g_ahi[NT * CD];   // gated attn, then W2 out
__device__ __align__(16) __nv_bfloat16 g_alo[NT * CD];
__device__ __align__(16) __nv_bfloat16 g_hrhi[NT * HD];
__device__ __align__(16) __nv_bfloat16 g_hrlo[NT * HD];
#define WSZ (23u * 1048576u)
__device__ __align__(16) __nv_bfloat16 g_wthi[WSZ];
__device__ __align__(16) __nv_bfloat16 g_wtlo[WSZ];

// ---------------- helpers ----------------------------------------------------
__device__ __forceinline__ uint32_t smem_u32(const void* p) {
    uint32_t a;
    asm("{ .reg .u64 t; cvta.to.shared.u64 t, %1; cvt.u32.u64 %0, t; }" : "=r"(a) : "l"(p));
    return a;
}
__device__ __forceinline__ void ldsm4(uint32_t* r, uint32_t a) {
    asm volatile("ldmatrix.sync.aligned.m8n8.x4.shared.b16 {%0,%1,%2,%3}, [%4];"
                 : "=r"(r[0]), "=r"(r[1]), "=r"(r[2]), "=r"(r[3]) : "r"(a));
}
__device__ __forceinline__ void mma16816(float* d, const uint32_t* a, const uint32_t* b) {
    asm volatile("mma.sync.aligned.m16n8k16.row.col.f32.bf16.bf16.f32 "
                 "{%0,%1,%2,%3}, {%4,%5,%6,%7}, {%8,%9}, {%0,%1,%2,%3};"
                 : "+f"(d[0]), "+f"(d[1]), "+f"(d[2]), "+f"(d[3])
                 : "r"(a[0]), "r"(a[1]), "r"(a[2]), "r"(a[3]), "r"(b[0]), "r"(b[1]));
}
__device__ __forceinline__ void cpa16(uint32_t s, const void* g) {
    asm volatile("cp.async.ca.shared.global [%0], [%1], 16;" :: "r"(s), "l"(g));
}
__device__ __forceinline__ float sigf(float x) { return 1.0f / (1.0f + expf(-x)); }
__device__ __forceinline__ unsigned packbf(__nv_bfloat16 a, __nv_bfloat16 b) {
    return (unsigned)__bfloat16_as_ushort(a) | ((unsigned)__bfloat16_as_ushort(b) << 16);
}
__device__ __forceinline__ void split2(float v0, float v1, unsigned& hw, unsigned& lw) {
    __nv_bfloat16 h0 = __float2bfloat16(v0), h1 = __float2bfloat16(v1);
    hw = packbf(h0, h1);
    lw = packbf(__float2bfloat16(v0 - __bfloat162float(h0)),
                __float2bfloat16(v1 - __bfloat162float(h1)));
}

// ================= HMMA tensor GEMM (bf16x3 emulated fp32) ====================
enum { TEPI_HR = 0, TEPI_STORE = 1, TEPI_GATE = 2, TEPI_SCATTER = 3,
       TEPI_SPLIT = 4, TEPI_GATE2 = 5, TEPI_ADDX = 6 };
#define TG_SMEM (2 * 32768 + 1024)

template <int EPI>
__device__ __forceinline__ void emit2(int grow, int gcol, float v0, float v1, int M,
                                      const float* __restrict__ aux,
                                      const int* __restrict__ sidx, const float* __restrict__ scl,
                                      float* __restrict__ outF,
                                      __nv_bfloat16* __restrict__ outHi,
                                      __nv_bfloat16* __restrict__ outLo, int ldo) {
    if (grow >= M) return;
    if (EPI == TEPI_STORE) {
        *(float2*)(outF + (size_t)grow * ldo + gcol) = make_float2(v0, v1);
    } else if (EPI == TEPI_ADDX) {
        float2 a = *(const float2*)(aux + (size_t)grow * CD + gcol);
        *(float2*)(outF + (size_t)grow * ldo + gcol) = make_float2(v0 + a.x, v1 + a.y);
    } else if (EPI == TEPI_SCATTER) {
        int orow = sidx[grow];
        float sc = scl[orow];
        float2* p = (float2*)(outF + (size_t)orow * ldo + gcol);
        float2 c = *p;
        c.x += v0 * sc; c.y += v1 * sc;
        *p = c;
    } else {
        if (EPI == TEPI_HR) {
            v0 = fmaxf(v0, 0.f); v0 *= v0;
            v1 = fmaxf(v1, 0.f); v1 *= v1;
        } else if (EPI == TEPI_GATE) {
            float2 a = *(const float2*)(aux + (size_t)grow * CD + gcol);
            v0 = a.x * sigf(v0); v1 = a.y * sigf(v1);
        } else if (EPI == TEPI_GATE2) {
            float2 a = *(const float2*)(aux + (size_t)grow * CD + gcol);
            v0 = sigf(a.x) * v0; v1 = sigf(a.y) * v1;
        }
        unsigned hw, lw;
        split2(v0, v1, hw, lw);
        *(unsigned*)(outHi + (size_t)grow * ldo + gcol) = hw;
        *(unsigned*)(outLo + (size_t)grow * ldo + gcol) = lw;
    }
}

template <int EPI>
__global__ void __launch_bounds__(256, 2)
tgemm(const __nv_bfloat16* __restrict__ Ahi, const __nv_bfloat16* __restrict__ Alo,
      const __nv_bfloat16* __restrict__ Bhi, const __nv_bfloat16* __restrict__ Blo,
      int Mstat, const int* __restrict__ Mptr, int K,
      const int* __restrict__ gidx, const float* __restrict__ aux,
      const int* __restrict__ sidx, const float* __restrict__ scl,
      float* __restrict__ outF,
      __nv_bfloat16* __restrict__ outHi, __nv_bfloat16* __restrict__ outLo, int ldo) {
    int M = Mptr ? *Mptr : Mstat;
    int bm = blockIdx.x * 128;
    if (bm >= M) return;
    int bn = blockIdx.y * 128;

    extern __shared__ char smraw[];
    uint32_t smb0 = smem_u32(smraw);
    uint32_t smb = (smb0 + 1023u) & ~1023u;

    int tid = threadIdx.x, lane = tid & 31, warp = tid >> 5;
    int wm = warp & 1, wn = warp >> 1;
    int quad = lane >> 3, r8 = lane & 7;

    uint32_t baseA[4], maskA[4];
    uint32_t kqA = (uint32_t)(quad >> 1) * 16;
#pragma unroll
    for (int mt = 0; mt < 4; mt++) {
        int rowA = wm * 64 + mt * 16 + (quad & 1) * 8 + r8;
        baseA[mt] = (uint32_t)rowA * 128;
        maskA[mt] = (uint32_t)(rowA & 7) << 4;
    }
    uint32_t baseB[2], maskB[2];
    uint32_t kqB = (uint32_t)(quad & 1) * 16;
#pragma unroll
    for (int n2 = 0; n2 < 2; n2++) {
        int rowB = wn * 32 + n2 * 16 + (quad >> 1) * 8 + r8;
        baseB[n2] = 16384u + (uint32_t)rowB * 128;
        maskB[n2] = (uint32_t)(rowB & 7) << 4;
    }

    int row = tid >> 1, h = tid & 1;
    int ra = bm + row; if (ra > M - 1) ra = M - 1;
    if (gidx) ra = gidx[ra];
    const __nv_bfloat16* pAh = Ahi + (size_t)ra * K + h * 16;
    const __nv_bfloat16* pAl = Alo + (size_t)ra * K + h * 16;
    const __nv_bfloat16* pBh = Bhi + (size_t)(bn + row) * K + h * 16;
    const __nv_bfloat16* pBl = Blo + (size_t)(bn + row) * K + h * 16;
    uint32_t mk = (uint32_t)(row & 7) << 4;
    uint32_t st0 = (uint32_t)row * 128 + (((uint32_t)h * 32) ^ mk);
    uint32_t st1 = (uint32_t)row * 128 + (((uint32_t)h * 32 + 16) ^ mk);
    uint32_t st2 = (uint32_t)row * 128 + ((64u + h * 32) ^ mk);
    uint32_t st3 = (uint32_t)row * 128 + ((64u + h * 32 + 16) ^ mk);

    auto stage = [&](int t, int buf) {
        int kc = t * 32;
        uint32_t ab = smb + (uint32_t)buf * 32768u;
        uint32_t bb = ab + 16384u;
        cpa16(ab + st0, pAh + kc); cpa16(ab + st1, pAh + kc + 8);
        cpa16(ab + st2, pAl + kc); cpa16(ab + st3, pAl + kc + 8);
        cpa16(bb + st0, pBh + kc); cpa16(bb + st1, pBh + kc + 8);
        cpa16(bb + st2, pBl + kc); cpa16(bb + st3, pBl + kc + 8);
        asm volatile("cp.async.commit_group;" ::: "memory");
    };

    float acc[4][4][4];
#pragma unroll
    for (int i = 0; i < 4; i++)
#pragma unroll
        for (int j = 0; j < 4; j++)
#pragma unroll
            for (int q = 0; q < 4; q++) acc[i][j][q] = 0.f;

    int nch = K >> 5;   // >= 2 always (K = 1024 or 4096)
    stage(0, 0);
    stage(1, 1);

    for (int t = 0; t < nch; t++) {
        if (t + 1 < nch) asm volatile("cp.async.wait_group 1;" ::: "memory");
        else             asm volatile("cp.async.wait_group 0;" ::: "memory");
        __syncthreads();
        uint32_t bufs = smb + (uint32_t)(t & 1) * 32768u;
#pragma unroll
        for (int ks = 0; ks < 2; ks++) {
            uint32_t cbB = kqB + (uint32_t)ks * 32;
            uint32_t bh[4][2], bl[4][2];
#pragma unroll
            for (int n2 = 0; n2 < 2; n2++) {
                uint32_t r[4];
                ldsm4(r, bufs + baseB[n2] + (cbB ^ maskB[n2]));
                bh[2 * n2][0] = r[0]; bh[2 * n2][1] = r[1];
                bh[2 * n2 + 1][0] = r[2]; bh[2 * n2 + 1][1] = r[3];
                ldsm4(r, bufs + baseB[n2] + ((cbB + 64u) ^ maskB[n2]));
                bl[2 * n2][0] = r[0]; bl[2 * n2][1] = r[1];
                bl[2 * n2 + 1][0] = r[2]; bl[2 * n2 + 1][1] = r[3];
            }
            uint32_t cbase = kqA + (uint32_t)ks * 32;
#pragma unroll
            for (int mt = 0; mt < 4; mt++) {
                uint32_t ah[4], al[4];
                ldsm4(ah, bufs + baseA[mt] + (cbase ^ maskA[mt]));
                ldsm4(al, bufs + baseA[mt] + ((cbase + 64u) ^ maskA[mt]));
#pragma unroll
                for (int nt = 0; nt < 4; nt++) {
                    mma16816(acc[mt][nt], ah, bh[nt]);
                    mma16816(acc[mt][nt], ah, bl[nt]);
                    mma16816(acc[mt][nt], al, bh[nt]);
                }
            }
        }
        __syncthreads();
        if (t + 2 < nch) stage(t + 2, t & 1);
    }

    int erow = lane >> 2, ecol = (lane & 3) * 2;
#pragma unroll
    for (int mt = 0; mt < 4; mt++) {
        int gr = bm + wm * 64 + mt * 16 + erow;
#pragma unroll
        for (int nt = 0; nt < 4; nt++) {
            int gc = bn + wn * 32 + nt * 8 + ecol;
            emit2<EPI>(gr,     gc, acc[mt][nt][0], acc[mt][nt][1], M, aux, sidx, scl, outF, outHi, outLo, ldo);
            emit2<EPI>(gr + 8, gc, acc[mt][nt][2], acc[mt][nt][3], M, aux, sidx, scl, outF, outHi, outLo, ldo);
        }
    }
}

// ======== transpose + split: W[K,N] -> WT_hi/lo[N,K] (bf16) ===================
__global__ void tsplit(const float* __restrict__ W, int K, int N,
                       __nv_bfloat16* __restrict__ hi, __nv_bfloat16* __restrict__ lo) {
    __shared__ float t[32][33];
    int n0 = blockIdx.x * 32, k0 = blockIdx.y * 32;
    int tx = threadIdx.x, ty = threadIdx.y;
#pragma unroll
    for (int j = 0; j < 4; j++)
        t[ty + 8 * j][tx] = W[(size_t)(k0 + ty + 8 * j) * N + n0 + tx];
    __syncthreads();
#pragma unroll
    for (int j = 0; j < 4; j++) {
        float v = t[tx][ty + 8 * j];
        size_t o = (size_t)(n0 + ty + 8 * j) * K + k0 + tx;
        __nv_bfloat16 h = __float2bfloat16(v);
        hi[o] = h;
        lo[o] = __float2bfloat16(v - __bfloat162float(h));
    }
}

// ================= LN / routing ===============================================
__device__ __forceinline__ float blockReduceSum(float v) {
    __shared__ float sh[8];
#pragma unroll
    for (int o = 16; o > 0; o >>= 1) v += __shfl_down_sync(0xffffffffu, v, o);
    int w = threadIdx.x >> 5, l = threadIdx.x & 31;
    if (l == 0) sh[w] = v;
    __syncthreads();
    if (threadIdx.x < 8) {
        float r = sh[threadIdx.x];
#pragma unroll
        for (int o = 4; o > 0; o >>= 1) r += __shfl_down_sync(0x000000ffu, r, o);
        if (threadIdx.x == 0) sh[0] = r;
    }
    __syncthreads();
    float res = sh[0];
    __syncthreads();
    return res;
}

__global__ void ln_kernel(const float* __restrict__ x, const float* __restrict__ w,
                          const float* __restrict__ b, float* __restrict__ out,
                          __nv_bfloat16* __restrict__ ohi, __nv_bfloat16* __restrict__ olo) {
    int row = blockIdx.x, tid = threadIdx.x;
    float4 v = ((const float4*)(x + (size_t)row * CD))[tid];
    float s = blockReduceSum(v.x + v.y + v.z + v.w);
    float mean = s * (1.0f / CD);
    float dx = v.x - mean, dy = v.y - mean, dz = v.z - mean, dw = v.w - mean;
    float s2 = blockReduceSum(dx * dx + dy * dy + dz * dz + dw * dw);
    float rstd = 1.0f / sqrtf(s2 * (1.0f / CD) + 1e-5f);
    float4 wv = ((const float4*)w)[tid], bv = ((const float4*)b)[tid];
    float4 o = make_float4(dx * rstd * wv.x + bv.x, dy * rstd * wv.y + bv.y,
                           dz * rstd * wv.z + bv.z, dw * rstd * wv.w + bv.w);
    ((float4*)(out + (size_t)row * CD))[tid] = o;
    unsigned h0, l0, h1, l1;
    split2(o.x, o.y, h0, l0);
    split2(o.z, o.w, h1, l1);
    ((uint2*)(ohi + (size_t)row * CD))[tid] = make_uint2(h0, h1);
    ((uint2*)(olo + (size_t)row * CD))[tid] = make_uint2(l0, l1);
}

__global__ void ln2_route_kernel(const float* __restrict__ x2, const float* __restrict__ w,
                                 const float* __restrict__ b, const float* __restrict__ conf_rwkv,
                                 const float* __restrict__ conf_trans, const float* __restrict__ w_diff,
                                 const float* __restrict__ W_aff, const float* __restrict__ capital,
                                 __nv_bfloat16* __restrict__ hhi, __nv_bfloat16* __restrict__ hlo,
                                 float* __restrict__ conf3, int* __restrict__ winner,
                                 int* __restrict__ rc_cnt, int* __restrict__ rc_list) {
    int row = blockIdx.x, tid = threadIdx.x;
    float4 v = ((const float4*)(x2 + (size_t)row * CD))[tid];
    float s = blockReduceSum(v.x + v.y + v.z + v.w);
    float mean = s * (1.0f / CD);
    float dx = v.x - mean, dy = v.y - mean, dz = v.z - mean, dw = v.w - mean;
    float s2 = blockReduceSum(dx * dx + dy * dy + dz * dz + dw * dw);
    float rstd = 1.0f / sqrtf(s2 * (1.0f / CD) + 1e-5f);
    float4 wv = ((const float4*)w)[tid], bv = ((const float4*)b)[tid];
    float4 o = make_float4(dx * rstd * wv.x + bv.x, dy * rstd * wv.y + bv.y,
                           dz * rstd * wv.z + bv.z, dw * rstd * wv.w + bv.w);
    unsigned h0, l0, h1, l1;
    split2(o.x, o.y, h0, l0);
    split2(o.z, o.w, h1, l1);
    ((uint2*)(hhi + (size_t)row * CD))[tid] = make_uint2(h0, h1);
    ((uint2*)(hlo + (size_t)row * CD))[tid] = make_uint2(l0, l1);

    float p[7];
    float4 c0 = ((const float4*)conf_rwkv)[tid];
    float4 c1 = ((const float4*)(conf_rwkv + CD))[tid];
    float4 ct = ((const float4*)conf_trans)[tid];
    float4 wd = ((const float4*)w_diff)[tid];
    p[0] = o.x * c0.x + o.y * c0.y + o.z * c0.z + o.w * c0.w;
    p[1] = o.x * c1.x + o.y * c1.y + o.z * c1.z + o.w * c1.w;
    p[2] = o.x * ct.x + o.y * ct.y + o.z * ct.z + o.w * ct.w;
    p[3] = o.x * wd.x + o.y * wd.y + o.z * wd.z + o.w * wd.w;
    const float* wa = W_aff + (size_t)tid * 12;
#pragma unroll
    for (int e = 0; e < 3; e++)
        p[4 + e] = o.x * wa[e] + o.y * wa[3 + e] + o.z * wa[6 + e] + o.w * wa[9 + e];

    __shared__ float red[7][8];
    int wid = tid >> 5, lid = tid & 31;
#pragma unroll
    for (int q = 0; q < 7; q++) {
        float vv = p[q];
#pragma unroll
        for (int o2 = 16; o2 > 0; o2 >>= 1) vv += __shfl_down_sync(0xffffffffu, vv, o2);
        if (lid == 0) red[q][wid] = vv;
    }
    __syncthreads();
    if (tid == 0) {
        float d[7];
#pragma unroll
        for (int q = 0; q < 7; q++) {
            float t = 0.f;
#pragma unroll
            for (int k = 0; k < 8; k++) t += red[q][k];
            d[q] = t;
        }
        float cf[3] = {sigf(d[0]), sigf(d[1]), sigf(d[2])};
        float diff = sigf(d[3]);
        float bids[3];
#pragma unroll
        for (int e = 0; e < 3; e++) {
            bids[e] = cf[e] * capital[e] * diff + d[4 + e];
            conf3[row * 3 + e] = cf[e];
        }
        int wdx = 0; float best = bids[0];
        if (bids[1] > best) { best = bids[1]; wdx = 1; }
        if (bids[2] > best) { best = bids[2]; wdx = 2; }
        float second = -1e30f;
#pragma unroll
        for (int e = 0; e < 3; e++)
            if (e != wdx && bids[e] > second) second = bids[e];
        winner[row] = wdx;
        if (best - second < 1e-3f) {
            int pos = atomicAdd(rc_cnt, 1);
            if (pos < RC_CAP) rc_list[pos] = row;
        }
    }
}

// exact fp32 recompute of routing for marginal tokens (coalesced row-major GEMV)
__global__ void recheck_kernel(const float* __restrict__ x, const float* __restrict__ xln,
                               const float* __restrict__ Wr, const float* __restrict__ Wv,
                               const float* __restrict__ Wo,
                               const float* __restrict__ ln2w, const float* __restrict__ ln2b,
                               const float* __restrict__ conf_rwkv, const float* __restrict__ conf_trans,
                               const float* __restrict__ w_diff, const float* __restrict__ W_aff,
                               const float* __restrict__ capital,
                               const int* __restrict__ rc_cnt, const int* __restrict__ rc_list,
                               int* __restrict__ winner) {
    int n = *rc_cnt; if (n > RC_CAP) n = RC_CAP;
    int bi = blockIdx.x;
    if (bi >= n) return;
    int row = rc_list[bi];
    int tid = threadIdx.x;
    __shared__ float sx[CD];
    __shared__ float su[CD];
    for (int c = tid; c < CD; c += 256) sx[c] = xln[(size_t)row * CD + c];
    __syncthreads();

    float racc[4] = {0, 0, 0, 0}, vacc[4] = {0, 0, 0, 0};
    for (int k = 0; k < CD; k++) {
        float xv = sx[k];
        const float* wr = Wr + (size_t)k * CD + tid;
        const float* wv = Wv + (size_t)k * CD + tid;
#pragma unroll
        for (int j = 0; j < 4; j++) {
            racc[j] += xv * wr[j * 256];
            vacc[j] += xv * wv[j * 256];
        }
    }
#pragma unroll
    for (int j = 0; j < 4; j++)
        su[tid + j * 256] = sigf(racc[j]) * vacc[j];
    __syncthreads();

    float oacc[4] = {0, 0, 0, 0};
    for (int k = 0; k < CD; k++) {
        float uv = su[k];
        const float* wo = Wo + (size_t)k * CD + tid;
#pragma unroll
        for (int j = 0; j < 4; j++) oacc[j] += uv * wo[j * 256];
    }
    __syncthreads();
#pragma unroll
    for (int j = 0; j < 4; j++)
        sx[tid + j * 256] = oacc[j] + x[(size_t)row * CD + tid + j * 256];
    __syncthreads();

    float ps = 0.f;
    for (int c = tid; c < CD; c += 256) ps += sx[c];
    float mean = blockReduceSum(ps) * (1.0f / CD);
    float ps2 = 0.f;
    for (int c = tid; c < CD; c += 256) { float d = sx[c] - mean; ps2 += d * d; }
    float rstd = 1.0f / sqrtf(blockReduceSum(ps2) * (1.0f / CD) + 1e-5f);

    float p[7] = {0, 0, 0, 0, 0, 0, 0};
    for (int c = tid; c < CD; c += 256) {
        float hc = (sx[c] - mean) * rstd * ln2w[c] + ln2b[c];
        p[0] += hc * conf_rwkv[c];
        p[1] += hc * conf_rwkv[CD + c];
        p[2] += hc * conf_trans[c];
        p[3] += hc * w_diff[c];
        p[4] += hc * W_aff[c * 3 + 0];
        p[5] += hc * W_aff[c * 3 + 1];
        p[6] += hc * W_aff[c * 3 + 2];
    }
    __shared__ float red[7][8];
    int wid = tid >> 5, lid = tid & 31;
#pragma unroll
    for (int q = 0; q < 7; q++) {
        float vv = p[q];
#pragma unroll
        for (int o2 = 16; o2 > 0; o2 >>= 1) vv += __shfl_down_sync(0xffffffffu, vv, o2);
        if (lid == 0) red[q][wid] = vv;
    }
    __syncthreads();
    if (tid == 0) {
        float d[7];
#pragma unroll
        for (int q = 0; q < 7; q++) {
            float t = 0.f;
#pragma unroll
            for (int k = 0; k < 8; k++) t += red[q][k];
            d[q] = t;
        }
        float cf[3] = {sigf(d[0]), sigf(d[1]), sigf(d[2])};
        float diff = sigf(d[3]);
        int wdx = 0; float best = -1e30f;
#pragma unroll
        for (int e = 0; e < 3; e++) {
            float bid = cf[e] * capital[e] * diff + d[4 + e];
            if (bid > best) { best = bid; wdx = e; }
        }
        winner[row] = wdx;
    }
}

__global__ void build_lists(const int* __restrict__ winner, const float* __restrict__ conf3,
                            float* __restrict__ scale_out, int* __restrict__ cnt, int* __restrict__ lst) {
    int i = blockIdx.x * 256 + threadIdx.x;
    if (i >= NT) return;
    int w = winner[i];
    float wc = conf3[i * 3 + w];
    scale_out[i] = wc / (wc + 1e-6f);
    int pos = atomicAdd(&cnt[w], 1);
    lst[w * NT + pos] = i;
}

__global__ void zero_cnt_kernel(int* c, int* rc) {
    if (threadIdx.x < 3) c[threadIdx.x] = 0;
    if (threadIdx.x == 0) *rc = 0;
}

// ================= launch =====================================================
extern "C" void kernel_launch(void* const* d_in, const int* in_sizes, int n_in,
                              void* d_out, int out_size) {
    const float* x = (const float*)d_in[0];
    const float* capital = (const float*)d_in[2];
    const float* ln1w = (const float*)d_in[3], *ln1b = (const float*)d_in[4];
    const float* ln2w = (const float*)d_in[5], *ln2b = (const float*)d_in[6];
    const float* Wr = (const float*)d_in[7], *Wv = (const float*)d_in[8];
    const float* Wo = (const float*)d_in[9], *Ws = (const float*)d_in[10];
    const float* Kr = (const float*)d_in[11], *Vr = (const float*)d_in[12];
    const float* confr = (const float*)d_in[13];
    const float* W1 = (const float*)d_in[14], *W2 = (const float*)d_in[15];
    const float* W3 = (const float*)d_in[16];
    const float* conft = (const float*)d_in[17], *wdiff = (const float*)d_in[18];
    const float* Waff = (const float*)d_in[19];
    float* out = (float*)d_out;

    void* p;
    cudaGetSymbolAddress(&p, g_xln);    float* xln = (float*)p;
    cudaGetSymbolAddress(&p, g_r);      float* rb = (float*)p;
    cudaGetSymbolAddress(&p, g_a);      float* ab = (float*)p;
    cudaGetSymbolAddress(&p, g_scale);  float* sclp = (float*)p;
    cudaGetSymbolAddress(&p, g_cnt);    int* cnt = (int*)p;
    cudaGetSymbolAddress(&p, g_list);   int* lst = (int*)p;
    cudaGetSymbolAddress(&p, g_winner); int* win = (int*)p;
    cudaGetSymbolAddress(&p, g_conf3);  float* conf3 = (float*)p;
    cudaGetSymbolAddress(&p, g_rc_cnt); int* rc_cnt = (int*)p;
    cudaGetSymbolAddress(&p, g_rc_list);int* rc_list = (int*)p;
    cudaGetSymbolAddress(&p, g_xhi);    __nv_bfloat16* xhi = (__nv_bfloat16*)p;
    cudaGetSymbolAddress(&p, g_xlo);    __nv_bfloat16* xlo = (__nv_bfloat16*)p;
    cudaGetSymbolAddress(&p, g_hhi);    __nv_bfloat16* hhi = (__nv_bfloat16*)p;
    cudaGetSymbolAddress(&p, g_hlo);    __nv_bfloat16* hlo = (__nv_bfloat16*)p;
    cudaGetSymbolAddress(&p, g_shi);    __nv_bfloat16* shi = (__nv_bfloat16*)p;
    cudaGetSymbolAddress(&p, g_slo);    __nv_bfloat16* slo = (__nv_bfloat16*)p;
    cudaGetSymbolAddress(&p, g_ahi);    __nv_bfloat16* ahi = (__nv_bfloat16*)p;
    cudaGetSymbolAddress(&p, g_alo);    __nv_bfloat16* alo = (__nv_bfloat16*)p;
    cudaGetSymbolAddress(&p, g_hrhi);   __nv_bfloat16* hrhi = (__nv_bfloat16*)p;
    cudaGetSymbolAddress(&p, g_hrlo);   __nv_bfloat16* hrlo = (__nv_bfloat16*)p;
    cudaGetSymbolAddress(&p, g_wthi);   __nv_bfloat16* wthi = (__nv_bfloat16*)p;
    cudaGetSymbolAddress(&p, g_wtlo);   __nv_bfloat16* wtlo = (__nv_bfloat16*)p;

    cudaFuncSetAttribute(tgemm<TEPI_HR>,      cudaFuncAttributeMaxDynamicSharedMemorySize, TG_SMEM);
    cudaFuncSetAttribute(tgemm<TEPI_STORE>,   cudaFuncAttributeMaxDynamicSharedMemorySize, TG_SMEM);
    cudaFuncSetAttribute(tgemm<TEPI_GATE>,    cudaFuncAttributeMaxDynamicSharedMemorySize, TG_SMEM);
    cudaFuncSetAttribute(tgemm<TEPI_SCATTER>, cudaFuncAttributeMaxDynamicSharedMemorySize, TG_SMEM);
    cudaFuncSetAttribute(tgemm<TEPI_SPLIT>,   cudaFuncAttributeMaxDynamicSharedMemorySize, TG_SMEM);
    cudaFuncSetAttribute(tgemm<TEPI_GATE2>,   cudaFuncAttributeMaxDynamicSharedMemorySize, TG_SMEM);
    cudaFuncSetAttribute(tgemm<TEPI_ADDX>,    cudaFuncAttributeMaxDynamicSharedMemorySize, TG_SMEM);

    const size_t M1 = 1048576;
    const size_t KR0T = 0, KR1T = 4 * M1, VR0T = 8 * M1, VR1T = 12 * M1;
    const size_t W1T = 16 * M1, W2T = 17 * M1, W3T = 18 * M1;
    const size_t WRT = 19 * M1, WVT = 20 * M1, WOT = 21 * M1, WST = 22 * M1;

    dim3 blk(256), tb(32, 8);
    dim3 gC(NT / 128, CD / 128), gH(NT / 128, HD / 128);

    // weight transpose+split (bf16 hi/lo)
    tsplit<<<dim3(HD / 32, CD / 32), tb>>>(Kr, CD, HD, wthi + KR0T, wtlo + KR0T);
    tsplit<<<dim3(HD / 32, CD / 32), tb>>>(Kr + (size_t)CD * HD, CD, HD, wthi + KR1T, wtlo + KR1T);
    tsplit<<<dim3(CD / 32, HD / 32), tb>>>(Vr, HD, CD, wthi + VR0T, wtlo + VR0T);
    tsplit<<<dim3(CD / 32, HD / 32), tb>>>(Vr + (size_t)HD * CD, HD, CD, wthi + VR1T, wtlo + VR1T);
    tsplit<<<dim3(CD / 32, CD / 32), tb>>>(W1, CD, CD, wthi + W1T, wtlo + W1T);
    tsplit<<<dim3(CD / 32, CD / 32), tb>>>(W2, CD, CD, wthi + W2T, wtlo + W2T);
    tsplit<<<dim3(CD / 32, CD / 32), tb>>>(W3, CD, CD, wthi + W3T, wtlo + W3T);
    tsplit<<<dim3(CD / 32, CD / 32), tb>>>(Wr, CD, CD, wthi + WRT, wtlo + WRT);
    tsplit<<<dim3(CD / 32, CD / 32), tb>>>(Wv, CD, CD, wthi + WVT, wtlo + WVT);
    tsplit<<<dim3(CD / 32, CD / 32), tb>>>(Wo, CD, CD, wthi + WOT, wtlo + WOT);
    tsplit<<<dim3(CD / 32, CD / 32), tb>>>(Ws, CD, CD, wthi + WST, wtlo + WST);

    zero_cnt_kernel<<<1, 32>>>(cnt, rc_cnt);
    ln_kernel<<<NT, 256>>>(x, ln1w, ln1b, xln, xhi, xlo);

    // attention path: bf16x3 HMMA
    tgemm<TEPI_STORE><<<gC, blk, TG_SMEM>>>(xhi, xlo, wthi + WRT, wtlo + WRT, NT, nullptr, CD,
                                            nullptr, nullptr, nullptr, nullptr, rb, nullptr, nullptr, CD);
    tgemm<TEPI_GATE2><<<gC, blk, TG_SMEM>>>(xhi, xlo, wthi + WVT, wtlo + WVT, NT, nullptr, CD,
                                            nullptr, rb, nullptr, nullptr, nullptr, ahi, alo, CD);
    tgemm<TEPI_ADDX><<<gC, blk, TG_SMEM>>>(ahi, alo, wthi + WOT, wtlo + WOT, NT, nullptr, CD,
                                           nullptr, x, nullptr, nullptr, out, nullptr, nullptr, CD);

    // routing (provisional, flags marginal tokens) -> exact recheck -> lists
    ln2_route_kernel<<<NT, 256>>>(out, ln2w, ln2b, confr, conft, wdiff, Waff, capital,
                                  hhi, hlo, conf3, win, rc_cnt, rc_list);
    recheck_kernel<<<RC_CAP, 256>>>(x, xln, Wr, Wv, Wo, ln2w, ln2b, confr, conft, wdiff,
                                    Waff, capital, rc_cnt, rc_list, win);
    build_lists<<<NT / 256, 256>>>(win, conf3, sclp, cnt, lst);

    // rwkv_state = xln @ Ws, SPARSE: winner==2 tokens only, compacted output
    tgemm<TEPI_SPLIT><<<gC, blk, TG_SMEM>>>(xhi, xlo, wthi + WST, wtlo + WST, 0, cnt + 2, CD,
                                            lst + 2 * NT, nullptr, nullptr, nullptr, nullptr, shi, slo, CD);

    // transformer expert (winner == 2)
    tgemm<TEPI_STORE><<<gC, blk, TG_SMEM>>>(hhi, hlo, wthi + W1T, wtlo + W1T, 0, cnt + 2, CD,
                                            lst + 2 * NT, nullptr, nullptr, nullptr, ab, nullptr, nullptr, CD);
    tgemm<TEPI_GATE><<<gC, blk, TG_SMEM>>>(shi, slo, wthi + W2T, wtlo + W2T, 0, cnt + 2, CD,
                                           nullptr, ab, nullptr, nullptr, nullptr, ahi, alo, CD);
    tgemm<TEPI_SCATTER><<<gC, blk, TG_SMEM>>>(ahi, alo, wthi + W3T, wtlo + W3T, 0, cnt + 2, CD,
                                              nullptr, nullptr, lst + 2 * NT, sclp, out, nullptr, nullptr, CD);

    // RWKV experts
    for (int e = 0; e < 2; e++) {
        tgemm<TEPI_HR><<<gH, blk, TG_SMEM>>>(hhi, hlo, wthi + (e ? KR1T : KR0T), wtlo + (e ? KR1T : KR0T),
                                             0, cnt + e, CD, lst + e * NT, nullptr, nullptr, nullptr,
                                             nullptr, hrhi, hrlo, HD);
        tgemm<TEPI_SCATTER><<<gC, blk, TG_SMEM>>>(hrhi, hrlo, wthi + (e ? VR1T : VR0T), wtlo + (e ? VR1T : VR0T),
                                                  0, cnt + e, HD, nullptr, nullptr, lst + e * NT, sclp,
                                                  out, nullptr, nullptr, CD);
    }
}

// round 9
// speedup vs baseline: 1.6492x; 1.0566x over previous
#include <cuda_runtime.h>
#include <cuda_bf16.h>
#include <math.h>
#include <stdint.h>

#define NT 8192
#define CD 1024
#define HD 4096
#define RC_CAP 512

// ---------------- scratch ----------------------------------------------------
__device__ __align__(16) float g_xln[NT * CD];
__device__ __align__(16) float g_r[NT * CD];
__device__ __align__(16) float g_a[NT * CD];
__device__ float g_scale[NT];
__device__ int g_cnt[3];
__device__ int g_list[3 * NT];
__device__ int g_winner[NT];
__device__ float g_conf3[3 * NT];
__device__ int g_rc_cnt;
__device__ int g_rc_list[RC_CAP];
__device__ __align__(16) __nv_bfloat16 g_xhi[NT * CD];
__device__ __align__(16) __nv_bfloat16 g_xlo[NT * CD];
__device__ __align__(16) __nv_bfloat16 g_hhi[NT * CD];
__device__ __align__(16) __nv_bfloat16 g_hlo[NT * CD];
__device__ __align__(16) __nv_bfloat16 g_shi[NT * CD];
__device__ __align__(16) __nv_bfloat16 g_slo[NT * CD];
__device__ __align__(16) __nv_bfloat16 g_ahi[NT * CD];
__device__ __align__(16) __nv_bfloat16 g_alo[NT * CD];
__device__ __align__(16) __nv_bfloat16 g_hr0hi[NT * HD];
__device__ __align__(16) __nv_bfloat16 g_hr0lo[NT * HD];
__device__ __align__(16) __nv_bfloat16 g_hr1hi[NT * HD];
__device__ __align__(16) __nv_bfloat16 g_hr1lo[NT * HD];
#define WSZ (23u * 1048576u)
__device__ __align__(16) __nv_bfloat16 g_wthi[WSZ];
__device__ __align__(16) __nv_bfloat16 g_wtlo[WSZ];

// ---------------- helpers ----------------------------------------------------
__device__ __forceinline__ uint32_t smem_u32(const void* p) {
    uint32_t a;
    asm("{ .reg .u64 t; cvta.to.shared.u64 t, %1; cvt.u32.u64 %0, t; }" : "=r"(a) : "l"(p));
    return a;
}
__device__ __forceinline__ void ldsm4(uint32_t* r, uint32_t a) {
    asm volatile("ldmatrix.sync.aligned.m8n8.x4.shared.b16 {%0,%1,%2,%3}, [%4];"
                 : "=r"(r[0]), "=r"(r[1]), "=r"(r[2]), "=r"(r[3]) : "r"(a));
}
__device__ __forceinline__ void mma16816(float* d, const uint32_t* a, const uint32_t* b) {
    asm volatile("mma.sync.aligned.m16n8k16.row.col.f32.bf16.bf16.f32 "
                 "{%0,%1,%2,%3}, {%4,%5,%6,%7}, {%8,%9}, {%0,%1,%2,%3};"
                 : "+f"(d[0]), "+f"(d[1]), "+f"(d[2]), "+f"(d[3])
                 : "r"(a[0]), "r"(a[1]), "r"(a[2]), "r"(a[3]), "r"(b[0]), "r"(b[1]));
}
__device__ __forceinline__ void cpa16(uint32_t s, const void* g) {
    asm volatile("cp.async.ca.shared.global [%0], [%1], 16;" :: "r"(s), "l"(g));
}
__device__ __forceinline__ float sigf(float x) { return 1.0f / (1.0f + expf(-x)); }
__device__ __forceinline__ unsigned packbf(__nv_bfloat16 a, __nv_bfloat16 b) {
    return (unsigned)__bfloat16_as_ushort(a) | ((unsigned)__bfloat16_as_ushort(b) << 16);
}
__device__ __forceinline__ void split2(float v0, float v1, unsigned& hw, unsigned& lw) {
    __nv_bfloat16 h0 = __float2bfloat16(v0), h1 = __float2bfloat16(v1);
    hw = packbf(h0, h1);
    lw = packbf(__float2bfloat16(v0 - __bfloat162float(h0)),
                __float2bfloat16(v1 - __bfloat162float(h1)));
}

// ================= HMMA tensor GEMM core (bf16x3 emulated fp32) ===============
enum { TEPI_HR = 0, TEPI_STORE = 1, TEPI_GATE = 2, TEPI_SCATTER = 3,
       TEPI_SPLIT = 4, TEPI_GATE2 = 5, TEPI_ADDX = 6 };
#define TG_SMEM (3 * 32768 + 1024)

struct GDesc {
    const __nv_bfloat16 *Ahi, *Alo, *Bhi, *Blo;
    const int* Mptr;
    const int* gidx;
    const float* aux;
    const int* sidx;
    const float* scl;
    float* outF;
    __nv_bfloat16 *outHi, *outLo;
    int K, ldo, Nb;
};

// mainloop: fills acc[4][4][4] for a 128x128 tile; 3-stage cp.async ring, 1 sync/chunk
__device__ __forceinline__ void tg_main(
    const __nv_bfloat16* __restrict__ Ahi, const __nv_bfloat16* __restrict__ Alo,
    const __nv_bfloat16* __restrict__ Bhi, const __nv_bfloat16* __restrict__ Blo,
    int M, int bm, int bn, int K, const int* __restrict__ gidx,
    uint32_t smb, float acc[4][4][4]) {
    int tid = threadIdx.x, lane = tid & 31, warp = tid >> 5;
    int wm = warp & 1, wn = warp >> 1;
    int quad = lane >> 3, r8 = lane & 7;

    uint32_t baseA[4], maskA[4];
    uint32_t kqA = (uint32_t)(quad >> 1) * 16;
#pragma unroll
    for (int mt = 0; mt < 4; mt++) {
        int rowA = wm * 64 + mt * 16 + (quad & 1) * 8 + r8;
        baseA[mt] = (uint32_t)rowA * 128;
        maskA[mt] = (uint32_t)(rowA & 7) << 4;
    }
    uint32_t baseB[2], maskB[2];
    uint32_t kqB = (uint32_t)(quad & 1) * 16;
#pragma unroll
    for (int n2 = 0; n2 < 2; n2++) {
        int rowB = wn * 32 + n2 * 16 + (quad >> 1) * 8 + r8;
        baseB[n2] = 16384u + (uint32_t)rowB * 128;
        maskB[n2] = (uint32_t)(rowB & 7) << 4;
    }

    int row = tid >> 1, h = tid & 1;
    int ra = bm + row; if (ra > M - 1) ra = M - 1;
    if (gidx) ra = gidx[ra];
    const __nv_bfloat16* pAh = Ahi + (size_t)ra * K + h * 16;
    const __nv_bfloat16* pAl = Alo + (size_t)ra * K + h * 16;
    const __nv_bfloat16* pBh = Bhi + (size_t)(bn + row) * K + h * 16;
    const __nv_bfloat16* pBl = Blo + (size_t)(bn + row) * K + h * 16;
    uint32_t mk = (uint32_t)(row & 7) << 4;
    uint32_t st0 = (uint32_t)row * 128 + (((uint32_t)h * 32) ^ mk);
    uint32_t st1 = (uint32_t)row * 128 + (((uint32_t)h * 32 + 16) ^ mk);
    uint32_t st2 = (uint32_t)row * 128 + ((64u + h * 32) ^ mk);
    uint32_t st3 = (uint32_t)row * 128 + ((64u + h * 32 + 16) ^ mk);

    auto stage = [&](int t, int buf) {
        int kc = t * 32;
        uint32_t ab = smb + (uint32_t)buf * 32768u;
        uint32_t bb = ab + 16384u;
        cpa16(ab + st0, pAh + kc); cpa16(ab + st1, pAh + kc + 8);
        cpa16(ab + st2, pAl + kc); cpa16(ab + st3, pAl + kc + 8);
        cpa16(bb + st0, pBh + kc); cpa16(bb + st1, pBh + kc + 8);
        cpa16(bb + st2, pBl + kc); cpa16(bb + st3, pBl + kc + 8);
        asm volatile("cp.async.commit_group;" ::: "memory");
    };

#pragma unroll
    for (int i = 0; i < 4; i++)
#pragma unroll
        for (int j = 0; j < 4; j++)
#pragma unroll
            for (int q = 0; q < 4; q++) acc[i][j][q] = 0.f;

    int nch = K >> 5;
    stage(0, 0);
    stage(1, 1);
    int b0 = 0;
    for (int t = 0; t < nch; t++) {
        if (t + 1 < nch) asm volatile("cp.async.wait_group 1;" ::: "memory");
        else             asm volatile("cp.async.wait_group 0;" ::: "memory");
        __syncthreads();
        if (t + 2 < nch) {
            int nb = b0 + 2; if (nb >= 3) nb -= 3;
            stage(t + 2, nb);
        }
        uint32_t bufs = smb + (uint32_t)b0 * 32768u;
#pragma unroll
        for (int ks = 0; ks < 2; ks++) {
            uint32_t cbB = kqB + (uint32_t)ks * 32;
            uint32_t bh[4][2], bl[4][2];
#pragma unroll
            for (int n2 = 0; n2 < 2; n2++) {
                uint32_t r[4];
                ldsm4(r, bufs + baseB[n2] + (cbB ^ maskB[n2]));
                bh[2 * n2][0] = r[0]; bh[2 * n2][1] = r[1];
                bh[2 * n2 + 1][0] = r[2]; bh[2 * n2 + 1][1] = r[3];
                ldsm4(r, bufs + baseB[n2] + ((cbB + 64u) ^ maskB[n2]));
                bl[2 * n2][0] = r[0]; bl[2 * n2][1] = r[1];
                bl[2 * n2 + 1][0] = r[2]; bl[2 * n2 + 1][1] = r[3];
            }
            uint32_t cbase = kqA + (uint32_t)ks * 32;
#pragma unroll
            for (int mt = 0; mt < 4; mt++) {
                uint32_t ah[4], al[4];
                ldsm4(ah, bufs + baseA[mt] + (cbase ^ maskA[mt]));
                ldsm4(al, bufs + baseA[mt] + ((cbase + 64u) ^ maskA[mt]));
#pragma unroll
                for (int nt = 0; nt < 4; nt++) {
                    mma16816(acc[mt][nt], ah, bh[nt]);
                    mma16816(acc[mt][nt], ah, bl[nt]);
                    mma16816(acc[mt][nt], al, bh[nt]);
                }
            }
        }
        b0++; if (b0 == 3) b0 = 0;
    }
}

template <int EPI>
__device__ __forceinline__ void emit2(int grow, int gcol, float v0, float v1, int M,
                                      const float* __restrict__ aux,
                                      const int* __restrict__ sidx, const float* __restrict__ scl,
                                      float* __restrict__ outF,
                                      __nv_bfloat16* __restrict__ outHi,
                                      __nv_bfloat16* __restrict__ outLo, int ldo) {
    if (grow >= M) return;
    if (EPI == TEPI_STORE) {
        *(float2*)(outF + (size_t)grow * ldo + gcol) = make_float2(v0, v1);
    } else if (EPI == TEPI_ADDX) {
        float2 a = *(const float2*)(aux + (size_t)grow * CD + gcol);
        *(float2*)(outF + (size_t)grow * ldo + gcol) = make_float2(v0 + a.x, v1 + a.y);
    } else if (EPI == TEPI_SCATTER) {
        int orow = sidx[grow];
        float sc = scl[orow];
        float2* p = (float2*)(outF + (size_t)orow * ldo + gcol);
        float2 c = *p;
        c.x += v0 * sc; c.y += v1 * sc;
        *p = c;
    } else {
        if (EPI == TEPI_HR) {
            v0 = fmaxf(v0, 0.f); v0 *= v0;
            v1 = fmaxf(v1, 0.f); v1 *= v1;
        } else if (EPI == TEPI_GATE) {
            float2 a = *(const float2*)(aux + (size_t)grow * CD + gcol);
            v0 = a.x * sigf(v0); v1 = a.y * sigf(v1);
        } else if (EPI == TEPI_GATE2) {
            float2 a = *(const float2*)(aux + (size_t)grow * CD + gcol);
            v0 = sigf(a.x) * v0; v1 = sigf(a.y) * v1;
        }
        unsigned hw, lw;
        split2(v0, v1, hw, lw);
        *(unsigned*)(outHi + (size_t)grow * ldo + gcol) = hw;
        *(unsigned*)(outLo + (size_t)grow * ldo + gcol) = lw;
    }
}

template <int EPI>
__device__ __forceinline__ void tg_epi(int M, int bm, int bn, float acc[4][4][4],
                                       const float* aux, const int* sidx, const float* scl,
                                       float* outF, __nv_bfloat16* outHi, __nv_bfloat16* outLo,
                                       int ldo) {
    int lane = threadIdx.x & 31, warp = threadIdx.x >> 5;
    int wm = warp & 1, wn = warp >> 1;
    int erow = lane >> 2, ecol = (lane & 3) * 2;
#pragma unroll
    for (int mt = 0; mt < 4; mt++) {
        int gr = bm + wm * 64 + mt * 16 + erow;
#pragma unroll
        for (int nt = 0; nt < 4; nt++) {
            int gc = bn + wn * 32 + nt * 8 + ecol;
            emit2<EPI>(gr,     gc, acc[mt][nt][0], acc[mt][nt][1], M, aux, sidx, scl, outF, outHi, outLo, ldo);
            emit2<EPI>(gr + 8, gc, acc[mt][nt][2], acc[mt][nt][3], M, aux, sidx, scl, outF, outHi, outLo, ldo);
        }
    }
}

// single-GEMM kernel
template <int EPI>
__global__ void __launch_bounds__(256, 2)
tgemm(const __nv_bfloat16* __restrict__ Ahi, const __nv_bfloat16* __restrict__ Alo,
      const __nv_bfloat16* __restrict__ Bhi, const __nv_bfloat16* __restrict__ Blo,
      int Mstat, const int* __restrict__ Mptr, int K,
      const int* __restrict__ gidx, const float* __restrict__ aux,
      const int* __restrict__ sidx, const float* __restrict__ scl,
      float* __restrict__ outF,
      __nv_bfloat16* __restrict__ outHi, __nv_bfloat16* __restrict__ outLo, int ldo) {
    int M = Mptr ? *Mptr : Mstat;
    int bm = blockIdx.x * 128;
    if (bm >= M) return;
    int bn = blockIdx.y * 128;
    extern __shared__ char smraw[];
    uint32_t smb0 = smem_u32(smraw);
    uint32_t smb = (smb0 + 1023u) & ~1023u;
    float acc[4][4][4];
    tg_main(Ahi, Alo, Bhi, Blo, M, bm, bn, K, gidx, smb, acc);
    tg_epi<EPI>(M, bm, bn, acc, aux, sidx, scl, outF, outHi, outLo, ldo);
}

// batched multi-GEMM kernel: blockIdx.z selects descriptor
template <int E0, int E1, int E2, int E3>
__global__ void __launch_bounds__(256, 2)
btgemm(GDesc g0, GDesc g1, GDesc g2, GDesc g3) {
    int z = blockIdx.z;
    GDesc g = (z == 0) ? g0 : (z == 1) ? g1 : (z == 2) ? g2 : g3;
    if ((int)blockIdx.y >= g.Nb) return;
    int M = *g.Mptr;
    int bm = blockIdx.x * 128;
    if (bm >= M) return;
    int bn = blockIdx.y * 128;
    extern __shared__ char smraw[];
    uint32_t smb0 = smem_u32(smraw);
    uint32_t smb = (smb0 + 1023u) & ~1023u;
    float acc[4][4][4];
    tg_main(g.Ahi, g.Alo, g.Bhi, g.Blo, M, bm, bn, g.K, g.gidx, smb, acc);
    if (z == 0)      tg_epi<E0>(M, bm, bn, acc, g.aux, g.sidx, g.scl, g.outF, g.outHi, g.outLo, g.ldo);
    else if (z == 1) tg_epi<E1>(M, bm, bn, acc, g.aux, g.sidx, g.scl, g.outF, g.outHi, g.outLo, g.ldo);
    else if (z == 2) tg_epi<E2>(M, bm, bn, acc, g.aux, g.sidx, g.scl, g.outF, g.outHi, g.outLo, g.ldo);
    else             tg_epi<E3>(M, bm, bn, acc, g.aux, g.sidx, g.scl, g.outF, g.outHi, g.outLo, g.ldo);
}

// ======== transpose + split: W[K,N] -> WT_hi/lo[N,K] (bf16) ===================
__global__ void tsplit(const float* __restrict__ W, int K, int N,
                       __nv_bfloat16* __restrict__ hi, __nv_bfloat16* __restrict__ lo) {
    __shared__ float t[32][33];
    int n0 = blockIdx.x * 32, k0 = blockIdx.y * 32;
    int tx = threadIdx.x, ty = threadIdx.y;
#pragma unroll
    for (int j = 0; j < 4; j++)
        t[ty + 8 * j][tx] = W[(size_t)(k0 + ty + 8 * j) * N + n0 + tx];
    __syncthreads();
#pragma unroll
    for (int j = 0; j < 4; j++) {
        float v = t[tx][ty + 8 * j];
        size_t o = (size_t)(n0 + ty + 8 * j) * K + k0 + tx;
        __nv_bfloat16 h = __float2bfloat16(v);
        hi[o] = h;
        lo[o] = __float2bfloat16(v - __bfloat162float(h));
    }
}

// ================= LN / routing ===============================================
__device__ __forceinline__ float blockReduceSum(float v) {
    __shared__ float sh[8];
#pragma unroll
    for (int o = 16; o > 0; o >>= 1) v += __shfl_down_sync(0xffffffffu, v, o);
    int w = threadIdx.x >> 5, l = threadIdx.x & 31;
    if (l == 0) sh[w] = v;
    __syncthreads();
    if (threadIdx.x < 8) {
        float r = sh[threadIdx.x];
#pragma unroll
        for (int o = 4; o > 0; o >>= 1) r += __shfl_down_sync(0x000000ffu, r, o);
        if (threadIdx.x == 0) sh[0] = r;
    }
    __syncthreads();
    float res = sh[0];
    __syncthreads();
    return res;
}

__global__ void ln_kernel(const float* __restrict__ x, const float* __restrict__ w,
                          const float* __restrict__ b, float* __restrict__ out,
                          __nv_bfloat16* __restrict__ ohi, __nv_bfloat16* __restrict__ olo) {
    int row = blockIdx.x, tid = threadIdx.x;
    float4 v = ((const float4*)(x + (size_t)row * CD))[tid];
    float s = blockReduceSum(v.x + v.y + v.z + v.w);
    float mean = s * (1.0f / CD);
    float dx = v.x - mean, dy = v.y - mean, dz = v.z - mean, dw = v.w - mean;
    float s2 = blockReduceSum(dx * dx + dy * dy + dz * dz + dw * dw);
    float rstd = 1.0f / sqrtf(s2 * (1.0f / CD) + 1e-5f);
    float4 wv = ((const float4*)w)[tid], bv = ((const float4*)b)[tid];
    float4 o = make_float4(dx * rstd * wv.x + bv.x, dy * rstd * wv.y + bv.y,
                           dz * rstd * wv.z + bv.z, dw * rstd * wv.w + bv.w);
    ((float4*)(out + (size_t)row * CD))[tid] = o;
    unsigned h0, l0, h1, l1;
    split2(o.x, o.y, h0, l0);
    split2(o.z, o.w, h1, l1);
    ((uint2*)(ohi + (size_t)row * CD))[tid] = make_uint2(h0, h1);
    ((uint2*)(olo + (size_t)row * CD))[tid] = make_uint2(l0, l1);
}

__global__ void ln2_route_kernel(const float* __restrict__ x2, const float* __restrict__ w,
                                 const float* __restrict__ b, const float* __restrict__ conf_rwkv,
                                 const float* __restrict__ conf_trans, const float* __restrict__ w_diff,
                                 const float* __restrict__ W_aff, const float* __restrict__ capital,
                                 __nv_bfloat16* __restrict__ hhi, __nv_bfloat16* __restrict__ hlo,
                                 float* __restrict__ conf3, int* __restrict__ winner,
                                 int* __restrict__ rc_cnt, int* __restrict__ rc_list) {
    int row = blockIdx.x, tid = threadIdx.x;
    float4 v = ((const float4*)(x2 + (size_t)row * CD))[tid];
    float s = blockReduceSum(v.x + v.y + v.z + v.w);
    float mean = s * (1.0f / CD);
    float dx = v.x - mean, dy = v.y - mean, dz = v.z - mean, dw = v.w - mean;
    float s2 = blockReduceSum(dx * dx + dy * dy + dz * dz + dw * dw);
    float rstd = 1.0f / sqrtf(s2 * (1.0f / CD) + 1e-5f);
    float4 wv = ((const float4*)w)[tid], bv = ((const float4*)b)[tid];
    float4 o = make_float4(dx * rstd * wv.x + bv.x, dy * rstd * wv.y + bv.y,
                           dz * rstd * wv.z + bv.z, dw * rstd * wv.w + bv.w);
    unsigned h0, l0, h1, l1;
    split2(o.x, o.y, h0, l0);
    split2(o.z, o.w, h1, l1);
    ((uint2*)(hhi + (size_t)row * CD))[tid] = make_uint2(h0, h1);
    ((uint2*)(hlo + (size_t)row * CD))[tid] = make_uint2(l0, l1);

    float p[7];
    float4 c0 = ((const float4*)conf_rwkv)[tid];
    float4 c1 = ((const float4*)(conf_rwkv + CD))[tid];
    float4 ct = ((const float4*)conf_trans)[tid];
    float4 wd = ((const float4*)w_diff)[tid];
    p[0] = o.x * c0.x + o.y * c0.y + o.z * c0.z + o.w * c0.w;
    p[1] = o.x * c1.x + o.y * c1.y + o.z * c1.z + o.w * c1.w;
    p[2] = o.x * ct.x + o.y * ct.y + o.z * ct.z + o.w * ct.w;
    p[3] = o.x * wd.x + o.y * wd.y + o.z * wd.z + o.w * wd.w;
    const float* wa = W_aff + (size_t)tid * 12;
#pragma unroll
    for (int e = 0; e < 3; e++)
        p[4 + e] = o.x * wa[e] + o.y * wa[3 + e] + o.z * wa[6 + e] + o.w * wa[9 + e];

    __shared__ float red[7][8];
    int wid = tid >> 5, lid = tid & 31;
#pragma unroll
    for (int q = 0; q < 7; q++) {
        float vv = p[q];
#pragma unroll
        for (int o2 = 16; o2 > 0; o2 >>= 1) vv += __shfl_down_sync(0xffffffffu, vv, o2);
        if (lid == 0) red[q][wid] = vv;
    }
    __syncthreads();
    if (tid == 0) {
        float d[7];
#pragma unroll
        for (int q = 0; q < 7; q++) {
            float t = 0.f;
#pragma unroll
            for (int k = 0; k < 8; k++) t += red[q][k];
            d[q] = t;
        }
        float cf[3] = {sigf(d[0]), sigf(d[1]), sigf(d[2])};
        float diff = sigf(d[3]);
        float bids[3];
#pragma unroll
        for (int e = 0; e < 3; e++) {
            bids[e] = cf[e] * capital[e] * diff + d[4 + e];
            conf3[row * 3 + e] = cf[e];
        }
        int wdx = 0; float best = bids[0];
        if (bids[1] > best) { best = bids[1]; wdx = 1; }
        if (bids[2] > best) { best = bids[2]; wdx = 2; }
        float second = -1e30f;
#pragma unroll
        for (int e = 0; e < 3; e++)
            if (e != wdx && bids[e] > second) second = bids[e];
        winner[row] = wdx;
        if (best - second < 1e-3f) {
            int pos = atomicAdd(rc_cnt, 1);
            if (pos < RC_CAP) rc_list[pos] = row;
        }
    }
}

// exact fp32 recompute of routing for marginal tokens (coalesced row-major GEMV)
__global__ void recheck_kernel(const float* __restrict__ x, const float* __restrict__ xln,
                               const float* __restrict__ Wr, const float* __restrict__ Wv,
                               const float* __restrict__ Wo,
                               const float* __restrict__ ln2w, const float* __restrict__ ln2b,
                               const float* __restrict__ conf_rwkv, const float* __restrict__ conf_trans,
                               const float* __restrict__ w_diff, const float* __restrict__ W_aff,
                               const float* __restrict__ capital,
                               const int* __restrict__ rc_cnt, const int* __restrict__ rc_list,
                               int* __restrict__ winner) {
    int n = *rc_cnt; if (n > RC_CAP) n = RC_CAP;
    int bi = blockIdx.x;
    if (bi >= n) return;
    int row = rc_list[bi];
    int tid = threadIdx.x;
    __shared__ float sx[CD];
    __shared__ float su[CD];
    for (int c = tid; c < CD; c += 256) sx[c] = xln[(size_t)row * CD + c];
    __syncthreads();

    float racc[4] = {0, 0, 0, 0}, vacc[4] = {0, 0, 0, 0};
    for (int k = 0; k < CD; k++) {
        float xv = sx[k];
        const float* wr = Wr + (size_t)k * CD + tid;
        const float* wv = Wv + (size_t)k * CD + tid;
#pragma unroll
        for (int j = 0; j < 4; j++) {
            racc[j] += xv * wr[j * 256];
            vacc[j] += xv * wv[j * 256];
        }
    }
#pragma unroll
    for (int j = 0; j < 4; j++)
        su[tid + j * 256] = sigf(racc[j]) * vacc[j];
    __syncthreads();

    float oacc[4] = {0, 0, 0, 0};
    for (int k = 0; k < CD; k++) {
        float uv = su[k];
        const float* wo = Wo + (size_t)k * CD + tid;
#pragma unroll
        for (int j = 0; j < 4; j++) oacc[j] += uv * wo[j * 256];
    }
    __syncthreads();
#pragma unroll
    for (int j = 0; j < 4; j++)
        sx[tid + j * 256] = oacc[j] + x[(size_t)row * CD + tid + j * 256];
    __syncthreads();

    float ps = 0.f;
    for (int c = tid; c < CD; c += 256) ps += sx[c];
    float mean = blockReduceSum(ps) * (1.0f / CD);
    float ps2 = 0.f;
    for (int c = tid; c < CD; c += 256) { float d = sx[c] - mean; ps2 += d * d; }
    float rstd = 1.0f / sqrtf(blockReduceSum(ps2) * (1.0f / CD) + 1e-5f);

    float p[7] = {0, 0, 0, 0, 0, 0, 0};
    for (int c = tid; c < CD; c += 256) {
        float hc = (sx[c] - mean) * rstd * ln2w[c] + ln2b[c];
        p[0] += hc * conf_rwkv[c];
        p[1] += hc * conf_rwkv[CD + c];
        p[2] += hc * conf_trans[c];
        p[3] += hc * w_diff[c];
        p[4] += hc * W_aff[c * 3 + 0];
        p[5] += hc * W_aff[c * 3 + 1];
        p[6] += hc * W_aff[c * 3 + 2];
    }
    __shared__ float red[7][8];
    int wid = tid >> 5, lid = tid & 31;
#pragma unroll
    for (int q = 0; q < 7; q++) {
        float vv = p[q];
#pragma unroll
        for (int o2 = 16; o2 > 0; o2 >>= 1) vv += __shfl_down_sync(0xffffffffu, vv, o2);
        if (lid == 0) red[q][wid] = vv;
    }
    __syncthreads();
    if (tid == 0) {
        float d[7];
#pragma unroll
        for (int q = 0; q < 7; q++) {
            float t = 0.f;
#pragma unroll
            for (int k = 0; k < 8; k++) t += red[q][k];
            d[q] = t;
        }
        float cf[3] = {sigf(d[0]), sigf(d[1]), sigf(d[2])};
        float diff = sigf(d[3]);
        int wdx = 0; float best = -1e30f;
#pragma unroll
        for (int e = 0; e < 3; e++) {
            float bid = cf[e] * capital[e] * diff + d[4 + e];
            if (bid > best) { best = bid; wdx = e; }
        }
        winner[row] = wdx;
    }
}

__global__ void build_lists(const int* __restrict__ winner, const float* __restrict__ conf3,
                            float* __restrict__ scale_out, int* __restrict__ cnt, int* __restrict__ lst) {
    int i = blockIdx.x * 256 + threadIdx.x;
    if (i >= NT) return;
    int w = winner[i];
    float wc = conf3[i * 3 + w];
    scale_out[i] = wc / (wc + 1e-6f);
    int pos = atomicAdd(&cnt[w], 1);
    lst[w * NT + pos] = i;
}

__global__ void zero_cnt_kernel(int* c, int* rc) {
    if (threadIdx.x < 3) c[threadIdx.x] = 0;
    if (threadIdx.x == 0) *rc = 0;
}

// ================= launch =====================================================
extern "C" void kernel_launch(void* const* d_in, const int* in_sizes, int n_in,
                              void* d_out, int out_size) {
    const float* x = (const float*)d_in[0];
    const float* capital = (const float*)d_in[2];
    const float* ln1w = (const float*)d_in[3], *ln1b = (const float*)d_in[4];
    const float* ln2w = (const float*)d_in[5], *ln2b = (const float*)d_in[6];
    const float* Wr = (const float*)d_in[7], *Wv = (const float*)d_in[8];
    const float* Wo = (const float*)d_in[9], *Ws = (const float*)d_in[10];
    const float* Kr = (const float*)d_in[11], *Vr = (const float*)d_in[12];
    const float* confr = (const float*)d_in[13];
    const float* W1 = (const float*)d_in[14], *W2 = (const float*)d_in[15];
    const float* W3 = (const float*)d_in[16];
    const float* conft = (const float*)d_in[17], *wdiff = (const float*)d_in[18];
    const float* Waff = (const float*)d_in[19];
    float* out = (float*)d_out;

    void* p;
    cudaGetSymbolAddress(&p, g_xln);    float* xln = (float*)p;
    cudaGetSymbolAddress(&p, g_r);      float* rb = (float*)p;
    cudaGetSymbolAddress(&p, g_a);      float* ab = (float*)p;
    cudaGetSymbolAddress(&p, g_scale);  float* sclp = (float*)p;
    cudaGetSymbolAddress(&p, g_cnt);    int* cnt = (int*)p;
    cudaGetSymbolAddress(&p, g_list);   int* lst = (int*)p;
    cudaGetSymbolAddress(&p, g_winner); int* win = (int*)p;
    cudaGetSymbolAddress(&p, g_conf3);  float* conf3 = (float*)p;
    cudaGetSymbolAddress(&p, g_rc_cnt); int* rc_cnt = (int*)p;
    cudaGetSymbolAddress(&p, g_rc_list);int* rc_list = (int*)p;
    cudaGetSymbolAddress(&p, g_xhi);    __nv_bfloat16* xhi = (__nv_bfloat16*)p;
    cudaGetSymbolAddress(&p, g_xlo);    __nv_bfloat16* xlo = (__nv_bfloat16*)p;
    cudaGetSymbolAddress(&p, g_hhi);    __nv_bfloat16* hhi = (__nv_bfloat16*)p;
    cudaGetSymbolAddress(&p, g_hlo);    __nv_bfloat16* hlo = (__nv_bfloat16*)p;
    cudaGetSymbolAddress(&p, g_shi);    __nv_bfloat16* shi = (__nv_bfloat16*)p;
    cudaGetSymbolAddress(&p, g_slo);    __nv_bfloat16* slo = (__nv_bfloat16*)p;
    cudaGetSymbolAddress(&p, g_ahi);    __nv_bfloat16* ahi = (__nv_bfloat16*)p;
    cudaGetSymbolAddress(&p, g_alo);    __nv_bfloat16* alo = (__nv_bfloat16*)p;
    cudaGetSymbolAddress(&p, g_hr0hi);  __nv_bfloat16* hr0hi = (__nv_bfloat16*)p;
    cudaGetSymbolAddress(&p, g_hr0lo);  __nv_bfloat16* hr0lo = (__nv_bfloat16*)p;
    cudaGetSymbolAddress(&p, g_hr1hi);  __nv_bfloat16* hr1hi = (__nv_bfloat16*)p;
    cudaGetSymbolAddress(&p, g_hr1lo);  __nv_bfloat16* hr1lo = (__nv_bfloat16*)p;
    cudaGetSymbolAddress(&p, g_wthi);   __nv_bfloat16* wthi = (__nv_bfloat16*)p;
    cudaGetSymbolAddress(&p, g_wtlo);   __nv_bfloat16* wtlo = (__nv_bfloat16*)p;

    cudaFuncSetAttribute(tgemm<TEPI_STORE>,   cudaFuncAttributeMaxDynamicSharedMemorySize, TG_SMEM);
    cudaFuncSetAttribute(tgemm<TEPI_GATE2>,   cudaFuncAttributeMaxDynamicSharedMemorySize, TG_SMEM);
    cudaFuncSetAttribute(tgemm<TEPI_ADDX>,    cudaFuncAttributeMaxDynamicSharedMemorySize, TG_SMEM);
    cudaFuncSetAttribute(tgemm<TEPI_SCATTER>, cudaFuncAttributeMaxDynamicSharedMemorySize, TG_SMEM);
    cudaFuncSetAttribute((const void*)btgemm<TEPI_SPLIT, TEPI_STORE, TEPI_HR, TEPI_HR>,
                         cudaFuncAttributeMaxDynamicSharedMemorySize, TG_SMEM);
    cudaFuncSetAttribute((const void*)btgemm<TEPI_GATE, TEPI_SCATTER, TEPI_SCATTER, TEPI_SCATTER>,
                         cudaFuncAttributeMaxDynamicSharedMemorySize, TG_SMEM);

    const size_t M1 = 1048576;
    const size_t KR0T = 0, KR1T = 4 * M1, VR0T = 8 * M1, VR1T = 12 * M1;
    const size_t W1T = 16 * M1, W2T = 17 * M1, W3T = 18 * M1;
    const size_t WRT = 19 * M1, WVT = 20 * M1, WOT = 21 * M1, WST = 22 * M1;

    dim3 blk(256), tb(32, 8);
    dim3 gC(NT / 128, CD / 128);

    // weight transpose+split (bf16 hi/lo)
    tsplit<<<dim3(HD / 32, CD / 32), tb>>>(Kr, CD, HD, wthi + KR0T, wtlo + KR0T);
    tsplit<<<dim3(HD / 32, CD / 32), tb>>>(Kr + (size_t)CD * HD, CD, HD, wthi + KR1T, wtlo + KR1T);
    tsplit<<<dim3(CD / 32, HD / 32), tb>>>(Vr, HD, CD, wthi + VR0T, wtlo + VR0T);
    tsplit<<<dim3(CD / 32, HD / 32), tb>>>(Vr + (size_t)HD * CD, HD, CD, wthi + VR1T, wtlo + VR1T);
    tsplit<<<dim3(CD / 32, CD / 32), tb>>>(W1, CD, CD, wthi + W1T, wtlo + W1T);
    tsplit<<<dim3(CD / 32, CD / 32), tb>>>(W2, CD, CD, wthi + W2T, wtlo + W2T);
    tsplit<<<dim3(CD / 32, CD / 32), tb>>>(W3, CD, CD, wthi + W3T, wtlo + W3T);
    tsplit<<<dim3(CD / 32, CD / 32), tb>>>(Wr, CD, CD, wthi + WRT, wtlo + WRT);
    tsplit<<<dim3(CD / 32, CD / 32), tb>>>(Wv, CD, CD, wthi + WVT, wtlo + WVT);
    tsplit<<<dim3(CD / 32, CD / 32), tb>>>(Wo, CD, CD, wthi + WOT, wtlo + WOT);
    tsplit<<<dim3(CD / 32, CD / 32), tb>>>(Ws, CD, CD, wthi + WST, wtlo + WST);

    zero_cnt_kernel<<<1, 32>>>(cnt, rc_cnt);
    ln_kernel<<<NT, 256>>>(x, ln1w, ln1b, xln, xhi, xlo);

    // attention path: bf16x3 HMMA
    tgemm<TEPI_STORE><<<gC, blk, TG_SMEM>>>(xhi, xlo, wthi + WRT, wtlo + WRT, NT, nullptr, CD,
                                            nullptr, nullptr, nullptr, nullptr, rb, nullptr, nullptr, CD);
    tgemm<TEPI_GATE2><<<gC, blk, TG_SMEM>>>(xhi, xlo, wthi + WVT, wtlo + WVT, NT, nullptr, CD,
                                            nullptr, rb, nullptr, nullptr, nullptr, ahi, alo, CD);
    tgemm<TEPI_ADDX><<<gC, blk, TG_SMEM>>>(ahi, alo, wthi + WOT, wtlo + WOT, NT, nullptr, CD,
                                           nullptr, x, nullptr, nullptr, out, nullptr, nullptr, CD);

    // routing (provisional, flags marginal tokens) -> exact recheck -> lists
    ln2_route_kernel<<<NT, 256>>>(out, ln2w, ln2b, confr, conft, wdiff, Waff, capital,
                                  hhi, hlo, conf3, win, rc_cnt, rc_list);
    recheck_kernel<<<RC_CAP, 256>>>(x, xln, Wr, Wv, Wo, ln2w, ln2b, confr, conft, wdiff,
                                    Waff, capital, rc_cnt, rc_list, win);
    build_lists<<<NT / 256, 256>>>(win, conf3, sclp, cnt, lst);

    // ---- batched expert set 1: {Ws(sparse), W1, K0, K1} ----
    GDesc dws = {xhi, xlo, wthi + WST, wtlo + WST, cnt + 2, lst + 2 * NT,
                 nullptr, nullptr, nullptr, nullptr, shi, slo, CD, CD, 8};
    GDesc dw1 = {hhi, hlo, wthi + W1T, wtlo + W1T, cnt + 2, lst + 2 * NT,
                 nullptr, nullptr, nullptr, ab, nullptr, nullptr, CD, CD, 8};
    GDesc dk0 = {hhi, hlo, wthi + KR0T, wtlo + KR0T, cnt + 0, lst + 0 * NT,
                 nullptr, nullptr, nullptr, nullptr, hr0hi, hr0lo, CD, HD, 32};
    GDesc dk1 = {hhi, hlo, wthi + KR1T, wtlo + KR1T, cnt + 1, lst + 1 * NT,
                 nullptr, nullptr, nullptr, nullptr, hr1hi, hr1lo, CD, HD, 32};
    btgemm<TEPI_SPLIT, TEPI_STORE, TEPI_HR, TEPI_HR>
        <<<dim3(NT / 128, 32, 4), blk, TG_SMEM>>>(dws, dw1, dk0, dk1);

    // ---- batched expert set 2: {W2(gate), V0, V1} ----
    GDesc dw2 = {shi, slo, wthi + W2T, wtlo + W2T, cnt + 2, nullptr,
                 ab, nullptr, nullptr, nullptr, ahi, alo, CD, CD, 8};
    GDesc dv0 = {hr0hi, hr0lo, wthi + VR0T, wtlo + VR0T, cnt + 0, nullptr,
                 nullptr, lst + 0 * NT, sclp, out, nullptr, nullptr, HD, CD, 8};
    GDesc dv1 = {hr1hi, hr1lo, wthi + VR1T, wtlo + VR1T, cnt + 1, nullptr,
                 nullptr, lst + 1 * NT, sclp, out, nullptr, nullptr, HD, CD, 8};
    btgemm<TEPI_GATE, TEPI_SCATTER, TEPI_SCATTER, TEPI_SCATTER>
        <<<dim3(NT / 128, 8, 3), blk, TG_SMEM>>>(dw2, dv0, dv1, dv1);

    // ---- set 3: W3 (scatter) ----
    tgemm<TEPI_SCATTER><<<gC, blk, TG_SMEM>>>(ahi, alo, wthi + W3T, wtlo + W3T, 0, cnt + 2, CD,
                                              nullptr, nullptr, lst + 2 * NT, sclp, out, nullptr, nullptr, CD);
}

// round 10
// speedup vs baseline: 1.9568x; 1.1865x over previous
#include <cuda_runtime.h>
#include <cuda_fp16.h>
#include <math.h>
#include <stdint.h>

#define NT 8192
#define CD 1024
#define HD 4096
#define RC_CAP 512

// ---------------- scratch ----------------------------------------------------
__device__ __align__(16) float g_xln[NT * CD];
__device__ __align__(16) float g_r[NT * CD];
__device__ __align__(16) float g_a[NT * CD];
__device__ float g_scale[NT];
__device__ int g_cnt[3];
__device__ int g_list[3 * NT];
__device__ int g_winner[NT];
__device__ float g_conf3[3 * NT];
__device__ int g_rc_cnt;
__device__ int g_rc_list[RC_CAP];
__device__ __align__(16) __half g_xh[NT * CD];    // xln fp16
__device__ __align__(16) __half g_hh[NT * CD];    // h fp16
__device__ __align__(16) __half g_sh[NT * CD];    // rwkv_state fp16 (compacted)
__device__ __align__(16) __half g_ah[NT * CD];    // gated attn / W2 out fp16
__device__ __align__(16) __half g_hr0[NT * HD];
__device__ __align__(16) __half g_hr1[NT * HD];
#define WSZ (23u * 1048576u)
__device__ __align__(16) __half g_wthi[WSZ];
__device__ __align__(16) __half g_wtlo[WSZ];

// ---------------- helpers ----------------------------------------------------
__device__ __forceinline__ uint32_t smem_u32(const void* p) {
    uint32_t a;
    asm("{ .reg .u64 t; cvta.to.shared.u64 t, %1; cvt.u32.u64 %0, t; }" : "=r"(a) : "l"(p));
    return a;
}
__device__ __forceinline__ void ldsm4(uint32_t* r, uint32_t a) {
    asm volatile("ldmatrix.sync.aligned.m8n8.x4.shared.b16 {%0,%1,%2,%3}, [%4];"
                 : "=r"(r[0]), "=r"(r[1]), "=r"(r[2]), "=r"(r[3]) : "r"(a));
}
__device__ __forceinline__ void mma16816(float* d, const uint32_t* a, const uint32_t* b) {
    asm volatile("mma.sync.aligned.m16n8k16.row.col.f32.f16.f16.f32 "
                 "{%0,%1,%2,%3}, {%4,%5,%6,%7}, {%8,%9}, {%0,%1,%2,%3};"
                 : "+f"(d[0]), "+f"(d[1]), "+f"(d[2]), "+f"(d[3])
                 : "r"(a[0]), "r"(a[1]), "r"(a[2]), "r"(a[3]), "r"(b[0]), "r"(b[1]));
}
__device__ __forceinline__ void cpa16(uint32_t s, const void* g) {
    asm volatile("cp.async.ca.shared.global [%0], [%1], 16;" :: "r"(s), "l"(g));
}
__device__ __forceinline__ float sigf(float x) { return 1.0f / (1.0f + expf(-x)); }
__device__ __forceinline__ unsigned packh(__half a, __half b) {
    return (unsigned)__half_as_ushort(a) | ((unsigned)__half_as_ushort(b) << 16);
}

// ================= HMMA tensor GEMM core (fp16 2-term emulation) ==============
// D = A_fp16 @ (Bhi + Blo)^T ; A single fp16, B split hi/lo fp16.
enum { TEPI_HR = 0, TEPI_STORE = 1, TEPI_GATE = 2, TEPI_SCATTER = 3,
       TEPI_CVT = 4, TEPI_GATE2 = 5, TEPI_ADDX = 6 };
// per buffer: A 16KB @0, BH 16KB @16384, BL 16KB @32768; 2 buffers
#define TG_SMEM (2 * 49152 + 1024)

struct GDesc {
    const __half *Ah, *Bhi, *Blo;
    const int* Mptr;
    const int* gidx;
    const float* aux;
    const int* sidx;
    const float* scl;
    float* outF;
    __half* outH;
    int K, ldo, Nb;
};

__device__ __forceinline__ void tg_main(
    const __half* __restrict__ Ah,
    const __half* __restrict__ Bhi, const __half* __restrict__ Blo,
    int M, int bm, int bn, int K, const int* __restrict__ gidx,
    uint32_t smb, float acc[4][4][4]) {
    int tid = threadIdx.x, lane = tid & 31, warp = tid >> 5;
    int wm = warp & 1, wn = warp >> 1;
    int quad = lane >> 3, r8 = lane & 7;

    uint32_t baseA[4], maskA[4];
    uint32_t kqA = (uint32_t)(quad >> 1) * 16;
#pragma unroll
    for (int mt = 0; mt < 4; mt++) {
        int rowA = wm * 64 + mt * 16 + (quad & 1) * 8 + r8;
        baseA[mt] = (uint32_t)rowA * 128;
        maskA[mt] = (uint32_t)(rowA & 7) << 4;
    }
    uint32_t baseB[2], maskB[2];
    uint32_t kqB = (uint32_t)(quad & 1) * 16;
#pragma unroll
    for (int n2 = 0; n2 < 2; n2++) {
        int rowB = wn * 32 + n2 * 16 + (quad >> 1) * 8 + r8;
        baseB[n2] = 16384u + (uint32_t)rowB * 128;
        maskB[n2] = (uint32_t)(rowB & 7) << 4;
    }

    // staging: 64 k-elems (128B) per row per chunk; 2 threads per row, 64B each
    int row = tid >> 1, h = tid & 1;
    int ra = bm + row; if (ra > M - 1) ra = M - 1;
    if (gidx) ra = gidx[ra];
    const __half* pA  = Ah  + (size_t)ra * K + h * 32;
    const __half* pBh = Bhi + (size_t)(bn + row) * K + h * 32;
    const __half* pBl = Blo + (size_t)(bn + row) * K + h * 32;
    uint32_t mk = (uint32_t)(row & 7) << 4;
    uint32_t st[4];
#pragma unroll
    for (int i = 0; i < 4; i++)
        st[i] = (uint32_t)row * 128 + (((uint32_t)h * 64 + i * 16) ^ mk);

    auto stage = [&](int t, int buf) {
        int kc = t * 64;
        uint32_t ab = smb + (uint32_t)buf * 49152u;
#pragma unroll
        for (int i = 0; i < 4; i++) {
            cpa16(ab + st[i],          pA  + kc + i * 8);
            cpa16(ab + 16384u + st[i], pBh + kc + i * 8);
            cpa16(ab + 32768u + st[i], pBl + kc + i * 8);
        }
        asm volatile("cp.async.commit_group;" ::: "memory");
    };

#pragma unroll
    for (int i = 0; i < 4; i++)
#pragma unroll
        for (int j = 0; j < 4; j++)
#pragma unroll
            for (int q = 0; q < 4; q++) acc[i][j][q] = 0.f;

    int nch = K >> 6;   // K = 1024 -> 16, 4096 -> 64
    stage(0, 0);
    stage(1, 1);
    for (int t = 0; t < nch; t++) {
        if (t + 1 < nch) asm volatile("cp.async.wait_group 1;" ::: "memory");
        else             asm volatile("cp.async.wait_group 0;" ::: "memory");
        __syncthreads();
        uint32_t bufs = smb + (uint32_t)(t & 1) * 49152u;
#pragma unroll
        for (int ks = 0; ks < 4; ks++) {
            uint32_t cb = (uint32_t)ks * 32;
            uint32_t bh[4][2], bl[4][2];
#pragma unroll
            for (int n2 = 0; n2 < 2; n2++) {
                uint32_t r[4];
                ldsm4(r, bufs + baseB[n2] + ((kqB + cb) ^ maskB[n2]));
                bh[2 * n2][0] = r[0]; bh[2 * n2][1] = r[1];
                bh[2 * n2 + 1][0] = r[2]; bh[2 * n2 + 1][1] = r[3];
                ldsm4(r, bufs + baseB[n2] + 16384u + ((kqB + cb) ^ maskB[n2]));
                bl[2 * n2][0] = r[0]; bl[2 * n2][1] = r[1];
                bl[2 * n2 + 1][0] = r[2]; bl[2 * n2 + 1][1] = r[3];
            }
#pragma unroll
            for (int mt = 0; mt < 4; mt++) {
                uint32_t a[4];
                ldsm4(a, bufs + baseA[mt] + ((kqA + cb) ^ maskA[mt]));
#pragma unroll
                for (int nt = 0; nt < 4; nt++) {
                    mma16816(acc[mt][nt], a, bh[nt]);
                    mma16816(acc[mt][nt], a, bl[nt]);
                }
            }
        }
        __syncthreads();
        if (t + 2 < nch) stage(t + 2, t & 1);
    }
}

template <int EPI>
__device__ __forceinline__ void emit2(int grow, int gcol, float v0, float v1, int M,
                                      const float* __restrict__ aux,
                                      const int* __restrict__ sidx, const float* __restrict__ scl,
                                      float* __restrict__ outF, __half* __restrict__ outH, int ldo) {
    if (grow >= M) return;
    if (EPI == TEPI_STORE) {
        *(float2*)(outF + (size_t)grow * ldo + gcol) = make_float2(v0, v1);
    } else if (EPI == TEPI_ADDX) {
        float2 a = *(const float2*)(aux + (size_t)grow * CD + gcol);
        *(float2*)(outF + (size_t)grow * ldo + gcol) = make_float2(v0 + a.x, v1 + a.y);
    } else if (EPI == TEPI_SCATTER) {
        int orow = sidx[grow];
        float sc = scl[orow];
        float2* p = (float2*)(outF + (size_t)orow * ldo + gcol);
        float2 c = *p;
        c.x += v0 * sc; c.y += v1 * sc;
        *p = c;
    } else {
        if (EPI == TEPI_HR) {
            v0 = fmaxf(v0, 0.f); v0 *= v0;
            v1 = fmaxf(v1, 0.f); v1 *= v1;
        } else if (EPI == TEPI_GATE) {
            float2 a = *(const float2*)(aux + (size_t)grow * CD + gcol);
            v0 = a.x * sigf(v0); v1 = a.y * sigf(v1);
        } else if (EPI == TEPI_GATE2) {
            float2 a = *(const float2*)(aux + (size_t)grow * CD + gcol);
            v0 = sigf(a.x) * v0; v1 = sigf(a.y) * v1;
        }
        *(unsigned*)(outH + (size_t)grow * ldo + gcol) =
            packh(__float2half_rn(v0), __float2half_rn(v1));
    }
}

template <int EPI>
__device__ __forceinline__ void tg_epi(int M, int bm, int bn, float acc[4][4][4],
                                       const float* aux, const int* sidx, const float* scl,
                                       float* outF, __half* outH, int ldo) {
    int lane = threadIdx.x & 31, warp = threadIdx.x >> 5;
    int wm = warp & 1, wn = warp >> 1;
    int erow = lane >> 2, ecol = (lane & 3) * 2;
#pragma unroll
    for (int mt = 0; mt < 4; mt++) {
        int gr = bm + wm * 64 + mt * 16 + erow;
#pragma unroll
        for (int nt = 0; nt < 4; nt++) {
            int gc = bn + wn * 32 + nt * 8 + ecol;
            emit2<EPI>(gr,     gc, acc[mt][nt][0], acc[mt][nt][1], M, aux, sidx, scl, outF, outH, ldo);
            emit2<EPI>(gr + 8, gc, acc[mt][nt][2], acc[mt][nt][3], M, aux, sidx, scl, outF, outH, ldo);
        }
    }
}

template <int EPI>
__global__ void __launch_bounds__(256, 2)
tgemm(const __half* __restrict__ Ah,
      const __half* __restrict__ Bhi, const __half* __restrict__ Blo,
      int Mstat, const int* __restrict__ Mptr, int K,
      const int* __restrict__ gidx, const float* __restrict__ aux,
      const int* __restrict__ sidx, const float* __restrict__ scl,
      float* __restrict__ outF, __half* __restrict__ outH, int ldo) {
    int M = Mptr ? *Mptr : Mstat;
    int bm = blockIdx.x * 128;
    if (bm >= M) return;
    int bn = blockIdx.y * 128;
    extern __shared__ char smraw[];
    uint32_t smb0 = smem_u32(smraw);
    uint32_t smb = (smb0 + 1023u) & ~1023u;
    float acc[4][4][4];
    tg_main(Ah, Bhi, Blo, M, bm, bn, K, gidx, smb, acc);
    tg_epi<EPI>(M, bm, bn, acc, aux, sidx, scl, outF, outH, ldo);
}

template <int E0, int E1, int E2, int E3>
__global__ void __launch_bounds__(256, 2)
btgemm(GDesc g0, GDesc g1, GDesc g2, GDesc g3) {
    int z = blockIdx.z;
    GDesc g = (z == 0) ? g0 : (z == 1) ? g1 : (z == 2) ? g2 : g3;
    if ((int)blockIdx.y >= g.Nb) return;
    int M = *g.Mptr;
    int bm = blockIdx.x * 128;
    if (bm >= M) return;
    int bn = blockIdx.y * 128;
    extern __shared__ char smraw[];
    uint32_t smb0 = smem_u32(smraw);
    uint32_t smb = (smb0 + 1023u) & ~1023u;
    float acc[4][4][4];
    tg_main(g.Ah, g.Bhi, g.Blo, M, bm, bn, g.K, g.gidx, smb, acc);
    if (z == 0)      tg_epi<E0>(M, bm, bn, acc, g.aux, g.sidx, g.scl, g.outF, g.outH, g.ldo);
    else if (z == 1) tg_epi<E1>(M, bm, bn, acc, g.aux, g.sidx, g.scl, g.outF, g.outH, g.ldo);
    else if (z == 2) tg_epi<E2>(M, bm, bn, acc, g.aux, g.sidx, g.scl, g.outF, g.outH, g.ldo);
    else             tg_epi<E3>(M, bm, bn, acc, g.aux, g.sidx, g.scl, g.outF, g.outH, g.ldo);
}

// ======== transpose + split: W[K,N] -> WT_hi/lo[N,K] (fp16) ===================
__global__ void tsplit(const float* __restrict__ W, int K, int N,
                       __half* __restrict__ hi, __half* __restrict__ lo) {
    __shared__ float t[32][33];
    int n0 = blockIdx.x * 32, k0 = blockIdx.y * 32;
    int tx = threadIdx.x, ty = threadIdx.y;
#pragma unroll
    for (int j = 0; j < 4; j++)
        t[ty + 8 * j][tx] = W[(size_t)(k0 + ty + 8 * j) * N + n0 + tx];
    __syncthreads();
#pragma unroll
    for (int j = 0; j < 4; j++) {
        float v = t[tx][ty + 8 * j];
        size_t o = (size_t)(n0 + ty + 8 * j) * K + k0 + tx;
        __half h = __float2half_rn(v);
        hi[o] = h;
        lo[o] = __float2half_rn(v - __half2float(h));
    }
}

// ================= LN / routing ===============================================
__device__ __forceinline__ float blockReduceSum(float v) {
    __shared__ float sh[8];
#pragma unroll
    for (int o = 16; o > 0; o >>= 1) v += __shfl_down_sync(0xffffffffu, v, o);
    int w = threadIdx.x >> 5, l = threadIdx.x & 31;
    if (l == 0) sh[w] = v;
    __syncthreads();
    if (threadIdx.x < 8) {
        float r = sh[threadIdx.x];
#pragma unroll
        for (int o = 4; o > 0; o >>= 1) r += __shfl_down_sync(0x000000ffu, r, o);
        if (threadIdx.x == 0) sh[0] = r;
    }
    __syncthreads();
    float res = sh[0];
    __syncthreads();
    return res;
}

__global__ void ln_kernel(const float* __restrict__ x, const float* __restrict__ w,
                          const float* __restrict__ b, float* __restrict__ out,
                          __half* __restrict__ oh) {
    int row = blockIdx.x, tid = threadIdx.x;
    float4 v = ((const float4*)(x + (size_t)row * CD))[tid];
    float s = blockReduceSum(v.x + v.y + v.z + v.w);
    float mean = s * (1.0f / CD);
    float dx = v.x - mean, dy = v.y - mean, dz = v.z - mean, dw = v.w - mean;
    float s2 = blockReduceSum(dx * dx + dy * dy + dz * dz + dw * dw);
    float rstd = 1.0f / sqrtf(s2 * (1.0f / CD) + 1e-5f);
    float4 wv = ((const float4*)w)[tid], bv = ((const float4*)b)[tid];
    float4 o = make_float4(dx * rstd * wv.x + bv.x, dy * rstd * wv.y + bv.y,
                           dz * rstd * wv.z + bv.z, dw * rstd * wv.w + bv.w);
    ((float4*)(out + (size_t)row * CD))[tid] = o;
    ((uint2*)(oh + (size_t)row * CD))[tid] =
        make_uint2(packh(__float2half_rn(o.x), __float2half_rn(o.y)),
                   packh(__float2half_rn(o.z), __float2half_rn(o.w)));
}

__global__ void ln2_route_kernel(const float* __restrict__ x2, const float* __restrict__ w,
                                 const float* __restrict__ b, const float* __restrict__ conf_rwkv,
                                 const float* __restrict__ conf_trans, const float* __restrict__ w_diff,
                                 const float* __restrict__ W_aff, const float* __restrict__ capital,
                                 __half* __restrict__ hh,
                                 float* __restrict__ conf3, int* __restrict__ winner,
                                 int* __restrict__ rc_cnt, int* __restrict__ rc_list) {
    int row = blockIdx.x, tid = threadIdx.x;
    float4 v = ((const float4*)(x2 + (size_t)row * CD))[tid];
    float s = blockReduceSum(v.x + v.y + v.z + v.w);
    float mean = s * (1.0f / CD);
    float dx = v.x - mean, dy = v.y - mean, dz = v.z - mean, dw = v.w - mean;
    float s2 = blockReduceSum(dx * dx + dy * dy + dz * dz + dw * dw);
    float rstd = 1.0f / sqrtf(s2 * (1.0f / CD) + 1e-5f);
    float4 wv = ((const float4*)w)[tid], bv = ((const float4*)b)[tid];
    float4 o = make_float4(dx * rstd * wv.x + bv.x, dy * rstd * wv.y + bv.y,
                           dz * rstd * wv.z + bv.z, dw * rstd * wv.w + bv.w);
    ((uint2*)(hh + (size_t)row * CD))[tid] =
        make_uint2(packh(__float2half_rn(o.x), __float2half_rn(o.y)),
                   packh(__float2half_rn(o.z), __float2half_rn(o.w)));

    float p[7];
    float4 c0 = ((const float4*)conf_rwkv)[tid];
    float4 c1 = ((const float4*)(conf_rwkv + CD))[tid];
    float4 ct = ((const float4*)conf_trans)[tid];
    float4 wd = ((const float4*)w_diff)[tid];
    p[0] = o.x * c0.x + o.y * c0.y + o.z * c0.z + o.w * c0.w;
    p[1] = o.x * c1.x + o.y * c1.y + o.z * c1.z + o.w * c1.w;
    p[2] = o.x * ct.x + o.y * ct.y + o.z * ct.z + o.w * ct.w;
    p[3] = o.x * wd.x + o.y * wd.y + o.z * wd.z + o.w * wd.w;
    const float* wa = W_aff + (size_t)tid * 12;
#pragma unroll
    for (int e = 0; e < 3; e++)
        p[4 + e] = o.x * wa[e] + o.y * wa[3 + e] + o.z * wa[6 + e] + o.w * wa[9 + e];

    __shared__ float red[7][8];
    int wid = tid >> 5, lid = tid & 31;
#pragma unroll
    for (int q = 0; q < 7; q++) {
        float vv = p[q];
#pragma unroll
        for (int o2 = 16; o2 > 0; o2 >>= 1) vv += __shfl_down_sync(0xffffffffu, vv, o2);
        if (lid == 0) red[q][wid] = vv;
    }
    __syncthreads();
    if (tid == 0) {
        float d[7];
#pragma unroll
        for (int q = 0; q < 7; q++) {
            float t = 0.f;
#pragma unroll
            for (int k = 0; k < 8; k++) t += red[q][k];
            d[q] = t;
        }
        float cf[3] = {sigf(d[0]), sigf(d[1]), sigf(d[2])};
        float diff = sigf(d[3]);
        float bids[3];
#pragma unroll
        for (int e = 0; e < 3; e++) {
            bids[e] = cf[e] * capital[e] * diff + d[4 + e];
            conf3[row * 3 + e] = cf[e];
        }
        int wdx = 0; float best = bids[0];
        if (bids[1] > best) { best = bids[1]; wdx = 1; }
        if (bids[2] > best) { best = bids[2]; wdx = 2; }
        float second = -1e30f;
#pragma unroll
        for (int e = 0; e < 3; e++)
            if (e != wdx && bids[e] > second) second = bids[e];
        winner[row] = wdx;
        if (best - second < 1e-3f) {
            int pos = atomicAdd(rc_cnt, 1);
            if (pos < RC_CAP) rc_list[pos] = row;
        }
    }
}

// exact fp32 recompute of routing for marginal tokens (coalesced row-major GEMV)
__global__ void recheck_kernel(const float* __restrict__ x, const float* __restrict__ xln,
                               const float* __restrict__ Wr, const float* __restrict__ Wv,
                               const float* __restrict__ Wo,
                               const float* __restrict__ ln2w, const float* __restrict__ ln2b,
                               const float* __restrict__ conf_rwkv, const float* __restrict__ conf_trans,
                               const float* __restrict__ w_diff, const float* __restrict__ W_aff,
                               const float* __restrict__ capital,
                               const int* __restrict__ rc_cnt, const int* __restrict__ rc_list,
                               int* __restrict__ winner) {
    int n = *rc_cnt; if (n > RC_CAP) n = RC_CAP;
    int bi = blockIdx.x;
    if (bi >= n) return;
    int row = rc_list[bi];
    int tid = threadIdx.x;
    __shared__ float sx[CD];
    __shared__ float su[CD];
    for (int c = tid; c < CD; c += 256) sx[c] = xln[(size_t)row * CD + c];
    __syncthreads();

    float racc[4] = {0, 0, 0, 0}, vacc[4] = {0, 0, 0, 0};
    for (int k = 0; k < CD; k++) {
        float xv = sx[k];
        const float* wr = Wr + (size_t)k * CD + tid;
        const float* wv = Wv + (size_t)k * CD + tid;
#pragma unroll
        for (int j = 0; j < 4; j++) {
            racc[j] += xv * wr[j * 256];
            vacc[j] += xv * wv[j * 256];
        }
    }
#pragma unroll
    for (int j = 0; j < 4; j++)
        su[tid + j * 256] = sigf(racc[j]) * vacc[j];
    __syncthreads();

    float oacc[4] = {0, 0, 0, 0};
    for (int k = 0; k < CD; k++) {
        float uv = su[k];
        const float* wo = Wo + (size_t)k * CD + tid;
#pragma unroll
        for (int j = 0; j < 4; j++) oacc[j] += uv * wo[j * 256];
    }
    __syncthreads();
#pragma unroll
    for (int j = 0; j < 4; j++)
        sx[tid + j * 256] = oacc[j] + x[(size_t)row * CD + tid + j * 256];
    __syncthreads();

    float ps = 0.f;
    for (int c = tid; c < CD; c += 256) ps += sx[c];
    float mean = blockReduceSum(ps) * (1.0f / CD);
    float ps2 = 0.f;
    for (int c = tid; c < CD; c += 256) { float d = sx[c] - mean; ps2 += d * d; }
    float rstd = 1.0f / sqrtf(blockReduceSum(ps2) * (1.0f / CD) + 1e-5f);

    float p[7] = {0, 0, 0, 0, 0, 0, 0};
    for (int c = tid; c < CD; c += 256) {
        float hc = (sx[c] - mean) * rstd * ln2w[c] + ln2b[c];
        p[0] += hc * conf_rwkv[c];
        p[1] += hc * conf_rwkv[CD + c];
        p[2] += hc * conf_trans[c];
        p[3] += hc * w_diff[c];
        p[4] += hc * W_aff[c * 3 + 0];
        p[5] += hc * W_aff[c * 3 + 1];
        p[6] += hc * W_aff[c * 3 + 2];
    }
    __shared__ float red[7][8];
    int wid = tid >> 5, lid = tid & 31;
#pragma unroll
    for (int q = 0; q < 7; q++) {
        float vv = p[q];
#pragma unroll
        for (int o2 = 16; o2 > 0; o2 >>= 1) vv += __shfl_down_sync(0xffffffffu, vv, o2);
        if (lid == 0) red[q][wid] = vv;
    }
    __syncthreads();
    if (tid == 0) {
        float d[7];
#pragma unroll
        for (int q = 0; q < 7; q++) {
            float t = 0.f;
#pragma unroll
            for (int k = 0; k < 8; k++) t += red[q][k];
            d[q] = t;
        }
        float cf[3] = {sigf(d[0]), sigf(d[1]), sigf(d[2])};
        float diff = sigf(d[3]);
        int wdx = 0; float best = -1e30f;
#pragma unroll
        for (int e = 0; e < 3; e++) {
            float bid = cf[e] * capital[e] * diff + d[4 + e];
            if (bid > best) { best = bid; wdx = e; }
        }
        winner[row] = wdx;
    }
}

__global__ void build_lists(const int* __restrict__ winner, const float* __restrict__ conf3,
                            float* __restrict__ scale_out, int* __restrict__ cnt, int* __restrict__ lst) {
    int i = blockIdx.x * 256 + threadIdx.x;
    if (i >= NT) return;
    int w = winner[i];
    float wc = conf3[i * 3 + w];
    scale_out[i] = wc / (wc + 1e-6f);
    int pos = atomicAdd(&cnt[w], 1);
    lst[w * NT + pos] = i;
}

__global__ void zero_cnt_kernel(int* c, int* rc) {
    if (threadIdx.x < 3) c[threadIdx.x] = 0;
    if (threadIdx.x == 0) *rc = 0;
}

// ================= launch =====================================================
extern "C" void kernel_launch(void* const* d_in, const int* in_sizes, int n_in,
                              void* d_out, int out_size) {
    const float* x = (const float*)d_in[0];
    const float* capital = (const float*)d_in[2];
    const float* ln1w = (const float*)d_in[3], *ln1b = (const float*)d_in[4];
    const float* ln2w = (const float*)d_in[5], *ln2b = (const float*)d_in[6];
    const float* Wr = (const float*)d_in[7], *Wv = (const float*)d_in[8];
    const float* Wo = (const float*)d_in[9], *Ws = (const float*)d_in[10];
    const float* Kr = (const float*)d_in[11], *Vr = (const float*)d_in[12];
    const float* confr = (const float*)d_in[13];
    const float* W1 = (const float*)d_in[14], *W2 = (const float*)d_in[15];
    const float* W3 = (const float*)d_in[16];
    const float* conft = (const float*)d_in[17], *wdiff = (const float*)d_in[18];
    const float* Waff = (const float*)d_in[19];
    float* out = (float*)d_out;

    void* p;
    cudaGetSymbolAddress(&p, g_xln);    float* xln = (float*)p;
    cudaGetSymbolAddress(&p, g_r);      float* rb = (float*)p;
    cudaGetSymbolAddress(&p, g_a);      float* ab = (float*)p;
    cudaGetSymbolAddress(&p, g_scale);  float* sclp = (float*)p;
    cudaGetSymbolAddress(&p, g_cnt);    int* cnt = (int*)p;
    cudaGetSymbolAddress(&p, g_list);   int* lst = (int*)p;
    cudaGetSymbolAddress(&p, g_winner); int* win = (int*)p;
    cudaGetSymbolAddress(&p, g_conf3);  float* conf3 = (float*)p;
    cudaGetSymbolAddress(&p, g_rc_cnt); int* rc_cnt = (int*)p;
    cudaGetSymbolAddress(&p, g_rc_list);int* rc_list = (int*)p;
    cudaGetSymbolAddress(&p, g_xh);     __half* xh = (__half*)p;
    cudaGetSymbolAddress(&p, g_hh);     __half* hh = (__half*)p;
    cudaGetSymbolAddress(&p, g_sh);     __half* sh = (__half*)p;
    cudaGetSymbolAddress(&p, g_ah);     __half* ah = (__half*)p;
    cudaGetSymbolAddress(&p, g_hr0);    __half* hr0 = (__half*)p;
    cudaGetSymbolAddress(&p, g_hr1);    __half* hr1 = (__half*)p;
    cudaGetSymbolAddress(&p, g_wthi);   __half* wthi = (__half*)p;
    cudaGetSymbolAddress(&p, g_wtlo);   __half* wtlo = (__half*)p;

    cudaFuncSetAttribute(tgemm<TEPI_STORE>,   cudaFuncAttributeMaxDynamicSharedMemorySize, TG_SMEM);
    cudaFuncSetAttribute(tgemm<TEPI_GATE2>,   cudaFuncAttributeMaxDynamicSharedMemorySize, TG_SMEM);
    cudaFuncSetAttribute(tgemm<TEPI_ADDX>,    cudaFuncAttributeMaxDynamicSharedMemorySize, TG_SMEM);
    cudaFuncSetAttribute(tgemm<TEPI_SCATTER>, cudaFuncAttributeMaxDynamicSharedMemorySize, TG_SMEM);
    cudaFuncSetAttribute((const void*)btgemm<TEPI_CVT, TEPI_STORE, TEPI_HR, TEPI_HR>,
                         cudaFuncAttributeMaxDynamicSharedMemorySize, TG_SMEM);
    cudaFuncSetAttribute((const void*)btgemm<TEPI_GATE, TEPI_SCATTER, TEPI_SCATTER, TEPI_SCATTER>,
                         cudaFuncAttributeMaxDynamicSharedMemorySize, TG_SMEM);

    const size_t M1 = 1048576;
    const size_t KR0T = 0, KR1T = 4 * M1, VR0T = 8 * M1, VR1T = 12 * M1;
    const size_t W1T = 16 * M1, W2T = 17 * M1, W3T = 18 * M1;
    const size_t WRT = 19 * M1, WVT = 20 * M1, WOT = 21 * M1, WST = 22 * M1;

    dim3 blk(256), tb(32, 8);
    dim3 gC(NT / 128, CD / 128);

    // weight transpose+split (fp16 hi/lo)
    tsplit<<<dim3(HD / 32, CD / 32), tb>>>(Kr, CD, HD, wthi + KR0T, wtlo + KR0T);
    tsplit<<<dim3(HD / 32, CD / 32), tb>>>(Kr + (size_t)CD * HD, CD, HD, wthi + KR1T, wtlo + KR1T);
    tsplit<<<dim3(CD / 32, HD / 32), tb>>>(Vr, HD, CD, wthi + VR0T, wtlo + VR0T);
    tsplit<<<dim3(CD / 32, HD / 32), tb>>>(Vr + (size_t)HD * CD, HD, CD, wthi + VR1T, wtlo + VR1T);
    tsplit<<<dim3(CD / 32, CD / 32), tb>>>(W1, CD, CD, wthi + W1T, wtlo + W1T);
    tsplit<<<dim3(CD / 32, CD / 32), tb>>>(W2, CD, CD, wthi + W2T, wtlo + W2T);
    tsplit<<<dim3(CD / 32, CD / 32), tb>>>(W3, CD, CD, wthi + W3T, wtlo + W3T);
    tsplit<<<dim3(CD / 32, CD / 32), tb>>>(Wr, CD, CD, wthi + WRT, wtlo + WRT);
    tsplit<<<dim3(CD / 32, CD / 32), tb>>>(Wv, CD, CD, wthi + WVT, wtlo + WVT);
    tsplit<<<dim3(CD / 32, CD / 32), tb>>>(Wo, CD, CD, wthi + WOT, wtlo + WOT);
    tsplit<<<dim3(CD / 32, CD / 32), tb>>>(Ws, CD, CD, wthi + WST, wtlo + WST);

    zero_cnt_kernel<<<1, 32>>>(cnt, rc_cnt);
    ln_kernel<<<NT, 256>>>(x, ln1w, ln1b, xln, xh);

    // attention path: fp16 2-term HMMA
    tgemm<TEPI_STORE><<<gC, blk, TG_SMEM>>>(xh, wthi + WRT, wtlo + WRT, NT, nullptr, CD,
                                            nullptr, nullptr, nullptr, nullptr, rb, nullptr, CD);
    tgemm<TEPI_GATE2><<<gC, blk, TG_SMEM>>>(xh, wthi + WVT, wtlo + WVT, NT, nullptr, CD,
                                            nullptr, rb, nullptr, nullptr, nullptr, ah, CD);
    tgemm<TEPI_ADDX><<<gC, blk, TG_SMEM>>>(ah, wthi + WOT, wtlo + WOT, NT, nullptr, CD,
                                           nullptr, x, nullptr, nullptr, out, nullptr, CD);

    // routing (provisional, flags marginal tokens) -> exact recheck -> lists
    ln2_route_kernel<<<NT, 256>>>(out, ln2w, ln2b, confr, conft, wdiff, Waff, capital,
                                  hh, conf3, win, rc_cnt, rc_list);
    recheck_kernel<<<RC_CAP, 256>>>(x, xln, Wr, Wv, Wo, ln2w, ln2b, confr, conft, wdiff,
                                    Waff, capital, rc_cnt, rc_list, win);
    build_lists<<<NT / 256, 256>>>(win, conf3, sclp, cnt, lst);

    // ---- batched expert set 1: {Ws(sparse,cvt), W1, K0, K1} ----
    GDesc dws = {xh, wthi + WST, wtlo + WST, cnt + 2, lst + 2 * NT,
                 nullptr, nullptr, nullptr, nullptr, sh, CD, CD, 8};
    GDesc dw1 = {hh, wthi + W1T, wtlo + W1T, cnt + 2, lst + 2 * NT,
                 nullptr, nullptr, nullptr, ab, nullptr, CD, CD, 8};
    GDesc dk0 = {hh, wthi + KR0T, wtlo + KR0T, cnt + 0, lst + 0 * NT,
                 nullptr, nullptr, nullptr, nullptr, hr0, CD, HD, 32};
    GDesc dk1 = {hh, wthi + KR1T, wtlo + KR1T, cnt + 1, lst + 1 * NT,
                 nullptr, nullptr, nullptr, nullptr, hr1, CD, HD, 32};
    btgemm<TEPI_CVT, TEPI_STORE, TEPI_HR, TEPI_HR>
        <<<dim3(NT / 128, 32, 4), blk, TG_SMEM>>>(dws, dw1, dk0, dk1);

    // ---- batched expert set 2: {W2(gate), V0, V1} ----
    GDesc dw2 = {sh, wthi + W2T, wtlo + W2T, cnt + 2, nullptr,
                 ab, nullptr, nullptr, nullptr, ah, CD, CD, 8};
    GDesc dv0 = {hr0, wthi + VR0T, wtlo + VR0T, cnt + 0, nullptr,
                 nullptr, lst + 0 * NT, sclp, out, nullptr, HD, CD, 8};
    GDesc dv1 = {hr1, wthi + VR1T, wtlo + VR1T, cnt + 1, nullptr,
                 nullptr, lst + 1 * NT, sclp, out, nullptr, HD, CD, 8};
    btgemm<TEPI_GATE, TEPI_SCATTER, TEPI_SCATTER, TEPI_SCATTER>
        <<<dim3(NT / 128, 8, 3), blk, TG_SMEM>>>(dw2, dv0, dv1, dv1);

    // ---- set 3: W3 (scatter) ----
    tgemm<TEPI_SCATTER><<<gC, blk, TG_SMEM>>>(ah, wthi + W3T, wtlo + W3T, 0, cnt + 2, CD,
                                              nullptr, nullptr, lst + 2 * NT, sclp, out, nullptr, CD);
}

// round 11
// speedup vs baseline: 2.7969x; 1.4293x over previous
#include <cuda_runtime.h>
#include <cuda_fp16.h>
#include <math.h>
#include <stdint.h>

#define NT 8192
#define CD 1024
#define HD 4096
#define RC_CAP 512

// ---------------- scratch ----------------------------------------------------
__device__ __align__(16) float g_xln[NT * CD];
__device__ __align__(16) float g_r[NT * CD];
__device__ __align__(16) float g_a[NT * CD];
__device__ float g_scale[NT];
__device__ int g_cnt[3];
__device__ int g_list[3 * NT];
__device__ int g_winner[NT];
__device__ float g_conf3[3 * NT];
__device__ int g_rc_cnt;
__device__ int g_rc_list[RC_CAP];
__device__ __align__(16) __half g_xh[NT * CD];    // xln fp16
__device__ __align__(16) __half g_hh[NT * CD];    // h fp16
__device__ __align__(16) __half g_sh[NT * CD];    // rwkv_state fp16 (compacted)
__device__ __align__(16) __half g_ah[NT * CD];    // gated attn / W2 out fp16
__device__ __align__(16) __half g_hr0[NT * HD];
__device__ __align__(16) __half g_hr1[NT * HD];
#define WSZ (23u * 1048576u)
__device__ __align__(16) __half g_wt[WSZ];

// ---------------- helpers ----------------------------------------------------
__device__ __forceinline__ uint32_t smem_u32(const void* p) {
    uint32_t a;
    asm("{ .reg .u64 t; cvta.to.shared.u64 t, %1; cvt.u32.u64 %0, t; }" : "=r"(a) : "l"(p));
    return a;
}
__device__ __forceinline__ void ldsm4(uint32_t* r, uint32_t a) {
    asm volatile("ldmatrix.sync.aligned.m8n8.x4.shared.b16 {%0,%1,%2,%3}, [%4];"
                 : "=r"(r[0]), "=r"(r[1]), "=r"(r[2]), "=r"(r[3]) : "r"(a));
}
__device__ __forceinline__ void mma16816(float* d, const uint32_t* a, const uint32_t* b) {
    asm volatile("mma.sync.aligned.m16n8k16.row.col.f32.f16.f16.f32 "
                 "{%0,%1,%2,%3}, {%4,%5,%6,%7}, {%8,%9}, {%0,%1,%2,%3};"
                 : "+f"(d[0]), "+f"(d[1]), "+f"(d[2]), "+f"(d[3])
                 : "r"(a[0]), "r"(a[1]), "r"(a[2]), "r"(a[3]), "r"(b[0]), "r"(b[1]));
}
__device__ __forceinline__ void cpa16(uint32_t s, const void* g) {
    asm volatile("cp.async.ca.shared.global [%0], [%1], 16;" :: "r"(s), "l"(g));
}
__device__ __forceinline__ float sigf(float x) { return 1.0f / (1.0f + expf(-x)); }
__device__ __forceinline__ unsigned packh(__half a, __half b) {
    return (unsigned)__half_as_ushort(a) | ((unsigned)__half_as_ushort(b) << 16);
}

// ================= HMMA tensor GEMM core (single fp16) ========================
enum { TEPI_HR = 0, TEPI_STORE = 1, TEPI_GATE = 2, TEPI_SCATTER = 3,
       TEPI_CVT = 4, TEPI_GATE2 = 5, TEPI_ADDX = 6 };
// per buffer: A 16KB @0, B 16KB @16384; 2 buffers
#define TG_SMEM (2 * 32768 + 1024)

struct GDesc {
    const __half *Ah, *Bh;
    const int* Mptr;
    const int* gidx;
    const float* aux;
    const int* sidx;
    const float* scl;
    float* outF;
    __half* outH;
    int K, ldo, Nb;
};

__device__ __forceinline__ void tg_main(
    const __half* __restrict__ Ah, const __half* __restrict__ Bh,
    int M, int bm, int bn, int K, const int* __restrict__ gidx,
    uint32_t smb, float acc[4][4][4]) {
    int tid = threadIdx.x, lane = tid & 31, warp = tid >> 5;
    int wm = warp & 1, wn = warp >> 1;
    int quad = lane >> 3, r8 = lane & 7;

    uint32_t baseA[4], maskA[4];
    uint32_t kqA = (uint32_t)(quad >> 1) * 16;
#pragma unroll
    for (int mt = 0; mt < 4; mt++) {
        int rowA = wm * 64 + mt * 16 + (quad & 1) * 8 + r8;
        baseA[mt] = (uint32_t)rowA * 128;
        maskA[mt] = (uint32_t)(rowA & 7) << 4;
    }
    uint32_t baseB[2], maskB[2];
    uint32_t kqB = (uint32_t)(quad & 1) * 16;
#pragma unroll
    for (int n2 = 0; n2 < 2; n2++) {
        int rowB = wn * 32 + n2 * 16 + (quad >> 1) * 8 + r8;
        baseB[n2] = 16384u + (uint32_t)rowB * 128;
        maskB[n2] = (uint32_t)(rowB & 7) << 4;
    }

    // staging: 64 k-elems (128B) per row per chunk; 2 threads per row, 64B each
    int row = tid >> 1, h = tid & 1;
    int ra = bm + row; if (ra > M - 1) ra = M - 1;
    if (gidx) ra = gidx[ra];
    const __half* pA = Ah + (size_t)ra * K + h * 32;
    const __half* pB = Bh + (size_t)(bn + row) * K + h * 32;
    uint32_t mk = (uint32_t)(row & 7) << 4;
    uint32_t st[4];
#pragma unroll
    for (int i = 0; i < 4; i++)
        st[i] = (uint32_t)row * 128 + (((uint32_t)h * 64 + i * 16) ^ mk);

    auto stage = [&](int t, int buf) {
        int kc = t * 64;
        uint32_t ab = smb + (uint32_t)buf * 32768u;
#pragma unroll
        for (int i = 0; i < 4; i++) {
            cpa16(ab + st[i],          pA + kc + i * 8);
            cpa16(ab + 16384u + st[i], pB + kc + i * 8);
        }
        asm volatile("cp.async.commit_group;" ::: "memory");
    };

#pragma unroll
    for (int i = 0; i < 4; i++)
#pragma unroll
        for (int j = 0; j < 4; j++)
#pragma unroll
            for (int q = 0; q < 4; q++) acc[i][j][q] = 0.f;

    int nch = K >> 6;
    stage(0, 0);
    stage(1, 1);
    for (int t = 0; t < nch; t++) {
        if (t + 1 < nch) asm volatile("cp.async.wait_group 1;" ::: "memory");
        else             asm volatile("cp.async.wait_group 0;" ::: "memory");
        __syncthreads();
        uint32_t bufs = smb + (uint32_t)(t & 1) * 32768u;
#pragma unroll
        for (int ks = 0; ks < 4; ks++) {
            uint32_t cb = (uint32_t)ks * 32;
            uint32_t bfr[4][2];
#pragma unroll
            for (int n2 = 0; n2 < 2; n2++) {
                uint32_t r[4];
                ldsm4(r, bufs + baseB[n2] + ((kqB + cb) ^ maskB[n2]));
                bfr[2 * n2][0] = r[0]; bfr[2 * n2][1] = r[1];
                bfr[2 * n2 + 1][0] = r[2]; bfr[2 * n2 + 1][1] = r[3];
            }
#pragma unroll
            for (int mt = 0; mt < 4; mt++) {
                uint32_t a[4];
                ldsm4(a, bufs + baseA[mt] + ((kqA + cb) ^ maskA[mt]));
#pragma unroll
                for (int nt = 0; nt < 4; nt++)
                    mma16816(acc[mt][nt], a, bfr[nt]);
            }
        }
        __syncthreads();
        if (t + 2 < nch) stage(t + 2, t & 1);
    }
}

template <int EPI>
__device__ __forceinline__ void emit2(int grow, int gcol, float v0, float v1, int M,
                                      const float* __restrict__ aux,
                                      const int* __restrict__ sidx, const float* __restrict__ scl,
                                      float* __restrict__ outF, __half* __restrict__ outH, int ldo) {
    if (grow >= M) return;
    if (EPI == TEPI_STORE) {
        *(float2*)(outF + (size_t)grow * ldo + gcol) = make_float2(v0, v1);
    } else if (EPI == TEPI_ADDX) {
        float2 a = *(const float2*)(aux + (size_t)grow * CD + gcol);
        *(float2*)(outF + (size_t)grow * ldo + gcol) = make_float2(v0 + a.x, v1 + a.y);
    } else if (EPI == TEPI_SCATTER) {
        int orow = sidx[grow];
        float sc = scl[orow];
        float2* p = (float2*)(outF + (size_t)orow * ldo + gcol);
        float2 c = *p;
        c.x += v0 * sc; c.y += v1 * sc;
        *p = c;
    } else {
        if (EPI == TEPI_HR) {
            v0 = fmaxf(v0, 0.f); v0 *= v0;
            v1 = fmaxf(v1, 0.f); v1 *= v1;
        } else if (EPI == TEPI_GATE) {
            float2 a = *(const float2*)(aux + (size_t)grow * CD + gcol);
            v0 = a.x * sigf(v0); v1 = a.y * sigf(v1);
        } else if (EPI == TEPI_GATE2) {
            float2 a = *(const float2*)(aux + (size_t)grow * CD + gcol);
            v0 = sigf(a.x) * v0; v1 = sigf(a.y) * v1;
        }
        *(unsigned*)(outH + (size_t)grow * ldo + gcol) =
            packh(__float2half_rn(v0), __float2half_rn(v1));
    }
}

template <int EPI>
__device__ __forceinline__ void tg_epi(int M, int bm, int bn, float acc[4][4][4],
                                       const float* aux, const int* sidx, const float* scl,
                                       float* outF, __half* outH, int ldo) {
    int lane = threadIdx.x & 31, warp = threadIdx.x >> 5;
    int wm = warp & 1, wn = warp >> 1;
    int erow = lane >> 2, ecol = (lane & 3) * 2;
#pragma unroll
    for (int mt = 0; mt < 4; mt++) {
        int gr = bm + wm * 64 + mt * 16 + erow;
#pragma unroll
        for (int nt = 0; nt < 4; nt++) {
            int gc = bn + wn * 32 + nt * 8 + ecol;
            emit2<EPI>(gr,     gc, acc[mt][nt][0], acc[mt][nt][1], M, aux, sidx, scl, outF, outH, ldo);
            emit2<EPI>(gr + 8, gc, acc[mt][nt][2], acc[mt][nt][3], M, aux, sidx, scl, outF, outH, ldo);
        }
    }
}

template <int EPI>
__global__ void __launch_bounds__(256, 2)
tgemm(const __half* __restrict__ Ah, const __half* __restrict__ Bh,
      int Mstat, const int* __restrict__ Mptr, int K,
      const int* __restrict__ gidx, const float* __restrict__ aux,
      const int* __restrict__ sidx, const float* __restrict__ scl,
      float* __restrict__ outF, __half* __restrict__ outH, int ldo) {
    int M = Mptr ? *Mptr : Mstat;
    int bm = blockIdx.x * 128;
    if (bm >= M) return;
    int bn = blockIdx.y * 128;
    extern __shared__ char smraw[];
    uint32_t smb0 = smem_u32(smraw);
    uint32_t smb = (smb0 + 1023u) & ~1023u;
    float acc[4][4][4];
    tg_main(Ah, Bh, M, bm, bn, K, gidx, smb, acc);
    tg_epi<EPI>(M, bm, bn, acc, aux, sidx, scl, outF, outH, ldo);
}

template <int E0, int E1, int E2, int E3>
__global__ void __launch_bounds__(256, 2)
btgemm(GDesc g0, GDesc g1, GDesc g2, GDesc g3) {
    int z = blockIdx.z;
    GDesc g = (z == 0) ? g0 : (z == 1) ? g1 : (z == 2) ? g2 : g3;
    if ((int)blockIdx.y >= g.Nb) return;
    int M = *g.Mptr;
    int bm = blockIdx.x * 128;
    if (bm >= M) return;
    int bn = blockIdx.y * 128;
    extern __shared__ char smraw[];
    uint32_t smb0 = smem_u32(smraw);
    uint32_t smb = (smb0 + 1023u) & ~1023u;
    float acc[4][4][4];
    tg_main(g.Ah, g.Bh, M, bm, bn, g.K, g.gidx, smb, acc);
    if (z == 0)      tg_epi<E0>(M, bm, bn, acc, g.aux, g.sidx, g.scl, g.outF, g.outH, g.ldo);
    else if (z == 1) tg_epi<E1>(M, bm, bn, acc, g.aux, g.sidx, g.scl, g.outF, g.outH, g.ldo);
    else if (z == 2) tg_epi<E2>(M, bm, bn, acc, g.aux, g.sidx, g.scl, g.outF, g.outH, g.ldo);
    else             tg_epi<E3>(M, bm, bn, acc, g.aux, g.sidx, g.scl, g.outF, g.outH, g.ldo);
}

// ======== transpose + convert: W[K,N] -> WT[N,K] (fp16) =======================
__global__ void tsplit(const float* __restrict__ W, int K, int N,
                       __half* __restrict__ hi) {
    __shared__ float t[32][33];
    int n0 = blockIdx.x * 32, k0 = blockIdx.y * 32;
    int tx = threadIdx.x, ty = threadIdx.y;
#pragma unroll
    for (int j = 0; j < 4; j++)
        t[ty + 8 * j][tx] = W[(size_t)(k0 + ty + 8 * j) * N + n0 + tx];
    __syncthreads();
#pragma unroll
    for (int j = 0; j < 4; j++) {
        float v = t[tx][ty + 8 * j];
        hi[(size_t)(n0 + ty + 8 * j) * K + k0 + tx] = __float2half_rn(v);
    }
}

// ================= LN / routing ===============================================
__device__ __forceinline__ float blockReduceSum(float v) {
    __shared__ float sh[8];
#pragma unroll
    for (int o = 16; o > 0; o >>= 1) v += __shfl_down_sync(0xffffffffu, v, o);
    int w = threadIdx.x >> 5, l = threadIdx.x & 31;
    if (l == 0) sh[w] = v;
    __syncthreads();
    if (threadIdx.x < 8) {
        float r = sh[threadIdx.x];
#pragma unroll
        for (int o = 4; o > 0; o >>= 1) r += __shfl_down_sync(0x000000ffu, r, o);
        if (threadIdx.x == 0) sh[0] = r;
    }
    __syncthreads();
    float res = sh[0];
    __syncthreads();
    return res;
}

__global__ void ln_kernel(const float* __restrict__ x, const float* __restrict__ w,
                          const float* __restrict__ b, float* __restrict__ out,
                          __half* __restrict__ oh) {
    int row = blockIdx.x, tid = threadIdx.x;
    float4 v = ((const float4*)(x + (size_t)row * CD))[tid];
    float s = blockReduceSum(v.x + v.y + v.z + v.w);
    float mean = s * (1.0f / CD);
    float dx = v.x - mean, dy = v.y - mean, dz = v.z - mean, dw = v.w - mean;
    float s2 = blockReduceSum(dx * dx + dy * dy + dz * dz + dw * dw);
    float rstd = 1.0f / sqrtf(s2 * (1.0f / CD) + 1e-5f);
    float4 wv = ((const float4*)w)[tid], bv = ((const float4*)b)[tid];
    float4 o = make_float4(dx * rstd * wv.x + bv.x, dy * rstd * wv.y + bv.y,
                           dz * rstd * wv.z + bv.z, dw * rstd * wv.w + bv.w);
    ((float4*)(out + (size_t)row * CD))[tid] = o;
    ((uint2*)(oh + (size_t)row * CD))[tid] =
        make_uint2(packh(__float2half_rn(o.x), __float2half_rn(o.y)),
                   packh(__float2half_rn(o.z), __float2half_rn(o.w)));
}

__global__ void ln2_route_kernel(const float* __restrict__ x2, const float* __restrict__ w,
                                 const float* __restrict__ b, const float* __restrict__ conf_rwkv,
                                 const float* __restrict__ conf_trans, const float* __restrict__ w_diff,
                                 const float* __restrict__ W_aff, const float* __restrict__ capital,
                                 __half* __restrict__ hh,
                                 float* __restrict__ conf3, int* __restrict__ winner,
                                 int* __restrict__ rc_cnt, int* __restrict__ rc_list) {
    int row = blockIdx.x, tid = threadIdx.x;
    float4 v = ((const float4*)(x2 + (size_t)row * CD))[tid];
    float s = blockReduceSum(v.x + v.y + v.z + v.w);
    float mean = s * (1.0f / CD);
    float dx = v.x - mean, dy = v.y - mean, dz = v.z - mean, dw = v.w - mean;
    float s2 = blockReduceSum(dx * dx + dy * dy + dz * dz + dw * dw);
    float rstd = 1.0f / sqrtf(s2 * (1.0f / CD) + 1e-5f);
    float4 wv = ((const float4*)w)[tid], bv = ((const float4*)b)[tid];
    float4 o = make_float4(dx * rstd * wv.x + bv.x, dy * rstd * wv.y + bv.y,
                           dz * rstd * wv.z + bv.z, dw * rstd * wv.w + bv.w);
    ((uint2*)(hh + (size_t)row * CD))[tid] =
        make_uint2(packh(__float2half_rn(o.x), __float2half_rn(o.y)),
                   packh(__float2half_rn(o.z), __float2half_rn(o.w)));

    float p[7];
    float4 c0 = ((const float4*)conf_rwkv)[tid];
    float4 c1 = ((const float4*)(conf_rwkv + CD))[tid];
    float4 ct = ((const float4*)conf_trans)[tid];
    float4 wd = ((const float4*)w_diff)[tid];
    p[0] = o.x * c0.x + o.y * c0.y + o.z * c0.z + o.w * c0.w;
    p[1] = o.x * c1.x + o.y * c1.y + o.z * c1.z + o.w * c1.w;
    p[2] = o.x * ct.x + o.y * ct.y + o.z * ct.z + o.w * ct.w;
    p[3] = o.x * wd.x + o.y * wd.y + o.z * wd.z + o.w * wd.w;
    const float* wa = W_aff + (size_t)tid * 12;
#pragma unroll
    for (int e = 0; e < 3; e++)
        p[4 + e] = o.x * wa[e] + o.y * wa[3 + e] + o.z * wa[6 + e] + o.w * wa[9 + e];

    __shared__ float red[7][8];
    int wid = tid >> 5, lid = tid & 31;
#pragma unroll
    for (int q = 0; q < 7; q++) {
        float vv = p[q];
#pragma unroll
        for (int o2 = 16; o2 > 0; o2 >>= 1) vv += __shfl_down_sync(0xffffffffu, vv, o2);
        if (lid == 0) red[q][wid] = vv;
    }
    __syncthreads();
    if (tid == 0) {
        float d[7];
#pragma unroll
        for (int q = 0; q < 7; q++) {
            float t = 0.f;
#pragma unroll
            for (int k = 0; k < 8; k++) t += red[q][k];
            d[q] = t;
        }
        float cf[3] = {sigf(d[0]), sigf(d[1]), sigf(d[2])};
        float diff = sigf(d[3]);
        float bids[3];
#pragma unroll
        for (int e = 0; e < 3; e++) {
            bids[e] = cf[e] * capital[e] * diff + d[4 + e];
            conf3[row * 3 + e] = cf[e];
        }
        int wdx = 0; float best = bids[0];
        if (bids[1] > best) { best = bids[1]; wdx = 1; }
        if (bids[2] > best) { best = bids[2]; wdx = 2; }
        float second = -1e30f;
#pragma unroll
        for (int e = 0; e < 3; e++)
            if (e != wdx && bids[e] > second) second = bids[e];
        winner[row] = wdx;
        if (best - second < 1e-3f) {
            int pos = atomicAdd(rc_cnt, 1);
            if (pos < RC_CAP) rc_list[pos] = row;
        }
    }
}

// exact fp32 recompute of routing for marginal tokens (coalesced row-major GEMV)
__global__ void recheck_kernel(const float* __restrict__ x, const float* __restrict__ xln,
                               const float* __restrict__ Wr, const float* __restrict__ Wv,
                               const float* __restrict__ Wo,
                               const float* __restrict__ ln2w, const float* __restrict__ ln2b,
                               const float* __restrict__ conf_rwkv, const float* __restrict__ conf_trans,
                               const float* __restrict__ w_diff, const float* __restrict__ W_aff,
                               const float* __restrict__ capital,
                               const int* __restrict__ rc_cnt, const int* __restrict__ rc_list,
                               int* __restrict__ winner) {
    int n = *rc_cnt; if (n > RC_CAP) n = RC_CAP;
    int bi = blockIdx.x;
    if (bi >= n) return;
    int row = rc_list[bi];
    int tid = threadIdx.x;
    __shared__ float sx[CD];
    __shared__ float su[CD];
    for (int c = tid; c < CD; c += 256) sx[c] = xln[(size_t)row * CD + c];
    __syncthreads();

    float racc[4] = {0, 0, 0, 0}, vacc[4] = {0, 0, 0, 0};
    for (int k = 0; k < CD; k++) {
        float xv = sx[k];
        const float* wr = Wr + (size_t)k * CD + tid;
        const float* wv = Wv + (size_t)k * CD + tid;
#pragma unroll
        for (int j = 0; j < 4; j++) {
            racc[j] += xv * wr[j * 256];
            vacc[j] += xv * wv[j * 256];
        }
    }
#pragma unroll
    for (int j = 0; j < 4; j++)
        su[tid + j * 256] = sigf(racc[j]) * vacc[j];
    __syncthreads();

    float oacc[4] = {0, 0, 0, 0};
    for (int k = 0; k < CD; k++) {
        float uv = su[k];
        const float* wo = Wo + (size_t)k * CD + tid;
#pragma unroll
        for (int j = 0; j < 4; j++) oacc[j] += uv * wo[j * 256];
    }
    __syncthreads();
#pragma unroll
    for (int j = 0; j < 4; j++)
        sx[tid + j * 256] = oacc[j] + x[(size_t)row * CD + tid + j * 256];
    __syncthreads();

    float ps = 0.f;
    for (int c = tid; c < CD; c += 256) ps += sx[c];
    float mean = blockReduceSum(ps) * (1.0f / CD);
    float ps2 = 0.f;
    for (int c = tid; c < CD; c += 256) { float d = sx[c] - mean; ps2 += d * d; }
    float rstd = 1.0f / sqrtf(blockReduceSum(ps2) * (1.0f / CD) + 1e-5f);

    float p[7] = {0, 0, 0, 0, 0, 0, 0};
    for (int c = tid; c < CD; c += 256) {
        float hc = (sx[c] - mean) * rstd * ln2w[c] + ln2b[c];
        p[0] += hc * conf_rwkv[c];
        p[1] += hc * conf_rwkv[CD + c];
        p[2] += hc * conf_trans[c];
        p[3] += hc * w_diff[c];
        p[4] += hc * W_aff[c * 3 + 0];
        p[5] += hc * W_aff[c * 3 + 1];
        p[6] += hc * W_aff[c * 3 + 2];
    }
    __shared__ float red[7][8];
    int wid = tid >> 5, lid = tid & 31;
#pragma unroll
    for (int q = 0; q < 7; q++) {
        float vv = p[q];
#pragma unroll
        for (int o2 = 16; o2 > 0; o2 >>= 1) vv += __shfl_down_sync(0xffffffffu, vv, o2);
        if (lid == 0) red[q][wid] = vv;
    }
    __syncthreads();
    if (tid == 0) {
        float d[7];
#pragma unroll
        for (int q = 0; q < 7; q++) {
            float t = 0.f;
#pragma unroll
            for (int k = 0; k < 8; k++) t += red[q][k];
            d[q] = t;
        }
        float cf[3] = {sigf(d[0]), sigf(d[1]), sigf(d[2])};
        float diff = sigf(d[3]);
        int wdx = 0; float best = -1e30f;
#pragma unroll
        for (int e = 0; e < 3; e++) {
            float bid = cf[e] * capital[e] * diff + d[4 + e];
            if (bid > best) { best = bid; wdx = e; }
        }
        winner[row] = wdx;
    }
}

__global__ void build_lists(const int* __restrict__ winner, const float* __restrict__ conf3,
                            float* __restrict__ scale_out, int* __restrict__ cnt, int* __restrict__ lst) {
    int i = blockIdx.x * 256 + threadIdx.x;
    if (i >= NT) return;
    int w = winner[i];
    float wc = conf3[i * 3 + w];
    scale_out[i] = wc / (wc + 1e-6f);
    int pos = atomicAdd(&cnt[w], 1);
    lst[w * NT + pos] = i;
}

__global__ void zero_cnt_kernel(int* c, int* rc) {
    if (threadIdx.x < 3) c[threadIdx.x] = 0;
    if (threadIdx.x == 0) *rc = 0;
}

// ================= launch =====================================================
extern "C" void kernel_launch(void* const* d_in, const int* in_sizes, int n_in,
                              void* d_out, int out_size) {
    const float* x = (const float*)d_in[0];
    const float* capital = (const float*)d_in[2];
    const float* ln1w = (const float*)d_in[3], *ln1b = (const float*)d_in[4];
    const float* ln2w = (const float*)d_in[5], *ln2b = (const float*)d_in[6];
    const float* Wr = (const float*)d_in[7], *Wv = (const float*)d_in[8];
    const float* Wo = (const float*)d_in[9], *Ws = (const float*)d_in[10];
    const float* Kr = (const float*)d_in[11], *Vr = (const float*)d_in[12];
    const float* confr = (const float*)d_in[13];
    const float* W1 = (const float*)d_in[14], *W2 = (const float*)d_in[15];
    const float* W3 = (const float*)d_in[16];
    const float* conft = (const float*)d_in[17], *wdiff = (const float*)d_in[18];
    const float* Waff = (const float*)d_in[19];
    float* out = (float*)d_out;

    void* p;
    cudaGetSymbolAddress(&p, g_xln);    float* xln = (float*)p;
    cudaGetSymbolAddress(&p, g_r);      float* rb = (float*)p;
    cudaGetSymbolAddress(&p, g_a);      float* ab = (float*)p;
    cudaGetSymbolAddress(&p, g_scale);  float* sclp = (float*)p;
    cudaGetSymbolAddress(&p, g_cnt);    int* cnt = (int*)p;
    cudaGetSymbolAddress(&p, g_list);   int* lst = (int*)p;
    cudaGetSymbolAddress(&p, g_winner); int* win = (int*)p;
    cudaGetSymbolAddress(&p, g_conf3);  float* conf3 = (float*)p;
    cudaGetSymbolAddress(&p, g_rc_cnt); int* rc_cnt = (int*)p;
    cudaGetSymbolAddress(&p, g_rc_list);int* rc_list = (int*)p;
    cudaGetSymbolAddress(&p, g_xh);     __half* xh = (__half*)p;
    cudaGetSymbolAddress(&p, g_hh);     __half* hh = (__half*)p;
    cudaGetSymbolAddress(&p, g_sh);     __half* sh = (__half*)p;
    cudaGetSymbolAddress(&p, g_ah);     __half* ah = (__half*)p;
    cudaGetSymbolAddress(&p, g_hr0);    __half* hr0 = (__half*)p;
    cudaGetSymbolAddress(&p, g_hr1);    __half* hr1 = (__half*)p;
    cudaGetSymbolAddress(&p, g_wt);     __half* wt = (__half*)p;

    cudaFuncSetAttribute(tgemm<TEPI_STORE>,   cudaFuncAttributeMaxDynamicSharedMemorySize, TG_SMEM);
    cudaFuncSetAttribute(tgemm<TEPI_GATE2>,   cudaFuncAttributeMaxDynamicSharedMemorySize, TG_SMEM);
    cudaFuncSetAttribute(tgemm<TEPI_ADDX>,    cudaFuncAttributeMaxDynamicSharedMemorySize, TG_SMEM);
    cudaFuncSetAttribute(tgemm<TEPI_SCATTER>, cudaFuncAttributeMaxDynamicSharedMemorySize, TG_SMEM);
    cudaFuncSetAttribute((const void*)btgemm<TEPI_CVT, TEPI_STORE, TEPI_HR, TEPI_HR>,
                         cudaFuncAttributeMaxDynamicSharedMemorySize, TG_SMEM);
    cudaFuncSetAttribute((const void*)btgemm<TEPI_GATE, TEPI_SCATTER, TEPI_SCATTER, TEPI_SCATTER>,
                         cudaFuncAttributeMaxDynamicSharedMemorySize, TG_SMEM);

    const size_t M1 = 1048576;
    const size_t KR0T = 0, KR1T = 4 * M1, VR0T = 8 * M1, VR1T = 12 * M1;
    const size_t W1T = 16 * M1, W2T = 17 * M1, W3T = 18 * M1;
    const size_t WRT = 19 * M1, WVT = 20 * M1, WOT = 21 * M1, WST = 22 * M1;

    dim3 blk(256), tb(32, 8);
    dim3 gC(NT / 128, CD / 128);

    // weight transpose+convert (fp16)
    tsplit<<<dim3(HD / 32, CD / 32), tb>>>(Kr, CD, HD, wt + KR0T);
    tsplit<<<dim3(HD / 32, CD / 32), tb>>>(Kr + (size_t)CD * HD, CD, HD, wt + KR1T);
    tsplit<<<dim3(CD / 32, HD / 32), tb>>>(Vr, HD, CD, wt + VR0T);
    tsplit<<<dim3(CD / 32, HD / 32), tb>>>(Vr + (size_t)HD * CD, HD, CD, wt + VR1T);
    tsplit<<<dim3(CD / 32, CD / 32), tb>>>(W1, CD, CD, wt + W1T);
    tsplit<<<dim3(CD / 32, CD / 32), tb>>>(W2, CD, CD, wt + W2T);
    tsplit<<<dim3(CD / 32, CD / 32), tb>>>(W3, CD, CD, wt + W3T);
    tsplit<<<dim3(CD / 32, CD / 32), tb>>>(Wr, CD, CD, wt + WRT);
    tsplit<<<dim3(CD / 32, CD / 32), tb>>>(Wv, CD, CD, wt + WVT);
    tsplit<<<dim3(CD / 32, CD / 32), tb>>>(Wo, CD, CD, wt + WOT);
    tsplit<<<dim3(CD / 32, CD / 32), tb>>>(Ws, CD, CD, wt + WST);

    zero_cnt_kernel<<<1, 32>>>(cnt, rc_cnt);
    ln_kernel<<<NT, 256>>>(x, ln1w, ln1b, xln, xh);

    // attention path: single-fp16 HMMA
    tgemm<TEPI_STORE><<<gC, blk, TG_SMEM>>>(xh, wt + WRT, NT, nullptr, CD,
                                            nullptr, nullptr, nullptr, nullptr, rb, nullptr, CD);
    tgemm<TEPI_GATE2><<<gC, blk, TG_SMEM>>>(xh, wt + WVT, NT, nullptr, CD,
                                            nullptr, rb, nullptr, nullptr, nullptr, ah, CD);
    tgemm<TEPI_ADDX><<<gC, blk, TG_SMEM>>>(ah, wt + WOT, NT, nullptr, CD,
                                           nullptr, x, nullptr, nullptr, out, nullptr, CD);

    // routing (provisional, flags marginal tokens) -> exact recheck -> lists
    ln2_route_kernel<<<NT, 256>>>(out, ln2w, ln2b, confr, conft, wdiff, Waff, capital,
                                  hh, conf3, win, rc_cnt, rc_list);
    recheck_kernel<<<RC_CAP, 256>>>(x, xln, Wr, Wv, Wo, ln2w, ln2b, confr, conft, wdiff,
                                    Waff, capital, rc_cnt, rc_list, win);
    build_lists<<<NT / 256, 256>>>(win, conf3, sclp, cnt, lst);

    // ---- batched expert set 1: {Ws(sparse,cvt), W1, K0, K1} ----
    GDesc dws = {xh, wt + WST, cnt + 2, lst + 2 * NT,
                 nullptr, nullptr, nullptr, nullptr, sh, CD, CD, 8};
    GDesc dw1 = {hh, wt + W1T, cnt + 2, lst + 2 * NT,
                 nullptr, nullptr, nullptr, ab, nullptr, CD, CD, 8};
    GDesc dk0 = {hh, wt + KR0T, cnt + 0, lst + 0 * NT,
                 nullptr, nullptr, nullptr, nullptr, hr0, CD, HD, 32};
    GDesc dk1 = {hh, wt + KR1T, cnt + 1, lst + 1 * NT,
                 nullptr, nullptr, nullptr, nullptr, hr1, CD, HD, 32};
    btgemm<TEPI_CVT, TEPI_STORE, TEPI_HR, TEPI_HR>
        <<<dim3(NT / 128, 32, 4), blk, TG_SMEM>>>(dws, dw1, dk0, dk1);

    // ---- batched expert set 2: {W2(gate), V0, V1} ----
    GDesc dw2 = {sh, wt + W2T, cnt + 2, nullptr,
                 ab, nullptr, nullptr, nullptr, ah, CD, CD, 8};
    GDesc dv0 = {hr0, wt + VR0T, cnt + 0, nullptr,
                 nullptr, lst + 0 * NT, sclp, out, nullptr, HD, CD, 8};
    GDesc dv1 = {hr1, wt + VR1T, cnt + 1, nullptr,
                 nullptr, lst + 1 * NT, sclp, out, nullptr, HD, CD, 8};
    btgemm<TEPI_GATE, TEPI_SCATTER, TEPI_SCATTER, TEPI_SCATTER>
        <<<dim3(NT / 128, 8, 3), blk, TG_SMEM>>>(dw2, dv0, dv1, dv1);

    // ---- set 3: W3 (scatter) ----
    tgemm<TEPI_SCATTER><<<gC, blk, TG_SMEM>>>(ah, wt + W3T, 0, cnt + 2, CD,
                                              nullptr, nullptr, lst + 2 * NT, sclp, out, nullptr, CD);
}